// round 2
// baseline (speedup 1.0000x reference)
#include <cuda_runtime.h>
#include <math.h>

// Problem constants
#define BB   2
#define SS   2048
#define DD   1024
#define HH   16
#define HDIM 64
#define DFFN 4096
#define ROWS (BB * SS)   // 4096

// -------- scratch (static device globals; no allocation) --------
__device__ float g_h[ROWS * DD];          // LN1(x) + pos_emb      (16 MB)
__device__ float g_qkv[ROWS * 3 * DD];    // qkv projections        (48 MB)
__device__ float g_attn[ROWS * DD];       // attention out [B,S,D]  (16 MB)
__device__ float g_x2[ROWS * DD];         // x + attn @ w_o + b_o   (16 MB)
__device__ float g_m[ROWS * DD];          // LN2(x2)                (16 MB)
__device__ float g_ff[ROWS * DFFN];       // gelu(m@w_fc + b_fc)    (64 MB)

// ---------------- GELU (tanh approximation, matches jax.nn.gelu default) ---
__device__ __forceinline__ float gelu_tanh(float x) {
    float x3 = x * x * x;
    float t = tanhf(0.7978845608028654f * (x + 0.044715f * x3));
    return 0.5f * x * (1.0f + t);
}

// ---------------- LayerNorm (+ optional pos_emb add) -----------------------
// one block per row, 256 threads, 4 floats/thread (D=1024)
__global__ void ln_kernel(const float* __restrict__ x,
                          const float* __restrict__ gam,
                          const float* __restrict__ bet,
                          const float* __restrict__ pos,   // nullptr => no add
                          float* __restrict__ out)
{
    int row = blockIdx.x;
    int tid = threadIdx.x;
    const float4* xr = (const float4*)(x + (size_t)row * DD);
    float4 v = xr[tid];
    float s  = v.x + v.y + v.z + v.w;
    float ss = v.x * v.x + v.y * v.y + v.z * v.z + v.w * v.w;
#pragma unroll
    for (int o = 16; o > 0; o >>= 1) {
        s  += __shfl_xor_sync(0xffffffffu, s,  o);
        ss += __shfl_xor_sync(0xffffffffu, ss, o);
    }
    __shared__ float sb[8], sb2[8], stats[2];
    int wid = tid >> 5, lane = tid & 31;
    if (lane == 0) { sb[wid] = s; sb2[wid] = ss; }
    __syncthreads();
    if (tid == 0) {
        float ts = 0.f, tss = 0.f;
#pragma unroll
        for (int i = 0; i < 8; i++) { ts += sb[i]; tss += sb2[i]; }
        float mu  = ts  * (1.0f / DD);
        float var = tss * (1.0f / DD) - mu * mu;
        stats[0] = mu;
        stats[1] = rsqrtf(var + 1e-5f);
    }
    __syncthreads();
    float mu = stats[0], rs = stats[1];
    int c = tid * 4;
    float4 gg = *(const float4*)(gam + c);
    float4 bb = *(const float4*)(bet + c);
    float4 o4;
    o4.x = (v.x - mu) * rs * gg.x + bb.x;
    o4.y = (v.y - mu) * rs * gg.y + bb.y;
    o4.z = (v.z - mu) * rs * gg.z + bb.z;
    o4.w = (v.w - mu) * rs * gg.w + bb.w;
    if (pos) {
        int srow = row % SS;
        float4 p = *(const float4*)(pos + (size_t)srow * DD + c);
        o4.x += p.x; o4.y += p.y; o4.z += p.z; o4.w += p.w;
    }
    ((float4*)(out + (size_t)row * DD))[tid] = o4;
}

// ---------------- Tiled fp32 GEMM: C = A[MxK] @ B[KxN] + epilogue ----------
// 128x128 tile, BK=16, 256 threads, 8x8 microtile per thread.
// EPI: 0 = +bias ; 1 = gelu(+bias) ; 2 = +bias + res
template <int EPI>
__global__ __launch_bounds__(256)
void gemm_kernel(const float* __restrict__ A, const float* __restrict__ Bm,
                 const float* __restrict__ bias, const float* __restrict__ res,
                 float* __restrict__ C, int M, int N, int K)
{
    __shared__ float As[16][128];
    __shared__ float Bs[16][128];
    int tid = threadIdx.x;
    int bn = blockIdx.x, bm = blockIdx.y;

    int aRow = tid >> 2;             // 0..63
    int aCol = (tid & 3) << 2;       // 0,4,8,12
    int bRow = tid >> 5;             // 0..7
    int bCol = (tid & 31) << 2;      // 0..124
    int tx = tid & 15, ty = tid >> 4;

    const float* Ap0 = A + (size_t)(bm * 128 + aRow) * K + aCol;
    const float* Ap1 = A + (size_t)(bm * 128 + aRow + 64) * K + aCol;
    const float* Bp0 = Bm + (size_t)bRow * N + bn * 128 + bCol;
    const float* Bp1 = Bm + (size_t)(bRow + 8) * N + bn * 128 + bCol;

    float acc[8][8];
#pragma unroll
    for (int i = 0; i < 8; i++)
#pragma unroll
        for (int j = 0; j < 8; j++) acc[i][j] = 0.f;

    for (int k0 = 0; k0 < K; k0 += 16) {
        float4 av0 = *(const float4*)(Ap0 + k0);
        float4 av1 = *(const float4*)(Ap1 + k0);
        float4 bv0 = *(const float4*)(Bp0 + (size_t)k0 * N);
        float4 bv1 = *(const float4*)(Bp1 + (size_t)k0 * N);
        __syncthreads();
        As[aCol + 0][aRow] = av0.x;
        As[aCol + 1][aRow] = av0.y;
        As[aCol + 2][aRow] = av0.z;
        As[aCol + 3][aRow] = av0.w;
        As[aCol + 0][aRow + 64] = av1.x;
        As[aCol + 1][aRow + 64] = av1.y;
        As[aCol + 2][aRow + 64] = av1.z;
        As[aCol + 3][aRow + 64] = av1.w;
        *(float4*)&Bs[bRow][bCol]     = bv0;
        *(float4*)&Bs[bRow + 8][bCol] = bv1;
        __syncthreads();
#pragma unroll
        for (int kk = 0; kk < 16; kk++) {
            float a[8], b[8];
            *(float4*)&a[0] = *(const float4*)&As[kk][ty * 8];
            *(float4*)&a[4] = *(const float4*)&As[kk][ty * 8 + 4];
            *(float4*)&b[0] = *(const float4*)&Bs[kk][tx * 8];
            *(float4*)&b[4] = *(const float4*)&Bs[kk][tx * 8 + 4];
#pragma unroll
            for (int i = 0; i < 8; i++)
#pragma unroll
                for (int j = 0; j < 8; j++) acc[i][j] += a[i] * b[j];
        }
    }

    int row0 = bm * 128 + ty * 8;
    int col0 = bn * 128 + tx * 8;
#pragma unroll
    for (int i = 0; i < 8; i++) {
        size_t base = (size_t)(row0 + i) * N + col0;
#pragma unroll
        for (int j = 0; j < 8; j++) {
            float v = acc[i][j] + bias[col0 + j];
            if (EPI == 1) v = gelu_tanh(v);
            if (EPI == 2) v += res[base + j];
            C[base + j] = v;
        }
    }
}

// ---------------- Causal attention (online softmax / flash style) ----------
// grid: (S/32, H, B), block: 128 threads.
// 32 queries per block; 4 threads per query, each owning 16 head dims.
__global__ __launch_bounds__(128)
void attn_kernel(const float* __restrict__ qkv, float* __restrict__ out)
{
    __shared__ float Ks[32][64];
    __shared__ float Vs[32][64];
    int qt = blockIdx.x, h = blockIdx.y, b = blockIdx.z;
    int tid = threadIdx.x;
    int ql = tid >> 2;       // 0..31 query within tile
    int cs = tid & 3;        // 0..3 dim-chunk
    int q0 = qt * 32;
    int qglob = q0 + ql;

    // load q fragment (16 floats) into registers, pre-scaled by 1/sqrt(64)
    size_t qbase = ((size_t)(b * SS + qglob) * 3 + 0) * DD + h * HDIM + cs * 16;
    float4 qv[4];
#pragma unroll
    for (int c = 0; c < 4; c++) {
        qv[c] = *(const float4*)(qkv + qbase + c * 4);
        qv[c].x *= 0.125f; qv[c].y *= 0.125f; qv[c].z *= 0.125f; qv[c].w *= 0.125f;
    }

    float4 acc4[4];
#pragma unroll
    for (int c = 0; c < 4; c++) acc4[c] = make_float4(0.f, 0.f, 0.f, 0.f);
    float mrun = -1e30f, l = 0.f;

    for (int kt = 0; kt <= qt; kt++) {
        __syncthreads();
        int sk = kt * 32 + ql;
        const float4* kg = (const float4*)(qkv + ((size_t)(b * SS + sk) * 3 + 1) * DD + h * HDIM + cs * 16);
        const float4* vg = (const float4*)(qkv + ((size_t)(b * SS + sk) * 3 + 2) * DD + h * HDIM + cs * 16);
        float4* kd = (float4*)&Ks[ql][cs * 16];
        float4* vd = (float4*)&Vs[ql][cs * 16];
#pragma unroll
        for (int c = 0; c < 4; c++) { kd[c] = kg[c]; vd[c] = vg[c]; }
        __syncthreads();

        float sc[32];
        float mt = -1e30f;
#pragma unroll
        for (int kc = 0; kc < 32; kc++) {
            const float4* kr = (const float4*)&Ks[kc][cs * 16];
            float p = 0.f;
#pragma unroll
            for (int c = 0; c < 4; c++) {
                float4 kk = kr[c];
                p += qv[c].x * kk.x + qv[c].y * kk.y + qv[c].z * kk.z + qv[c].w * kk.w;
            }
            // reduce over the 4 dim-chunk threads (lanes 4q..4q+3)
            p += __shfl_xor_sync(0xffffffffu, p, 1);
            p += __shfl_xor_sync(0xffffffffu, p, 2);
            if (kt == qt && (kt * 32 + kc) > qglob) p = -1e30f;
            sc[kc] = p;
            mt = fmaxf(mt, p);
        }

        float nm = fmaxf(mrun, mt);
        float corr = __expf(mrun - nm);
        l *= corr;
#pragma unroll
        for (int c = 0; c < 4; c++) {
            acc4[c].x *= corr; acc4[c].y *= corr; acc4[c].z *= corr; acc4[c].w *= corr;
        }
        float ps = 0.f;
#pragma unroll
        for (int kc = 0; kc < 32; kc++) {
            float p = __expf(sc[kc] - nm);
            ps += p;
            sc[kc] = p;
        }
        l += ps;
        mrun = nm;
#pragma unroll
        for (int kc = 0; kc < 32; kc++) {
            const float4* vr = (const float4*)&Vs[kc][cs * 16];
            float p = sc[kc];
#pragma unroll
            for (int c = 0; c < 4; c++) {
                float4 vv = vr[c];
                acc4[c].x += p * vv.x; acc4[c].y += p * vv.y;
                acc4[c].z += p * vv.z; acc4[c].w += p * vv.w;
            }
        }
    }

    float inv = 1.0f / l;
    float* op = out + (size_t)(b * SS + qglob) * DD + h * HDIM + cs * 16;
#pragma unroll
    for (int c = 0; c < 4; c++) {
        float4 o;
        o.x = acc4[c].x * inv; o.y = acc4[c].y * inv;
        o.z = acc4[c].z * inv; o.w = acc4[c].w * inv;
        *(float4*)(op + c * 4) = o;
    }
}

// ---------------- launch ---------------------------------------------------
extern "C" void kernel_launch(void* const* d_in, const int* in_sizes, int n_in,
                              void* d_out, int out_size)
{
    const float* x    = (const float*)d_in[0];
    const float* pos  = (const float*)d_in[1];
    const float* ln1g = (const float*)d_in[2];
    const float* ln1b = (const float*)d_in[3];
    const float* wqkv = (const float*)d_in[4];
    const float* bqkv = (const float*)d_in[5];
    const float* wo   = (const float*)d_in[6];
    const float* bo   = (const float*)d_in[7];
    const float* ln2g = (const float*)d_in[8];
    const float* ln2b = (const float*)d_in[9];
    const float* wfc  = (const float*)d_in[10];
    const float* bfc  = (const float*)d_in[11];
    const float* wpr  = (const float*)d_in[12];
    const float* bpr  = (const float*)d_in[13];
    float* out = (float*)d_out;

    float *p_h, *p_qkv, *p_attn, *p_x2, *p_m, *p_ff;
    cudaGetSymbolAddress((void**)&p_h,    g_h);
    cudaGetSymbolAddress((void**)&p_qkv,  g_qkv);
    cudaGetSymbolAddress((void**)&p_attn, g_attn);
    cudaGetSymbolAddress((void**)&p_x2,   g_x2);
    cudaGetSymbolAddress((void**)&p_m,    g_m);
    cudaGetSymbolAddress((void**)&p_ff,   g_ff);

    // 1) h = LN1(x) + pos
    ln_kernel<<<ROWS, 256>>>(x, ln1g, ln1b, pos, p_h);

    // 2) qkv = h @ w_qkv + b_qkv      [4096 x 3072]
    gemm_kernel<0><<<dim3(3 * DD / 128, ROWS / 128), 256>>>(
        p_h, wqkv, bqkv, nullptr, p_qkv, ROWS, 3 * DD, DD);

    // 3) causal attention -> [B,S,D]
    attn_kernel<<<dim3(SS / 32, HH, BB), 128>>>(p_qkv, p_attn);

    // 4) x2 = x + attn @ w_o + b_o    [4096 x 1024]
    gemm_kernel<2><<<dim3(DD / 128, ROWS / 128), 256>>>(
        p_attn, wo, bo, x, p_x2, ROWS, DD, DD);

    // 5) m = LN2(x2)
    ln_kernel<<<ROWS, 256>>>(p_x2, ln2g, ln2b, nullptr, p_m);

    // 6) ff = gelu(m @ w_fc + b_fc)   [4096 x 4096]
    gemm_kernel<1><<<dim3(DFFN / 128, ROWS / 128), 256>>>(
        p_m, wfc, bfc, nullptr, p_ff, ROWS, DFFN, DD);

    // 7) out = x2 + ff @ w_proj + b_proj  [4096 x 1024]
    gemm_kernel<2><<<dim3(DD / 128, ROWS / 128), 256>>>(
        p_ff, wpr, bpr, p_x2, out, ROWS, DD, DFFN);
}

// round 3
// speedup vs baseline: 1.4284x; 1.4284x over previous
#include <cuda_runtime.h>
#include <math.h>

// Problem constants
#define BB   2
#define SS   2048
#define DD   1024
#define HH   16
#define HDIM 64
#define DFFN 4096
#define ROWS (BB * SS)   // 4096

// -------- scratch (static device globals; no allocation) --------
__device__ float g_h[ROWS * DD];          // LN1(x) + pos_emb
__device__ float g_qkv[ROWS * 3 * DD];    // qkv projections
__device__ float g_attn[ROWS * DD];       // attention out [B,S,D]
__device__ float g_x2[ROWS * DD];         // x + attn @ w_o + b_o
__device__ float g_m[ROWS * DD];          // LN2(x2)
__device__ float g_ff[ROWS * DFFN];       // gelu(m@w_fc + b_fc)

// ---------------- GELU (tanh approximation, matches jax.nn.gelu default) ---
__device__ __forceinline__ float gelu_tanh(float x) {
    float x3 = x * x * x;
    float t = tanhf(0.7978845608028654f * (x + 0.044715f * x3));
    return 0.5f * x * (1.0f + t);
}

// ---------------- LayerNorm (+ optional pos_emb add) -----------------------
__global__ void ln_kernel(const float* __restrict__ x,
                          const float* __restrict__ gam,
                          const float* __restrict__ bet,
                          const float* __restrict__ pos,   // nullptr => no add
                          float* __restrict__ out)
{
    int row = blockIdx.x;
    int tid = threadIdx.x;
    const float4* xr = (const float4*)(x + (size_t)row * DD);
    float4 v = xr[tid];
    float s  = v.x + v.y + v.z + v.w;
    float ss = v.x * v.x + v.y * v.y + v.z * v.z + v.w * v.w;
#pragma unroll
    for (int o = 16; o > 0; o >>= 1) {
        s  += __shfl_xor_sync(0xffffffffu, s,  o);
        ss += __shfl_xor_sync(0xffffffffu, ss, o);
    }
    __shared__ float sb[8], sb2[8], stats[2];
    int wid = tid >> 5, lane = tid & 31;
    if (lane == 0) { sb[wid] = s; sb2[wid] = ss; }
    __syncthreads();
    if (tid == 0) {
        float ts = 0.f, tss = 0.f;
#pragma unroll
        for (int i = 0; i < 8; i++) { ts += sb[i]; tss += sb2[i]; }
        float mu  = ts  * (1.0f / DD);
        float var = tss * (1.0f / DD) - mu * mu;
        stats[0] = mu;
        stats[1] = rsqrtf(var + 1e-5f);
    }
    __syncthreads();
    float mu = stats[0], rs = stats[1];
    int c = tid * 4;
    float4 gg = *(const float4*)(gam + c);
    float4 bb = *(const float4*)(bet + c);
    float4 o4;
    o4.x = (v.x - mu) * rs * gg.x + bb.x;
    o4.y = (v.y - mu) * rs * gg.y + bb.y;
    o4.z = (v.z - mu) * rs * gg.z + bb.z;
    o4.w = (v.w - mu) * rs * gg.w + bb.w;
    if (pos) {
        int srow = row % SS;
        float4 p = *(const float4*)(pos + (size_t)srow * DD + c);
        o4.x += p.x; o4.y += p.y; o4.z += p.z; o4.w += p.w;
    }
    ((float4*)(out + (size_t)row * DD))[tid] = o4;
}

// ---------------- Tiled fp32 GEMM with register prefetch -------------------
// 128x128 tile, BK=16, 256 threads, 8x8 microtile per thread.
// EPI: 0 = +bias ; 1 = gelu(+bias) ; 2 = +bias + res
template <int EPI>
__global__ __launch_bounds__(256)
void gemm_kernel(const float* __restrict__ A, const float* __restrict__ Bm,
                 const float* __restrict__ bias, const float* __restrict__ res,
                 float* __restrict__ C, int M, int N, int K)
{
    __shared__ float As[16][128];
    __shared__ float Bs[16][128];
    int tid = threadIdx.x;
    int bn = blockIdx.x, bm = blockIdx.y;

    int aRow = tid >> 2;             // 0..63
    int aCol = (tid & 3) << 2;       // 0,4,8,12
    int bRow = tid >> 5;             // 0..7
    int bCol = (tid & 31) << 2;      // 0..124
    int tx = tid & 15, ty = tid >> 4;

    const float* Ap0 = A + (size_t)(bm * 128 + aRow) * K + aCol;
    const float* Ap1 = A + (size_t)(bm * 128 + aRow + 64) * K + aCol;
    const float* Bp0 = Bm + (size_t)bRow * N + bn * 128 + bCol;
    const float* Bp1 = Bm + (size_t)(bRow + 8) * N + bn * 128 + bCol;

    float acc[8][8];
#pragma unroll
    for (int i = 0; i < 8; i++)
#pragma unroll
        for (int j = 0; j < 8; j++) acc[i][j] = 0.f;

    // prologue: fetch first K-slab into registers
    float4 av0 = *(const float4*)(Ap0);
    float4 av1 = *(const float4*)(Ap1);
    float4 bv0 = *(const float4*)(Bp0);
    float4 bv1 = *(const float4*)(Bp1);

    for (int k0 = 0; k0 < K; k0 += 16) {
        __syncthreads();
        As[aCol + 0][aRow] = av0.x;
        As[aCol + 1][aRow] = av0.y;
        As[aCol + 2][aRow] = av0.z;
        As[aCol + 3][aRow] = av0.w;
        As[aCol + 0][aRow + 64] = av1.x;
        As[aCol + 1][aRow + 64] = av1.y;
        As[aCol + 2][aRow + 64] = av1.z;
        As[aCol + 3][aRow + 64] = av1.w;
        *(float4*)&Bs[bRow][bCol]     = bv0;
        *(float4*)&Bs[bRow + 8][bCol] = bv1;
        __syncthreads();

        // prefetch next slab (overlaps with compute below)
        bool more = (k0 + 16) < K;
        float4 nav0, nav1, nbv0, nbv1;
        if (more) {
            nav0 = *(const float4*)(Ap0 + k0 + 16);
            nav1 = *(const float4*)(Ap1 + k0 + 16);
            nbv0 = *(const float4*)(Bp0 + (size_t)(k0 + 16) * N);
            nbv1 = *(const float4*)(Bp1 + (size_t)(k0 + 16) * N);
        }

#pragma unroll
        for (int kk = 0; kk < 16; kk++) {
            float a[8], b[8];
            *(float4*)&a[0] = *(const float4*)&As[kk][ty * 8];
            *(float4*)&a[4] = *(const float4*)&As[kk][ty * 8 + 4];
            *(float4*)&b[0] = *(const float4*)&Bs[kk][tx * 8];
            *(float4*)&b[4] = *(const float4*)&Bs[kk][tx * 8 + 4];
#pragma unroll
            for (int i = 0; i < 8; i++)
#pragma unroll
                for (int j = 0; j < 8; j++) acc[i][j] += a[i] * b[j];
        }
        if (more) { av0 = nav0; av1 = nav1; bv0 = nbv0; bv1 = nbv1; }
    }

    int row0 = bm * 128 + ty * 8;
    int col0 = bn * 128 + tx * 8;
#pragma unroll
    for (int i = 0; i < 8; i++) {
        size_t base = (size_t)(row0 + i) * N + col0;
#pragma unroll
        for (int j = 0; j < 8; j++) {
            float v = acc[i][j] + bias[col0 + j];
            if (EPI == 1) v = gelu_tanh(v);
            if (EPI == 2) v += res[base + j];
            C[base + j] = v;
        }
    }
}

// ---------------- Causal attention: 64x64 tiles, register-blocked ----------
// grid: (S/64, H, B), block: 128 threads.
// Thread map: tx = tid&15 (4 key/dim cols), ty = tid>>4 (8 query rows).
// Dynamic smem: Qt[64][64] (d-major), Kt[64][64] (d-major), Vs[64][64], Ps[64][68]
#define AT_QT(d,q) sm[(d) * 64 + (q)]
#define AT_KT(d,k) sm[4096 + (d) * 64 + (k)]
#define AT_VS(k,d) sm[8192 + (k) * 64 + (d)]
#define AT_PS(q,k) sm[12288 + (q) * 68 + (k)]
#define ATTN_SMEM ((12288 + 64 * 68) * 4)

__global__ __launch_bounds__(128)
void attn_kernel(const float* __restrict__ qkv, float* __restrict__ out)
{
    extern __shared__ float sm[];
    int qt = (int)gridDim.x - 1 - (int)blockIdx.x;  // heavy blocks first
    int h = blockIdx.y, b = blockIdx.z;
    int tid = threadIdx.x;
    int tx = tid & 15, ty = tid >> 4;
    int q0 = qt * 64;

    // load Q tile transposed (d-major), pre-scaled by 1/sqrt(64)
    {
        int qq = tid >> 1;
        int d0 = (tid & 1) * 32;
        const float* src = qkv + ((size_t)(b * SS + q0 + qq) * 3 + 0) * DD + h * HDIM + d0;
#pragma unroll
        for (int c = 0; c < 32; c += 4) {
            float4 v = *(const float4*)(src + c);
            AT_QT(d0 + c + 0, qq) = v.x * 0.125f;
            AT_QT(d0 + c + 1, qq) = v.y * 0.125f;
            AT_QT(d0 + c + 2, qq) = v.z * 0.125f;
            AT_QT(d0 + c + 3, qq) = v.w * 0.125f;
        }
    }

    float acc[8][4];
    float mrun[8], lrun[8];
#pragma unroll
    for (int i = 0; i < 8; i++) {
        mrun[i] = -1e30f; lrun[i] = 0.f;
#pragma unroll
        for (int d = 0; d < 4; d++) acc[i][d] = 0.f;
    }

    for (int kt = 0; kt <= qt; kt++) {
        __syncthreads();   // protect Kt/Vs/Ps (and Qt on first iter)
        // load K transposed + V natural
        {
            int kk = tid >> 1;
            int d0 = (tid & 1) * 32;
            const float* ks = qkv + ((size_t)(b * SS + kt * 64 + kk) * 3 + 1) * DD + h * HDIM + d0;
            const float* vs = qkv + ((size_t)(b * SS + kt * 64 + kk) * 3 + 2) * DD + h * HDIM + d0;
#pragma unroll
            for (int c = 0; c < 32; c += 4) {
                float4 kv4 = *(const float4*)(ks + c);
                AT_KT(d0 + c + 0, kk) = kv4.x;
                AT_KT(d0 + c + 1, kk) = kv4.y;
                AT_KT(d0 + c + 2, kk) = kv4.z;
                AT_KT(d0 + c + 3, kk) = kv4.w;
                *(float4*)&AT_VS(kk, d0 + c) = *(const float4*)(vs + c);
            }
        }
        __syncthreads();

        // S = Q K^T : 8x4 microtile per thread
        float s[8][4];
#pragma unroll
        for (int i = 0; i < 8; i++)
#pragma unroll
            for (int j = 0; j < 4; j++) s[i][j] = 0.f;
        for (int d = 0; d < 64; d++) {
            float a[8], kb[4];
            *(float4*)&a[0] = *(const float4*)&AT_QT(d, ty * 8);
            *(float4*)&a[4] = *(const float4*)&AT_QT(d, ty * 8 + 4);
            *(float4*)&kb[0] = *(const float4*)&AT_KT(d, tx * 4);
#pragma unroll
            for (int i = 0; i < 8; i++)
#pragma unroll
                for (int j = 0; j < 4; j++) s[i][j] += a[i] * kb[j];
        }
        // causal mask on diagonal tile
        if (kt == qt) {
#pragma unroll
            for (int i = 0; i < 8; i++)
#pragma unroll
                for (int j = 0; j < 4; j++)
                    if (tx * 4 + j > ty * 8 + i) s[i][j] = -1e30f;
        }
        // online softmax per row (16-lane shuffle reduction across tx)
#pragma unroll
        for (int i = 0; i < 8; i++) {
            float mt = fmaxf(fmaxf(s[i][0], s[i][1]), fmaxf(s[i][2], s[i][3]));
#pragma unroll
            for (int o = 1; o <= 8; o <<= 1)
                mt = fmaxf(mt, __shfl_xor_sync(0xffffffffu, mt, o));
            float nm = fmaxf(mrun[i], mt);
            float corr = __expf(mrun[i] - nm);
            float p0 = __expf(s[i][0] - nm);
            float p1 = __expf(s[i][1] - nm);
            float p2 = __expf(s[i][2] - nm);
            float p3 = __expf(s[i][3] - nm);
            *(float4*)&AT_PS(ty * 8 + i, tx * 4) = make_float4(p0, p1, p2, p3);
            float ps = p0 + p1 + p2 + p3;
#pragma unroll
            for (int o = 1; o <= 8; o <<= 1)
                ps += __shfl_xor_sync(0xffffffffu, ps, o);
            lrun[i] = lrun[i] * corr + ps;
            mrun[i] = nm;
            acc[i][0] *= corr; acc[i][1] *= corr; acc[i][2] *= corr; acc[i][3] *= corr;
        }
        __syncthreads();
        // O += P V
        for (int k = 0; k < 64; k++) {
            float vb[4];
            *(float4*)&vb[0] = *(const float4*)&AT_VS(k, tx * 4);
#pragma unroll
            for (int i = 0; i < 8; i++) {
                float p = AT_PS(ty * 8 + i, k);
                acc[i][0] += p * vb[0];
                acc[i][1] += p * vb[1];
                acc[i][2] += p * vb[2];
                acc[i][3] += p * vb[3];
            }
        }
    }

    // normalize + write out
#pragma unroll
    for (int i = 0; i < 8; i++) {
        float inv = 1.0f / lrun[i];
        int q = q0 + ty * 8 + i;
        float4 o;
        o.x = acc[i][0] * inv; o.y = acc[i][1] * inv;
        o.z = acc[i][2] * inv; o.w = acc[i][3] * inv;
        *(float4*)(out + (size_t)(b * SS + q) * DD + h * HDIM + tx * 4) = o;
    }
}

// ---------------- launch ---------------------------------------------------
extern "C" void kernel_launch(void* const* d_in, const int* in_sizes, int n_in,
                              void* d_out, int out_size)
{
    const float* x    = (const float*)d_in[0];
    const float* pos  = (const float*)d_in[1];
    const float* ln1g = (const float*)d_in[2];
    const float* ln1b = (const float*)d_in[3];
    const float* wqkv = (const float*)d_in[4];
    const float* bqkv = (const float*)d_in[5];
    const float* wo   = (const float*)d_in[6];
    const float* bo   = (const float*)d_in[7];
    const float* ln2g = (const float*)d_in[8];
    const float* ln2b = (const float*)d_in[9];
    const float* wfc  = (const float*)d_in[10];
    const float* bfc  = (const float*)d_in[11];
    const float* wpr  = (const float*)d_in[12];
    const float* bpr  = (const float*)d_in[13];
    float* out = (float*)d_out;

    float *p_h, *p_qkv, *p_attn, *p_x2, *p_m, *p_ff;
    cudaGetSymbolAddress((void**)&p_h,    g_h);
    cudaGetSymbolAddress((void**)&p_qkv,  g_qkv);
    cudaGetSymbolAddress((void**)&p_attn, g_attn);
    cudaGetSymbolAddress((void**)&p_x2,   g_x2);
    cudaGetSymbolAddress((void**)&p_m,    g_m);
    cudaGetSymbolAddress((void**)&p_ff,   g_ff);

    cudaFuncSetAttribute(attn_kernel,
                         cudaFuncAttributeMaxDynamicSharedMemorySize, ATTN_SMEM);

    // 1) h = LN1(x) + pos
    ln_kernel<<<ROWS, 256>>>(x, ln1g, ln1b, pos, p_h);

    // 2) qkv = h @ w_qkv + b_qkv      [4096 x 3072]
    gemm_kernel<0><<<dim3(3 * DD / 128, ROWS / 128), 256>>>(
        p_h, wqkv, bqkv, nullptr, p_qkv, ROWS, 3 * DD, DD);

    // 3) causal attention -> [B,S,D]
    attn_kernel<<<dim3(SS / 64, HH, BB), 128, ATTN_SMEM>>>(p_qkv, p_attn);

    // 4) x2 = x + attn @ w_o + b_o    [4096 x 1024]
    gemm_kernel<2><<<dim3(DD / 128, ROWS / 128), 256>>>(
        p_attn, wo, bo, x, p_x2, ROWS, DD, DD);

    // 5) m = LN2(x2)
    ln_kernel<<<ROWS, 256>>>(p_x2, ln2g, ln2b, nullptr, p_m);

    // 6) ff = gelu(m @ w_fc + b_fc)   [4096 x 4096]
    gemm_kernel<1><<<dim3(DFFN / 128, ROWS / 128), 256>>>(
        p_m, wfc, bfc, nullptr, p_ff, ROWS, DFFN, DD);

    // 7) out = x2 + ff @ w_proj + b_proj  [4096 x 1024]
    gemm_kernel<2><<<dim3(DD / 128, ROWS / 128), 256>>>(
        p_ff, wpr, bpr, p_x2, out, ROWS, DD, DFFN);
}

// round 5
// speedup vs baseline: 1.9461x; 1.3624x over previous
#include <cuda_runtime.h>
#include <cuda_bf16.h>
#include <math.h>
#include <stdint.h>

// Problem constants
#define BB   2
#define SS   2048
#define DD   1024
#define HH   16
#define HDIM 64
#define DFFN 4096
#define ROWS (BB * SS)   // 4096

// -------- scratch (static device globals; no allocation) --------
__device__ __align__(16) __nv_bfloat16 g_h_hi[ROWS * DD], g_h_lo[ROWS * DD];
__device__ __align__(16) float         g_qkv[ROWS * 3 * DD];
__device__ __align__(16) __nv_bfloat16 g_at_hi[ROWS * DD], g_at_lo[ROWS * DD];
__device__ __align__(16) float         g_x2[ROWS * DD];
__device__ __align__(16) __nv_bfloat16 g_m_hi[ROWS * DD], g_m_lo[ROWS * DD];
__device__ __align__(16) __nv_bfloat16 g_ff_hi[ROWS * DFFN], g_ff_lo[ROWS * DFFN];
// transposed, split weights: Wt[n][k] = W[k][n]
__device__ __align__(16) __nv_bfloat16 g_wqkv_hi[3 * DD * DD], g_wqkv_lo[3 * DD * DD];
__device__ __align__(16) __nv_bfloat16 g_wo_hi[DD * DD],       g_wo_lo[DD * DD];
__device__ __align__(16) __nv_bfloat16 g_wfc_hi[DFFN * DD],    g_wfc_lo[DFFN * DD];
__device__ __align__(16) __nv_bfloat16 g_wpr_hi[DD * DFFN],    g_wpr_lo[DD * DFFN];

// ======================= portable PTX helpers ==============================
__device__ __forceinline__ uint32_t smem_u32(const void* p) {
    uint32_t a;
    asm("{ .reg .u64 t; cvta.to.shared.u64 t, %1; cvt.u32.u64 %0, t; }" : "=r"(a) : "l"(p));
    return a;
}

__device__ __forceinline__ void cp_async16(uint32_t saddr, const void* gaddr) {
    asm volatile("cp.async.cg.shared.global [%0], [%1], 16;" :: "r"(saddr), "l"(gaddr));
}
__device__ __forceinline__ void cp_async_wait_all() {
    asm volatile("cp.async.commit_group;\n\tcp.async.wait_group 0;" ::: "memory");
}

__device__ __forceinline__ void ldsm_x4(uint32_t* r, uint32_t addr) {
    asm volatile("ldmatrix.sync.aligned.m8n8.x4.shared.b16 {%0,%1,%2,%3}, [%4];"
        : "=r"(r[0]), "=r"(r[1]), "=r"(r[2]), "=r"(r[3]) : "r"(addr));
}

__device__ __forceinline__ void mma16816(float* c, const uint32_t* a, const uint32_t* b) {
    asm volatile(
        "mma.sync.aligned.m16n8k16.row.col.f32.bf16.bf16.f32 "
        "{%0,%1,%2,%3}, {%4,%5,%6,%7}, {%8,%9}, {%0,%1,%2,%3};"
        : "+f"(c[0]), "+f"(c[1]), "+f"(c[2]), "+f"(c[3])
        : "r"(a[0]), "r"(a[1]), "r"(a[2]), "r"(a[3]), "r"(b[0]), "r"(b[1]));
}

// ======================= small math helpers ================================
__device__ __forceinline__ float gelu_tanh(float x) {
    float x3 = x * x * x;
    float t = tanhf(0.7978845608028654f * (x + 0.044715f * x3));
    return 0.5f * x * (1.0f + t);
}

__device__ __forceinline__ void store_hilo4(__nv_bfloat16* oh, __nv_bfloat16* ol,
                                            size_t idx, float4 v)
{
    __nv_bfloat16 h0 = __float2bfloat16(v.x), h1 = __float2bfloat16(v.y);
    __nv_bfloat16 h2 = __float2bfloat16(v.z), h3 = __float2bfloat16(v.w);
    float l0 = v.x - __bfloat162float(h0), l1 = v.y - __bfloat162float(h1);
    float l2 = v.z - __bfloat162float(h2), l3 = v.w - __bfloat162float(h3);
    *(__nv_bfloat162*)(oh + idx)     = __halves2bfloat162(h0, h1);
    *(__nv_bfloat162*)(oh + idx + 2) = __halves2bfloat162(h2, h3);
    *(__nv_bfloat162*)(ol + idx)     = __halves2bfloat162(__float2bfloat16(l0), __float2bfloat16(l1));
    *(__nv_bfloat162*)(ol + idx + 2) = __halves2bfloat162(__float2bfloat16(l2), __float2bfloat16(l3));
}

__device__ __forceinline__ void store_hilo2(__nv_bfloat16* oh, __nv_bfloat16* ol,
                                            size_t idx, float a, float b)
{
    __nv_bfloat16 h0 = __float2bfloat16(a), h1 = __float2bfloat16(b);
    float l0 = a - __bfloat162float(h0), l1 = b - __bfloat162float(h1);
    *(__nv_bfloat162*)(oh + idx) = __halves2bfloat162(h0, h1);
    *(__nv_bfloat162*)(ol + idx) = __halves2bfloat162(__float2bfloat16(l0), __float2bfloat16(l1));
}

// ============ weight transpose + bf16 split: Wt[n][k] = W[k][n] ============
__global__ void wsplit_t(const float* __restrict__ W, __nv_bfloat16* __restrict__ Th,
                         __nv_bfloat16* __restrict__ Tl, int K, int N)
{
    __shared__ float t[32][33];
    int bx = blockIdx.x, by = blockIdx.y;
    int x = threadIdx.x, y = threadIdx.y;
#pragma unroll
    for (int i = 0; i < 32; i += 8)
        t[y + i][x] = W[(size_t)(by * 32 + y + i) * N + bx * 32 + x];
    __syncthreads();
#pragma unroll
    for (int i = 0; i < 32; i += 8) {
        float v = t[x][y + i];
        __nv_bfloat16 h = __float2bfloat16(v);
        float lo = v - __bfloat162float(h);
        size_t o = (size_t)(bx * 32 + y + i) * K + by * 32 + x;
        Th[o] = h;
        Tl[o] = __float2bfloat16(lo);
    }
}

// ---------------- LayerNorm (+ optional pos add) -> bf16 hi/lo -------------
__global__ void ln_bf(const float* __restrict__ x,
                      const float* __restrict__ gam,
                      const float* __restrict__ bet,
                      const float* __restrict__ pos,
                      __nv_bfloat16* __restrict__ oh,
                      __nv_bfloat16* __restrict__ ol)
{
    int row = blockIdx.x;
    int tid = threadIdx.x;
    const float4* xr = (const float4*)(x + (size_t)row * DD);
    float4 v = xr[tid];
    float s  = v.x + v.y + v.z + v.w;
    float ss = v.x * v.x + v.y * v.y + v.z * v.z + v.w * v.w;
#pragma unroll
    for (int o = 16; o > 0; o >>= 1) {
        s  += __shfl_xor_sync(0xffffffffu, s,  o);
        ss += __shfl_xor_sync(0xffffffffu, ss, o);
    }
    __shared__ float sb[8], sb2[8], stats[2];
    int wid = tid >> 5, lane = tid & 31;
    if (lane == 0) { sb[wid] = s; sb2[wid] = ss; }
    __syncthreads();
    if (tid == 0) {
        float ts = 0.f, tss = 0.f;
#pragma unroll
        for (int i = 0; i < 8; i++) { ts += sb[i]; tss += sb2[i]; }
        float mu  = ts  * (1.0f / DD);
        float var = tss * (1.0f / DD) - mu * mu;
        stats[0] = mu;
        stats[1] = rsqrtf(var + 1e-5f);
    }
    __syncthreads();
    float mu = stats[0], rs = stats[1];
    int c = tid * 4;
    float4 gg = *(const float4*)(gam + c);
    float4 bb = *(const float4*)(bet + c);
    float4 o4;
    o4.x = (v.x - mu) * rs * gg.x + bb.x;
    o4.y = (v.y - mu) * rs * gg.y + bb.y;
    o4.z = (v.z - mu) * rs * gg.z + bb.z;
    o4.w = (v.w - mu) * rs * gg.w + bb.w;
    if (pos) {
        int srow = row % SS;
        float4 p = *(const float4*)(pos + (size_t)srow * DD + c);
        o4.x += p.x; o4.y += p.y; o4.z += p.z; o4.w += p.w;
    }
    store_hilo4(oh, ol, (size_t)row * DD + c, o4);
}

// =================== mma.sync bf16-split GEMM ==============================
// C[M,N] = A[M,K] @ Wt[N,K]^T + bias (+epilogue). 128x128 CTA tile,
// 256 threads (8 warps as 4m x 2n, 32x64 warp tile), K-chunks of 64.
// 3 passes (hi*hi + lo*hi + hi*lo) into fp32 accumulators.
// EPI: 0 = +bias -> fp32 ; 1 = gelu(+bias) -> bf16 hi/lo ; 2 = +bias+res -> fp32
#define OFF_AH 0
#define OFF_AL 16384
#define OFF_BH 32768
#define OFF_BL 49152
#define TCG_SMEM 65536

// smem row layout: 128 rows x 64 bf16 (128B), 16B-chunk XOR swizzle by row%8
__device__ __forceinline__ uint32_t swz(int row, int chunk16) {
    return (uint32_t)(row * 128 + ((chunk16 * 16) ^ ((row & 7) << 4)));
}

__device__ __forceinline__ void cp_tile(uint32_t sbase,
                                        const __nv_bfloat16* __restrict__ src,
                                        int row0, int k0, int ldk, int tid)
{
#pragma unroll
    for (int j = 0; j < 4; j++) {
        int v = tid + (j << 8);          // 0..1023
        int r = v >> 3, c = v & 7;       // row, 16B-chunk
        cp_async16(sbase + swz(r, c), src + (size_t)(row0 + r) * ldk + k0 + c * 8);
    }
}

template <int EPI>
__global__ __launch_bounds__(256, 2)
void tc_gemm(const __nv_bfloat16* __restrict__ Ahi, const __nv_bfloat16* __restrict__ Alo,
             const __nv_bfloat16* __restrict__ Bhi, const __nv_bfloat16* __restrict__ Blo,
             const float* __restrict__ bias, const float* __restrict__ res,
             float* __restrict__ Cf, __nv_bfloat16* __restrict__ Chi,
             __nv_bfloat16* __restrict__ Clo, int M, int N, int K)
{
    extern __shared__ __align__(128) char smc[];
    uint32_t sb = smem_u32(smc);
    int tid = threadIdx.x, wid = tid >> 5, lane = tid & 31;
    int warp_m = wid >> 1, warp_n = wid & 1;
    int bn = blockIdx.x, bm = blockIdx.y;

    float acc[2][8][4];
#pragma unroll
    for (int mi = 0; mi < 2; mi++)
#pragma unroll
        for (int ni = 0; ni < 8; ni++)
#pragma unroll
            for (int q = 0; q < 4; q++) acc[mi][ni][q] = 0.f;

    // ldmatrix per-thread address bases (swizzled)
    // A frag: row = tile_row + (lane&7) + ((lane>>3)&1)*8 ; col16off = (lane>>4)*16 (bytes)
    int lrA = (lane & 7) + ((lane >> 3) & 1) * 8;
    uint32_t lcA = (uint32_t)((lane >> 4) << 4);
    uint32_t aBase[2], alBase[2];
#pragma unroll
    for (int mi = 0; mi < 2; mi++) {
        int row = warp_m * 32 + mi * 16 + lrA;
        uint32_t b2 = (uint32_t)(row * 128 + ((row & 7) << 4));
        aBase[mi]  = sb + OFF_AH + b2;
        alBase[mi] = sb + OFF_AL + b2;
    }
    // B frag: row = tile_n + (lane&7) + ((lane>>4)&1)*8 ; col16off = ((lane>>3)&1)*16
    int lrB = (lane & 7) + ((lane >> 4) & 1) * 8;
    uint32_t lcB = (uint32_t)(((lane >> 3) & 1) << 4);
    uint32_t bBase[4], blBase[4];
#pragma unroll
    for (int p = 0; p < 4; p++) {
        int row = warp_n * 64 + p * 16 + lrB;
        uint32_t b2 = (uint32_t)(row * 128 + ((row & 7) << 4));
        bBase[p]  = sb + OFF_BH + b2;
        blBase[p] = sb + OFF_BL + b2;
    }

    int nchunk = K >> 6;
    for (int ch = 0; ch < nchunk; ch++) {
        int k0 = ch << 6;
        __syncthreads();
        cp_tile(sb + OFF_AH, Ahi, bm * 128, k0, K, tid);
        cp_tile(sb + OFF_AL, Alo, bm * 128, k0, K, tid);
        cp_tile(sb + OFF_BH, Bhi, bn * 128, k0, K, tid);
        cp_tile(sb + OFF_BL, Blo, bn * 128, k0, K, tid);
        cp_async_wait_all();
        __syncthreads();

#pragma unroll
        for (int ks = 0; ks < 4; ks++) {
            uint32_t k2 = (uint32_t)(ks << 5);   // ks*16 cols * 2 bytes
            uint32_t ah[2][4], bh[8][2];
            // load A hi + B hi
#pragma unroll
            for (int mi = 0; mi < 2; mi++)
                ldsm_x4(ah[mi], aBase[mi] ^ (k2 + lcA));
#pragma unroll
            for (int p = 0; p < 4; p++) {
                uint32_t r4[4];
                ldsm_x4(r4, bBase[p] ^ (k2 + lcB));
                bh[2 * p][0] = r4[0]; bh[2 * p][1] = r4[1];
                bh[2 * p + 1][0] = r4[2]; bh[2 * p + 1][1] = r4[3];
            }
            // pass 1: hi * hi
#pragma unroll
            for (int mi = 0; mi < 2; mi++)
#pragma unroll
                for (int ni = 0; ni < 8; ni++)
                    mma16816(acc[mi][ni], ah[mi], bh[ni]);
            // pass 2: lo * hi
            {
                uint32_t al[2][4];
#pragma unroll
                for (int mi = 0; mi < 2; mi++)
                    ldsm_x4(al[mi], alBase[mi] ^ (k2 + lcA));
#pragma unroll
                for (int mi = 0; mi < 2; mi++)
#pragma unroll
                    for (int ni = 0; ni < 8; ni++)
                        mma16816(acc[mi][ni], al[mi], bh[ni]);
            }
            // pass 3: hi * lo
            {
                uint32_t bl[8][2];
#pragma unroll
                for (int p = 0; p < 4; p++) {
                    uint32_t r4[4];
                    ldsm_x4(r4, blBase[p] ^ (k2 + lcB));
                    bl[2 * p][0] = r4[0]; bl[2 * p][1] = r4[1];
                    bl[2 * p + 1][0] = r4[2]; bl[2 * p + 1][1] = r4[3];
                }
#pragma unroll
                for (int mi = 0; mi < 2; mi++)
#pragma unroll
                    for (int ni = 0; ni < 8; ni++)
                        mma16816(acc[mi][ni], ah[mi], bl[ni]);
            }
        }
    }

    // epilogue
    int g = lane >> 2, tig = lane & 3;
#pragma unroll
    for (int mi = 0; mi < 2; mi++) {
#pragma unroll
        for (int half = 0; half < 2; half++) {
            int r = bm * 128 + warp_m * 32 + mi * 16 + g + half * 8;
#pragma unroll
            for (int ni = 0; ni < 8; ni++) {
                int c = bn * 128 + warp_n * 64 + ni * 8 + tig * 2;
                float v0 = acc[mi][ni][half * 2 + 0];
                float v1 = acc[mi][ni][half * 2 + 1];
                float2 bv = *(const float2*)(bias + c);
                v0 += bv.x; v1 += bv.y;
                size_t base = (size_t)r * N + c;
                if (EPI == 1) {
                    store_hilo2(Chi, Clo, base, gelu_tanh(v0), gelu_tanh(v1));
                } else {
                    if (EPI == 2) {
                        float2 rv = *(const float2*)(res + base);
                        v0 += rv.x; v1 += rv.y;
                    }
                    *(float2*)(Cf + base) = make_float2(v0, v1);
                }
            }
        }
    }
}

// ---------------- Causal attention: 64x64 tiles, register-blocked ----------
#define AT_QT(d,q) sm[(d) * 64 + (q)]
#define AT_KT(d,k) sm[4096 + (d) * 64 + (k)]
#define AT_VS(k,d) sm[8192 + (k) * 64 + (d)]
#define AT_PS(q,k) sm[12288 + (q) * 68 + (k)]
#define ATTN_SMEM ((12288 + 64 * 68) * 4)

__global__ __launch_bounds__(128)
void attn_kernel(const float* __restrict__ qkv,
                 __nv_bfloat16* __restrict__ oh, __nv_bfloat16* __restrict__ ol)
{
    extern __shared__ float sm[];
    int qt = (int)gridDim.x - 1 - (int)blockIdx.x;  // heavy blocks first
    int h = blockIdx.y, b = blockIdx.z;
    int tid = threadIdx.x;
    int tx = tid & 15, ty = tid >> 4;
    int q0 = qt * 64;

    {
        int qq = tid >> 1;
        int d0 = (tid & 1) * 32;
        const float* src = qkv + ((size_t)(b * SS + q0 + qq) * 3 + 0) * DD + h * HDIM + d0;
#pragma unroll
        for (int c = 0; c < 32; c += 4) {
            float4 v = *(const float4*)(src + c);
            AT_QT(d0 + c + 0, qq) = v.x * 0.125f;
            AT_QT(d0 + c + 1, qq) = v.y * 0.125f;
            AT_QT(d0 + c + 2, qq) = v.z * 0.125f;
            AT_QT(d0 + c + 3, qq) = v.w * 0.125f;
        }
    }

    float acc[8][4];
    float mrun[8], lrun[8];
#pragma unroll
    for (int i = 0; i < 8; i++) {
        mrun[i] = -1e30f; lrun[i] = 0.f;
#pragma unroll
        for (int d = 0; d < 4; d++) acc[i][d] = 0.f;
    }

    for (int kt = 0; kt <= qt; kt++) {
        __syncthreads();
        {
            int kk = tid >> 1;
            int d0 = (tid & 1) * 32;
            const float* ks = qkv + ((size_t)(b * SS + kt * 64 + kk) * 3 + 1) * DD + h * HDIM + d0;
            const float* vs = qkv + ((size_t)(b * SS + kt * 64 + kk) * 3 + 2) * DD + h * HDIM + d0;
#pragma unroll
            for (int c = 0; c < 32; c += 4) {
                float4 kv4 = *(const float4*)(ks + c);
                AT_KT(d0 + c + 0, kk) = kv4.x;
                AT_KT(d0 + c + 1, kk) = kv4.y;
                AT_KT(d0 + c + 2, kk) = kv4.z;
                AT_KT(d0 + c + 3, kk) = kv4.w;
                *(float4*)&AT_VS(kk, d0 + c) = *(const float4*)(vs + c);
            }
        }
        __syncthreads();

        float s[8][4];
#pragma unroll
        for (int i = 0; i < 8; i++)
#pragma unroll
            for (int j = 0; j < 4; j++) s[i][j] = 0.f;
        for (int d = 0; d < 64; d++) {
            float a[8], kb[4];
            *(float4*)&a[0] = *(const float4*)&AT_QT(d, ty * 8);
            *(float4*)&a[4] = *(const float4*)&AT_QT(d, ty * 8 + 4);
            *(float4*)&kb[0] = *(const float4*)&AT_KT(d, tx * 4);
#pragma unroll
            for (int i = 0; i < 8; i++)
#pragma unroll
                for (int j = 0; j < 4; j++) s[i][j] += a[i] * kb[j];
        }
        if (kt == qt) {
#pragma unroll
            for (int i = 0; i < 8; i++)
#pragma unroll
                for (int j = 0; j < 4; j++)
                    if (tx * 4 + j > ty * 8 + i) s[i][j] = -1e30f;
        }
#pragma unroll
        for (int i = 0; i < 8; i++) {
            float mt = fmaxf(fmaxf(s[i][0], s[i][1]), fmaxf(s[i][2], s[i][3]));
#pragma unroll
            for (int o = 1; o <= 8; o <<= 1)
                mt = fmaxf(mt, __shfl_xor_sync(0xffffffffu, mt, o));
            float nm = fmaxf(mrun[i], mt);
            float corr = __expf(mrun[i] - nm);
            float p0 = __expf(s[i][0] - nm);
            float p1 = __expf(s[i][1] - nm);
            float p2 = __expf(s[i][2] - nm);
            float p3 = __expf(s[i][3] - nm);
            *(float4*)&AT_PS(ty * 8 + i, tx * 4) = make_float4(p0, p1, p2, p3);
            float ps = p0 + p1 + p2 + p3;
#pragma unroll
            for (int o = 1; o <= 8; o <<= 1)
                ps += __shfl_xor_sync(0xffffffffu, ps, o);
            lrun[i] = lrun[i] * corr + ps;
            mrun[i] = nm;
            acc[i][0] *= corr; acc[i][1] *= corr; acc[i][2] *= corr; acc[i][3] *= corr;
        }
        __syncthreads();
        for (int k = 0; k < 64; k++) {
            float vb[4];
            *(float4*)&vb[0] = *(const float4*)&AT_VS(k, tx * 4);
#pragma unroll
            for (int i = 0; i < 8; i++) {
                float p = AT_PS(ty * 8 + i, k);
                acc[i][0] += p * vb[0];
                acc[i][1] += p * vb[1];
                acc[i][2] += p * vb[2];
                acc[i][3] += p * vb[3];
            }
        }
    }

#pragma unroll
    for (int i = 0; i < 8; i++) {
        float inv = 1.0f / lrun[i];
        int q = q0 + ty * 8 + i;
        store_hilo4(oh, ol, (size_t)(b * SS + q) * DD + h * HDIM + tx * 4,
                    make_float4(acc[i][0] * inv, acc[i][1] * inv,
                                acc[i][2] * inv, acc[i][3] * inv));
    }
}

// ---------------- launch ---------------------------------------------------
extern "C" void kernel_launch(void* const* d_in, const int* in_sizes, int n_in,
                              void* d_out, int out_size)
{
    const float* x    = (const float*)d_in[0];
    const float* pos  = (const float*)d_in[1];
    const float* ln1g = (const float*)d_in[2];
    const float* ln1b = (const float*)d_in[3];
    const float* wqkv = (const float*)d_in[4];
    const float* bqkv = (const float*)d_in[5];
    const float* wo   = (const float*)d_in[6];
    const float* bo   = (const float*)d_in[7];
    const float* ln2g = (const float*)d_in[8];
    const float* ln2b = (const float*)d_in[9];
    const float* wfc  = (const float*)d_in[10];
    const float* bfc  = (const float*)d_in[11];
    const float* wpr  = (const float*)d_in[12];
    const float* bpr  = (const float*)d_in[13];
    float* out = (float*)d_out;

    __nv_bfloat16 *p_h_hi, *p_h_lo, *p_at_hi, *p_at_lo, *p_m_hi, *p_m_lo, *p_ff_hi, *p_ff_lo;
    __nv_bfloat16 *p_wqkv_hi, *p_wqkv_lo, *p_wo_hi, *p_wo_lo, *p_wfc_hi, *p_wfc_lo, *p_wpr_hi, *p_wpr_lo;
    float *p_qkv, *p_x2;
    cudaGetSymbolAddress((void**)&p_h_hi, g_h_hi);   cudaGetSymbolAddress((void**)&p_h_lo, g_h_lo);
    cudaGetSymbolAddress((void**)&p_qkv, g_qkv);
    cudaGetSymbolAddress((void**)&p_at_hi, g_at_hi); cudaGetSymbolAddress((void**)&p_at_lo, g_at_lo);
    cudaGetSymbolAddress((void**)&p_x2, g_x2);
    cudaGetSymbolAddress((void**)&p_m_hi, g_m_hi);   cudaGetSymbolAddress((void**)&p_m_lo, g_m_lo);
    cudaGetSymbolAddress((void**)&p_ff_hi, g_ff_hi); cudaGetSymbolAddress((void**)&p_ff_lo, g_ff_lo);
    cudaGetSymbolAddress((void**)&p_wqkv_hi, g_wqkv_hi); cudaGetSymbolAddress((void**)&p_wqkv_lo, g_wqkv_lo);
    cudaGetSymbolAddress((void**)&p_wo_hi, g_wo_hi);     cudaGetSymbolAddress((void**)&p_wo_lo, g_wo_lo);
    cudaGetSymbolAddress((void**)&p_wfc_hi, g_wfc_hi);   cudaGetSymbolAddress((void**)&p_wfc_lo, g_wfc_lo);
    cudaGetSymbolAddress((void**)&p_wpr_hi, g_wpr_hi);   cudaGetSymbolAddress((void**)&p_wpr_lo, g_wpr_lo);

    cudaFuncSetAttribute(attn_kernel, cudaFuncAttributeMaxDynamicSharedMemorySize, ATTN_SMEM);
    cudaFuncSetAttribute(tc_gemm<0>, cudaFuncAttributeMaxDynamicSharedMemorySize, TCG_SMEM);
    cudaFuncSetAttribute(tc_gemm<1>, cudaFuncAttributeMaxDynamicSharedMemorySize, TCG_SMEM);
    cudaFuncSetAttribute(tc_gemm<2>, cudaFuncAttributeMaxDynamicSharedMemorySize, TCG_SMEM);

    dim3 tb(32, 8);
    // 0) weight transpose + split (deterministic, every launch)
    wsplit_t<<<dim3(3 * DD / 32, DD / 32), tb>>>(wqkv, p_wqkv_hi, p_wqkv_lo, DD, 3 * DD);
    wsplit_t<<<dim3(DD / 32, DD / 32), tb>>>(wo, p_wo_hi, p_wo_lo, DD, DD);
    wsplit_t<<<dim3(DFFN / 32, DD / 32), tb>>>(wfc, p_wfc_hi, p_wfc_lo, DD, DFFN);
    wsplit_t<<<dim3(DD / 32, DFFN / 32), tb>>>(wpr, p_wpr_hi, p_wpr_lo, DFFN, DD);

    // 1) h = LN1(x) + pos  -> bf16 hi/lo
    ln_bf<<<ROWS, 256>>>(x, ln1g, ln1b, pos, p_h_hi, p_h_lo);

    // 2) qkv = h @ w_qkv + b_qkv -> fp32 [4096 x 3072]
    tc_gemm<0><<<dim3(3 * DD / 128, ROWS / 128), 256, TCG_SMEM>>>(
        p_h_hi, p_h_lo, p_wqkv_hi, p_wqkv_lo, bqkv, nullptr,
        p_qkv, nullptr, nullptr, ROWS, 3 * DD, DD);

    // 3) causal attention -> bf16 hi/lo
    attn_kernel<<<dim3(SS / 64, HH, BB), 128, ATTN_SMEM>>>(p_qkv, p_at_hi, p_at_lo);

    // 4) x2 = x + attn @ w_o + b_o -> fp32
    tc_gemm<2><<<dim3(DD / 128, ROWS / 128), 256, TCG_SMEM>>>(
        p_at_hi, p_at_lo, p_wo_hi, p_wo_lo, bo, x,
        p_x2, nullptr, nullptr, ROWS, DD, DD);

    // 5) m = LN2(x2) -> bf16 hi/lo
    ln_bf<<<ROWS, 256>>>(p_x2, ln2g, ln2b, nullptr, p_m_hi, p_m_lo);

    // 6) ff = gelu(m @ w_fc + b_fc) -> bf16 hi/lo [4096 x 4096]
    tc_gemm<1><<<dim3(DFFN / 128, ROWS / 128), 256, TCG_SMEM>>>(
        p_m_hi, p_m_lo, p_wfc_hi, p_wfc_lo, bfc, nullptr,
        nullptr, p_ff_hi, p_ff_lo, ROWS, DFFN, DD);

    // 7) out = x2 + ff @ w_proj + b_proj -> fp32
    tc_gemm<2><<<dim3(DD / 128, ROWS / 128), 256, TCG_SMEM>>>(
        p_ff_hi, p_ff_lo, p_wpr_hi, p_wpr_lo, bpr, p_x2,
        out, nullptr, nullptr, ROWS, DD, DFFN);
}

// round 6
// speedup vs baseline: 2.9662x; 1.5242x over previous
#include <cuda_runtime.h>
#include <cuda_bf16.h>
#include <math.h>
#include <stdint.h>

// Problem constants
#define BB   2
#define SS   2048
#define DD   1024
#define HH   16
#define HDIM 64
#define DFFN 4096
#define ROWS (BB * SS)   // 4096

// -------- scratch (static device globals; no allocation) --------
__device__ __align__(16) __nv_bfloat16 g_h_hi[ROWS * DD], g_h_lo[ROWS * DD];
__device__ __align__(16) float         g_qkv[ROWS * 3 * DD];
__device__ __align__(16) __nv_bfloat16 g_at_hi[ROWS * DD], g_at_lo[ROWS * DD];
__device__ __align__(16) float         g_x2[ROWS * DD];
__device__ __align__(16) __nv_bfloat16 g_m_hi[ROWS * DD], g_m_lo[ROWS * DD];
__device__ __align__(16) __nv_bfloat16 g_ff_hi[ROWS * DFFN], g_ff_lo[ROWS * DFFN];
// transposed, split weights: Wt[n][k] = W[k][n]
__device__ __align__(16) __nv_bfloat16 g_wqkv_hi[3 * DD * DD], g_wqkv_lo[3 * DD * DD];
__device__ __align__(16) __nv_bfloat16 g_wo_hi[DD * DD],       g_wo_lo[DD * DD];
__device__ __align__(16) __nv_bfloat16 g_wfc_hi[DFFN * DD],    g_wfc_lo[DFFN * DD];
__device__ __align__(16) __nv_bfloat16 g_wpr_hi[DD * DFFN],    g_wpr_lo[DD * DFFN];

// ======================= portable PTX helpers ==============================
__device__ __forceinline__ uint32_t smem_u32(const void* p) {
    uint32_t a;
    asm("{ .reg .u64 t; cvta.to.shared.u64 t, %1; cvt.u32.u64 %0, t; }" : "=r"(a) : "l"(p));
    return a;
}

__device__ __forceinline__ void cp_async16(uint32_t saddr, const void* gaddr) {
    asm volatile("cp.async.cg.shared.global [%0], [%1], 16;" :: "r"(saddr), "l"(gaddr));
}
__device__ __forceinline__ void cp_commit() {
    asm volatile("cp.async.commit_group;" ::: "memory");
}
template <int N>
__device__ __forceinline__ void cp_wait() {
    asm volatile("cp.async.wait_group %0;" :: "n"(N) : "memory");
}

__device__ __forceinline__ void ldsm_x4(uint32_t* r, uint32_t addr) {
    asm volatile("ldmatrix.sync.aligned.m8n8.x4.shared.b16 {%0,%1,%2,%3}, [%4];"
        : "=r"(r[0]), "=r"(r[1]), "=r"(r[2]), "=r"(r[3]) : "r"(addr));
}

__device__ __forceinline__ void mma16816(float* c, const uint32_t* a, const uint32_t* b) {
    asm volatile(
        "mma.sync.aligned.m16n8k16.row.col.f32.bf16.bf16.f32 "
        "{%0,%1,%2,%3}, {%4,%5,%6,%7}, {%8,%9}, {%0,%1,%2,%3};"
        : "+f"(c[0]), "+f"(c[1]), "+f"(c[2]), "+f"(c[3])
        : "r"(a[0]), "r"(a[1]), "r"(a[2]), "r"(a[3]), "r"(b[0]), "r"(b[1]));
}

// ======================= small math helpers ================================
__device__ __forceinline__ float gelu_tanh(float x) {
    float x3 = x * x * x;
    float t = tanhf(0.7978845608028654f * (x + 0.044715f * x3));
    return 0.5f * x * (1.0f + t);
}

__device__ __forceinline__ void store_hilo4(__nv_bfloat16* oh, __nv_bfloat16* ol,
                                            size_t idx, float4 v)
{
    __nv_bfloat16 h0 = __float2bfloat16(v.x), h1 = __float2bfloat16(v.y);
    __nv_bfloat16 h2 = __float2bfloat16(v.z), h3 = __float2bfloat16(v.w);
    float l0 = v.x - __bfloat162float(h0), l1 = v.y - __bfloat162float(h1);
    float l2 = v.z - __bfloat162float(h2), l3 = v.w - __bfloat162float(h3);
    *(__nv_bfloat162*)(oh + idx)     = __halves2bfloat162(h0, h1);
    *(__nv_bfloat162*)(oh + idx + 2) = __halves2bfloat162(h2, h3);
    *(__nv_bfloat162*)(ol + idx)     = __halves2bfloat162(__float2bfloat16(l0), __float2bfloat16(l1));
    *(__nv_bfloat162*)(ol + idx + 2) = __halves2bfloat162(__float2bfloat16(l2), __float2bfloat16(l3));
}

__device__ __forceinline__ void store_hilo2(__nv_bfloat16* oh, __nv_bfloat16* ol,
                                            size_t idx, float a, float b)
{
    __nv_bfloat16 h0 = __float2bfloat16(a), h1 = __float2bfloat16(b);
    float l0 = a - __bfloat162float(h0), l1 = b - __bfloat162float(h1);
    *(__nv_bfloat162*)(oh + idx) = __halves2bfloat162(h0, h1);
    *(__nv_bfloat162*)(ol + idx) = __halves2bfloat162(__float2bfloat16(l0), __float2bfloat16(l1));
}

// ============ weight transpose + bf16 split: Wt[n][k] = W[k][n] ============
__global__ void wsplit_t(const float* __restrict__ W, __nv_bfloat16* __restrict__ Th,
                         __nv_bfloat16* __restrict__ Tl, int K, int N)
{
    __shared__ float t[32][33];
    int bx = blockIdx.x, by = blockIdx.y;
    int x = threadIdx.x, y = threadIdx.y;
#pragma unroll
    for (int i = 0; i < 32; i += 8)
        t[y + i][x] = W[(size_t)(by * 32 + y + i) * N + bx * 32 + x];
    __syncthreads();
#pragma unroll
    for (int i = 0; i < 32; i += 8) {
        float v = t[x][y + i];
        __nv_bfloat16 h = __float2bfloat16(v);
        float lo = v - __bfloat162float(h);
        size_t o = (size_t)(bx * 32 + y + i) * K + by * 32 + x;
        Th[o] = h;
        Tl[o] = __float2bfloat16(lo);
    }
}

// ---------------- LayerNorm (+ optional pos add) -> bf16 hi/lo -------------
__global__ void ln_bf(const float* __restrict__ x,
                      const float* __restrict__ gam,
                      const float* __restrict__ bet,
                      const float* __restrict__ pos,
                      __nv_bfloat16* __restrict__ oh,
                      __nv_bfloat16* __restrict__ ol)
{
    int row = blockIdx.x;
    int tid = threadIdx.x;
    const float4* xr = (const float4*)(x + (size_t)row * DD);
    float4 v = xr[tid];
    float s  = v.x + v.y + v.z + v.w;
    float ss = v.x * v.x + v.y * v.y + v.z * v.z + v.w * v.w;
#pragma unroll
    for (int o = 16; o > 0; o >>= 1) {
        s  += __shfl_xor_sync(0xffffffffu, s,  o);
        ss += __shfl_xor_sync(0xffffffffu, ss, o);
    }
    __shared__ float sb[8], sb2[8], stats[2];
    int wid = tid >> 5, lane = tid & 31;
    if (lane == 0) { sb[wid] = s; sb2[wid] = ss; }
    __syncthreads();
    if (tid == 0) {
        float ts = 0.f, tss = 0.f;
#pragma unroll
        for (int i = 0; i < 8; i++) { ts += sb[i]; tss += sb2[i]; }
        float mu  = ts  * (1.0f / DD);
        float var = tss * (1.0f / DD) - mu * mu;
        stats[0] = mu;
        stats[1] = rsqrtf(var + 1e-5f);
    }
    __syncthreads();
    float mu = stats[0], rs = stats[1];
    int c = tid * 4;
    float4 gg = *(const float4*)(gam + c);
    float4 bb = *(const float4*)(bet + c);
    float4 o4;
    o4.x = (v.x - mu) * rs * gg.x + bb.x;
    o4.y = (v.y - mu) * rs * gg.y + bb.y;
    o4.z = (v.z - mu) * rs * gg.z + bb.z;
    o4.w = (v.w - mu) * rs * gg.w + bb.w;
    if (pos) {
        int srow = row % SS;
        float4 p = *(const float4*)(pos + (size_t)srow * DD + c);
        o4.x += p.x; o4.y += p.y; o4.z += p.z; o4.w += p.w;
    }
    store_hilo4(oh, ol, (size_t)row * DD + c, o4);
}

// =================== mma.sync bf16-split GEMM (pipelined) ==================
// C[M,N] = A[M,K] @ Wt[N,K]^T + bias (+epilogue). 128x128 CTA tile,
// 256 threads (8 warps as 4m x 2n, 32x64 warp tile).
// K-chunks of 32, two cp.async stages (load ch+1 overlaps MMA of ch).
// 3 passes (hi*hi + lo*hi + hi*lo) into fp32 accumulators.
// EPI: 0 = +bias -> fp32 ; 1 = gelu(+bias) -> bf16 hi/lo ; 2 = +bias+res -> fp32
// Stage layout (32 KB): AH 0, AL 8K, BH 16K, BL 24K; 128 rows x 32 bf16 (64B rows).
#define OFF_AH 0
#define OFF_AL 8192
#define OFF_BH 16384
#define OFF_BL 24576
#define STAGE  32768
#define TCG_SMEM (2 * STAGE)

// 64B rows: 4 x 16B chunks; conflict-free swizzle chunk ^= (row>>1)&3
__device__ __forceinline__ uint32_t swz32(int row, int chunk) {
    return (uint32_t)(row * 64 + (((chunk ^ (row >> 1)) & 3) << 4));
}

__device__ __forceinline__ void cp_stage(uint32_t sbase,
                                         const __nv_bfloat16* __restrict__ Ahi,
                                         const __nv_bfloat16* __restrict__ Alo,
                                         const __nv_bfloat16* __restrict__ Bhi,
                                         const __nv_bfloat16* __restrict__ Blo,
                                         int am0, int bn0, int k0, int ldkA, int ldkB, int tid)
{
#pragma unroll
    for (int j = 0; j < 2; j++) {
        int v = tid + (j << 8);          // 0..511
        int r = v >> 2, c = v & 3;       // row, 16B-chunk
        uint32_t so = swz32(r, c);
        size_t goA = (size_t)(am0 + r) * ldkA + k0 + c * 8;
        size_t goB = (size_t)(bn0 + r) * ldkB + k0 + c * 8;
        cp_async16(sbase + OFF_AH + so, Ahi + goA);
        cp_async16(sbase + OFF_AL + so, Alo + goA);
        cp_async16(sbase + OFF_BH + so, Bhi + goB);
        cp_async16(sbase + OFF_BL + so, Blo + goB);
    }
}

template <int EPI>
__global__ __launch_bounds__(256, 2)
void tc_gemm(const __nv_bfloat16* __restrict__ Ahi, const __nv_bfloat16* __restrict__ Alo,
             const __nv_bfloat16* __restrict__ Bhi, const __nv_bfloat16* __restrict__ Blo,
             const float* __restrict__ bias, const float* __restrict__ res,
             float* __restrict__ Cf, __nv_bfloat16* __restrict__ Chi,
             __nv_bfloat16* __restrict__ Clo, int M, int N, int K)
{
    extern __shared__ __align__(128) char smc[];
    uint32_t sb = smem_u32(smc);
    int tid = threadIdx.x, wid = tid >> 5, lane = tid & 31;
    int warp_m = wid >> 1, warp_n = wid & 1;
    int bn = blockIdx.x, bm = blockIdx.y;
    int am0 = bm * 128, bn0 = bn * 128;

    float acc[2][8][4];
#pragma unroll
    for (int mi = 0; mi < 2; mi++)
#pragma unroll
        for (int ni = 0; ni < 8; ni++)
#pragma unroll
            for (int q = 0; q < 4; q++) acc[mi][ni][q] = 0.f;

    // ldmatrix per-thread bases. addr = stage + base2 + (kx ^ x) where kx = ks*32.
    int lrA = (lane & 7) + ((lane >> 3) & 1) * 8;
    uint32_t cAoff = (uint32_t)((lane >> 4) << 4);
    uint32_t aB[2], aX[2];
#pragma unroll
    for (int mi = 0; mi < 2; mi++) {
        int row = warp_m * 32 + mi * 16 + lrA;
        aB[mi] = (uint32_t)(row * 64);
        aX[mi] = cAoff ^ (uint32_t)((((row >> 1) & 3)) << 4);
    }
    int lrB = (lane & 7) + ((lane >> 4) & 1) * 8;
    uint32_t cBoff = (uint32_t)(((lane >> 3) & 1) << 4);
    uint32_t bB[4], bX[4];
#pragma unroll
    for (int p = 0; p < 4; p++) {
        int row = warp_n * 64 + p * 16 + lrB;
        bB[p] = (uint32_t)(row * 64);
        bX[p] = cBoff ^ (uint32_t)((((row >> 1) & 3)) << 4);
    }

    int nchunk = K >> 5;
    cp_stage(sb, Ahi, Alo, Bhi, Blo, am0, bn0, 0, K, K, tid);
    cp_commit();

    for (int ch = 0; ch < nchunk; ch++) {
        uint32_t st = sb + (uint32_t)(ch & 1) * STAGE;
        if (ch + 1 < nchunk) {
            cp_stage(sb + (uint32_t)((ch + 1) & 1) * STAGE,
                     Ahi, Alo, Bhi, Blo, am0, bn0, (ch + 1) << 5, K, K, tid);
            cp_commit();
            cp_wait<1>();
        } else {
            cp_wait<0>();
        }
        __syncthreads();

#pragma unroll
        for (int ks = 0; ks < 2; ks++) {
            uint32_t kx = (uint32_t)(ks << 5);
            uint32_t ah[2][4], bh[8][2];
#pragma unroll
            for (int mi = 0; mi < 2; mi++)
                ldsm_x4(ah[mi], st + OFF_AH + aB[mi] + (kx ^ aX[mi]));
#pragma unroll
            for (int p = 0; p < 4; p++) {
                uint32_t r4[4];
                ldsm_x4(r4, st + OFF_BH + bB[p] + (kx ^ bX[p]));
                bh[2 * p][0] = r4[0]; bh[2 * p][1] = r4[1];
                bh[2 * p + 1][0] = r4[2]; bh[2 * p + 1][1] = r4[3];
            }
            // pass 1: hi * hi
#pragma unroll
            for (int mi = 0; mi < 2; mi++)
#pragma unroll
                for (int ni = 0; ni < 8; ni++)
                    mma16816(acc[mi][ni], ah[mi], bh[ni]);
            // pass 2: lo * hi
            {
                uint32_t al[2][4];
#pragma unroll
                for (int mi = 0; mi < 2; mi++)
                    ldsm_x4(al[mi], st + OFF_AL + aB[mi] + (kx ^ aX[mi]));
#pragma unroll
                for (int mi = 0; mi < 2; mi++)
#pragma unroll
                    for (int ni = 0; ni < 8; ni++)
                        mma16816(acc[mi][ni], al[mi], bh[ni]);
            }
            // pass 3: hi * lo
            {
                uint32_t bl[8][2];
#pragma unroll
                for (int p = 0; p < 4; p++) {
                    uint32_t r4[4];
                    ldsm_x4(r4, st + OFF_BL + bB[p] + (kx ^ bX[p]));
                    bl[2 * p][0] = r4[0]; bl[2 * p][1] = r4[1];
                    bl[2 * p + 1][0] = r4[2]; bl[2 * p + 1][1] = r4[3];
                }
#pragma unroll
                for (int mi = 0; mi < 2; mi++)
#pragma unroll
                    for (int ni = 0; ni < 8; ni++)
                        mma16816(acc[mi][ni], ah[mi], bl[ni]);
            }
        }
        __syncthreads();
    }

    // epilogue
    int g = lane >> 2, tig = lane & 3;
#pragma unroll
    for (int mi = 0; mi < 2; mi++) {
#pragma unroll
        for (int half = 0; half < 2; half++) {
            int r = bm * 128 + warp_m * 32 + mi * 16 + g + half * 8;
#pragma unroll
            for (int ni = 0; ni < 8; ni++) {
                int c = bn * 128 + warp_n * 64 + ni * 8 + tig * 2;
                float v0 = acc[mi][ni][half * 2 + 0];
                float v1 = acc[mi][ni][half * 2 + 1];
                float2 bv = *(const float2*)(bias + c);
                v0 += bv.x; v1 += bv.y;
                size_t base = (size_t)r * N + c;
                if (EPI == 1) {
                    store_hilo2(Chi, Clo, base, gelu_tanh(v0), gelu_tanh(v1));
                } else {
                    if (EPI == 2) {
                        float2 rv = *(const float2*)(res + base);
                        v0 += rv.x; v1 += rv.y;
                    }
                    *(float2*)(Cf + base) = make_float2(v0, v1);
                }
            }
        }
    }
}

// ---------------- Causal attention: 64x64 tiles, register-blocked ----------
#define AT_QT(d,q) sm[(d) * 64 + (q)]
#define AT_KT(d,k) sm[4096 + (d) * 64 + (k)]
#define AT_VS(k,d) sm[8192 + (k) * 64 + (d)]
#define AT_PS(q,k) sm[12288 + (q) * 68 + (k)]
#define ATTN_SMEM ((12288 + 64 * 68) * 4)

__global__ __launch_bounds__(128)
void attn_kernel(const float* __restrict__ qkv,
                 __nv_bfloat16* __restrict__ oh, __nv_bfloat16* __restrict__ ol)
{
    extern __shared__ float sm[];
    int qt = (int)gridDim.x - 1 - (int)blockIdx.x;  // heavy blocks first
    int h = blockIdx.y, b = blockIdx.z;
    int tid = threadIdx.x;
    int tx = tid & 15, ty = tid >> 4;
    int q0 = qt * 64;

    {
        int qq = tid >> 1;
        int d0 = (tid & 1) * 32;
        const float* src = qkv + ((size_t)(b * SS + q0 + qq) * 3 + 0) * DD + h * HDIM + d0;
#pragma unroll
        for (int c = 0; c < 32; c += 4) {
            float4 v = *(const float4*)(src + c);
            AT_QT(d0 + c + 0, qq) = v.x * 0.125f;
            AT_QT(d0 + c + 1, qq) = v.y * 0.125f;
            AT_QT(d0 + c + 2, qq) = v.z * 0.125f;
            AT_QT(d0 + c + 3, qq) = v.w * 0.125f;
        }
    }

    float acc[8][4];
    float mrun[8], lrun[8];
#pragma unroll
    for (int i = 0; i < 8; i++) {
        mrun[i] = -1e30f; lrun[i] = 0.f;
#pragma unroll
        for (int d = 0; d < 4; d++) acc[i][d] = 0.f;
    }

    for (int kt = 0; kt <= qt; kt++) {
        __syncthreads();
        {
            int kk = tid >> 1;
            int d0 = (tid & 1) * 32;
            const float* ks = qkv + ((size_t)(b * SS + kt * 64 + kk) * 3 + 1) * DD + h * HDIM + d0;
            const float* vs = qkv + ((size_t)(b * SS + kt * 64 + kk) * 3 + 2) * DD + h * HDIM + d0;
#pragma unroll
            for (int c = 0; c < 32; c += 4) {
                float4 kv4 = *(const float4*)(ks + c);
                AT_KT(d0 + c + 0, kk) = kv4.x;
                AT_KT(d0 + c + 1, kk) = kv4.y;
                AT_KT(d0 + c + 2, kk) = kv4.z;
                AT_KT(d0 + c + 3, kk) = kv4.w;
                *(float4*)&AT_VS(kk, d0 + c) = *(const float4*)(vs + c);
            }
        }
        __syncthreads();

        float s[8][4];
#pragma unroll
        for (int i = 0; i < 8; i++)
#pragma unroll
            for (int j = 0; j < 4; j++) s[i][j] = 0.f;
        for (int d = 0; d < 64; d++) {
            float a[8], kb[4];
            *(float4*)&a[0] = *(const float4*)&AT_QT(d, ty * 8);
            *(float4*)&a[4] = *(const float4*)&AT_QT(d, ty * 8 + 4);
            *(float4*)&kb[0] = *(const float4*)&AT_KT(d, tx * 4);
#pragma unroll
            for (int i = 0; i < 8; i++)
#pragma unroll
                for (int j = 0; j < 4; j++) s[i][j] += a[i] * kb[j];
        }
        if (kt == qt) {
#pragma unroll
            for (int i = 0; i < 8; i++)
#pragma unroll
                for (int j = 0; j < 4; j++)
                    if (tx * 4 + j > ty * 8 + i) s[i][j] = -1e30f;
        }
#pragma unroll
        for (int i = 0; i < 8; i++) {
            float mt = fmaxf(fmaxf(s[i][0], s[i][1]), fmaxf(s[i][2], s[i][3]));
#pragma unroll
            for (int o = 1; o <= 8; o <<= 1)
                mt = fmaxf(mt, __shfl_xor_sync(0xffffffffu, mt, o));
            float nm = fmaxf(mrun[i], mt);
            float corr = __expf(mrun[i] - nm);
            float p0 = __expf(s[i][0] - nm);
            float p1 = __expf(s[i][1] - nm);
            float p2 = __expf(s[i][2] - nm);
            float p3 = __expf(s[i][3] - nm);
            *(float4*)&AT_PS(ty * 8 + i, tx * 4) = make_float4(p0, p1, p2, p3);
            float ps = p0 + p1 + p2 + p3;
#pragma unroll
            for (int o = 1; o <= 8; o <<= 1)
                ps += __shfl_xor_sync(0xffffffffu, ps, o);
            lrun[i] = lrun[i] * corr + ps;
            mrun[i] = nm;
            acc[i][0] *= corr; acc[i][1] *= corr; acc[i][2] *= corr; acc[i][3] *= corr;
        }
        __syncthreads();
        for (int k = 0; k < 64; k++) {
            float vb[4];
            *(float4*)&vb[0] = *(const float4*)&AT_VS(k, tx * 4);
#pragma unroll
            for (int i = 0; i < 8; i++) {
                float p = AT_PS(ty * 8 + i, k);
                acc[i][0] += p * vb[0];
                acc[i][1] += p * vb[1];
                acc[i][2] += p * vb[2];
                acc[i][3] += p * vb[3];
            }
        }
    }

#pragma unroll
    for (int i = 0; i < 8; i++) {
        float inv = 1.0f / lrun[i];
        int q = q0 + ty * 8 + i;
        store_hilo4(oh, ol, (size_t)(b * SS + q) * DD + h * HDIM + tx * 4,
                    make_float4(acc[i][0] * inv, acc[i][1] * inv,
                                acc[i][2] * inv, acc[i][3] * inv));
    }
}

// ---------------- launch ---------------------------------------------------
extern "C" void kernel_launch(void* const* d_in, const int* in_sizes, int n_in,
                              void* d_out, int out_size)
{
    const float* x    = (const float*)d_in[0];
    const float* pos  = (const float*)d_in[1];
    const float* ln1g = (const float*)d_in[2];
    const float* ln1b = (const float*)d_in[3];
    const float* wqkv = (const float*)d_in[4];
    const float* bqkv = (const float*)d_in[5];
    const float* wo   = (const float*)d_in[6];
    const float* bo   = (const float*)d_in[7];
    const float* ln2g = (const float*)d_in[8];
    const float* ln2b = (const float*)d_in[9];
    const float* wfc  = (const float*)d_in[10];
    const float* bfc  = (const float*)d_in[11];
    const float* wpr  = (const float*)d_in[12];
    const float* bpr  = (const float*)d_in[13];
    float* out = (float*)d_out;

    __nv_bfloat16 *p_h_hi, *p_h_lo, *p_at_hi, *p_at_lo, *p_m_hi, *p_m_lo, *p_ff_hi, *p_ff_lo;
    __nv_bfloat16 *p_wqkv_hi, *p_wqkv_lo, *p_wo_hi, *p_wo_lo, *p_wfc_hi, *p_wfc_lo, *p_wpr_hi, *p_wpr_lo;
    float *p_qkv, *p_x2;
    cudaGetSymbolAddress((void**)&p_h_hi, g_h_hi);   cudaGetSymbolAddress((void**)&p_h_lo, g_h_lo);
    cudaGetSymbolAddress((void**)&p_qkv, g_qkv);
    cudaGetSymbolAddress((void**)&p_at_hi, g_at_hi); cudaGetSymbolAddress((void**)&p_at_lo, g_at_lo);
    cudaGetSymbolAddress((void**)&p_x2, g_x2);
    cudaGetSymbolAddress((void**)&p_m_hi, g_m_hi);   cudaGetSymbolAddress((void**)&p_m_lo, g_m_lo);
    cudaGetSymbolAddress((void**)&p_ff_hi, g_ff_hi); cudaGetSymbolAddress((void**)&p_ff_lo, g_ff_lo);
    cudaGetSymbolAddress((void**)&p_wqkv_hi, g_wqkv_hi); cudaGetSymbolAddress((void**)&p_wqkv_lo, g_wqkv_lo);
    cudaGetSymbolAddress((void**)&p_wo_hi, g_wo_hi);     cudaGetSymbolAddress((void**)&p_wo_lo, g_wo_lo);
    cudaGetSymbolAddress((void**)&p_wfc_hi, g_wfc_hi);   cudaGetSymbolAddress((void**)&p_wfc_lo, g_wfc_lo);
    cudaGetSymbolAddress((void**)&p_wpr_hi, g_wpr_hi);   cudaGetSymbolAddress((void**)&p_wpr_lo, g_wpr_lo);

    cudaFuncSetAttribute(attn_kernel, cudaFuncAttributeMaxDynamicSharedMemorySize, ATTN_SMEM);
    cudaFuncSetAttribute(tc_gemm<0>, cudaFuncAttributeMaxDynamicSharedMemorySize, TCG_SMEM);
    cudaFuncSetAttribute(tc_gemm<1>, cudaFuncAttributeMaxDynamicSharedMemorySize, TCG_SMEM);
    cudaFuncSetAttribute(tc_gemm<2>, cudaFuncAttributeMaxDynamicSharedMemorySize, TCG_SMEM);

    dim3 tb(32, 8);
    // 0) weight transpose + split (deterministic, every launch)
    wsplit_t<<<dim3(3 * DD / 32, DD / 32), tb>>>(wqkv, p_wqkv_hi, p_wqkv_lo, DD, 3 * DD);
    wsplit_t<<<dim3(DD / 32, DD / 32), tb>>>(wo, p_wo_hi, p_wo_lo, DD, DD);
    wsplit_t<<<dim3(DFFN / 32, DD / 32), tb>>>(wfc, p_wfc_hi, p_wfc_lo, DD, DFFN);
    wsplit_t<<<dim3(DD / 32, DFFN / 32), tb>>>(wpr, p_wpr_hi, p_wpr_lo, DFFN, DD);

    // 1) h = LN1(x) + pos  -> bf16 hi/lo
    ln_bf<<<ROWS, 256>>>(x, ln1g, ln1b, pos, p_h_hi, p_h_lo);

    // 2) qkv = h @ w_qkv + b_qkv -> fp32 [4096 x 3072]
    tc_gemm<0><<<dim3(3 * DD / 128, ROWS / 128), 256, TCG_SMEM>>>(
        p_h_hi, p_h_lo, p_wqkv_hi, p_wqkv_lo, bqkv, nullptr,
        p_qkv, nullptr, nullptr, ROWS, 3 * DD, DD);

    // 3) causal attention -> bf16 hi/lo
    attn_kernel<<<dim3(SS / 64, HH, BB), 128, ATTN_SMEM>>>(p_qkv, p_at_hi, p_at_lo);

    // 4) x2 = x + attn @ w_o + b_o -> fp32
    tc_gemm<2><<<dim3(DD / 128, ROWS / 128), 256, TCG_SMEM>>>(
        p_at_hi, p_at_lo, p_wo_hi, p_wo_lo, bo, x,
        p_x2, nullptr, nullptr, ROWS, DD, DD);

    // 5) m = LN2(x2) -> bf16 hi/lo
    ln_bf<<<ROWS, 256>>>(p_x2, ln2g, ln2b, nullptr, p_m_hi, p_m_lo);

    // 6) ff = gelu(m @ w_fc + b_fc) -> bf16 hi/lo [4096 x 4096]
    tc_gemm<1><<<dim3(DFFN / 128, ROWS / 128), 256, TCG_SMEM>>>(
        p_m_hi, p_m_lo, p_wfc_hi, p_wfc_lo, bfc, nullptr,
        nullptr, p_ff_hi, p_ff_lo, ROWS, DFFN, DD);

    // 7) out = x2 + ff @ w_proj + b_proj -> fp32
    tc_gemm<2><<<dim3(DD / 128, ROWS / 128), 256, TCG_SMEM>>>(
        p_ff_hi, p_ff_lo, p_wpr_hi, p_wpr_lo, bpr, p_x2,
        out, nullptr, nullptr, ROWS, DD, DFFN);
}

// round 7
// speedup vs baseline: 2.9886x; 1.0075x over previous
#include <cuda_runtime.h>
#include <cuda_bf16.h>
#include <math.h>
#include <stdint.h>

// Problem constants
#define BB   2
#define SS   2048
#define DD   1024
#define HH   16
#define HDIM 64
#define DFFN 4096
#define ROWS (BB * SS)   // 4096

// -------- scratch (static device globals; no allocation) --------
__device__ __align__(16) __nv_bfloat16 g_h_hi[ROWS * DD], g_h_lo[ROWS * DD];
__device__ __align__(16) float         g_qkv[ROWS * 3 * DD];
__device__ __align__(16) __nv_bfloat16 g_at_hi[ROWS * DD], g_at_lo[ROWS * DD];
__device__ __align__(16) float         g_x2[ROWS * DD];
__device__ __align__(16) __nv_bfloat16 g_m_hi[ROWS * DD], g_m_lo[ROWS * DD];
__device__ __align__(16) __nv_bfloat16 g_ff_hi[ROWS * DFFN], g_ff_lo[ROWS * DFFN];
// transposed, split weights: Wt[n][k] = W[k][n]
__device__ __align__(16) __nv_bfloat16 g_wqkv_hi[3 * DD * DD], g_wqkv_lo[3 * DD * DD];
__device__ __align__(16) __nv_bfloat16 g_wo_hi[DD * DD],       g_wo_lo[DD * DD];
__device__ __align__(16) __nv_bfloat16 g_wfc_hi[DFFN * DD],    g_wfc_lo[DFFN * DD];
__device__ __align__(16) __nv_bfloat16 g_wpr_hi[DD * DFFN],    g_wpr_lo[DD * DFFN];

// ======================= portable PTX helpers ==============================
__device__ __forceinline__ uint32_t smem_u32(const void* p) {
    uint32_t a;
    asm("{ .reg .u64 t; cvta.to.shared.u64 t, %1; cvt.u32.u64 %0, t; }" : "=r"(a) : "l"(p));
    return a;
}

__device__ __forceinline__ void cp_async16(uint32_t saddr, const void* gaddr) {
    asm volatile("cp.async.cg.shared.global [%0], [%1], 16;" :: "r"(saddr), "l"(gaddr));
}
__device__ __forceinline__ void cp_commit() {
    asm volatile("cp.async.commit_group;" ::: "memory");
}
template <int N>
__device__ __forceinline__ void cp_wait() {
    asm volatile("cp.async.wait_group %0;" :: "n"(N) : "memory");
}

__device__ __forceinline__ void ldsm_x4(uint32_t* r, uint32_t addr) {
    asm volatile("ldmatrix.sync.aligned.m8n8.x4.shared.b16 {%0,%1,%2,%3}, [%4];"
        : "=r"(r[0]), "=r"(r[1]), "=r"(r[2]), "=r"(r[3]) : "r"(addr));
}

__device__ __forceinline__ void mma16816(float* c, const uint32_t* a, const uint32_t* b) {
    asm volatile(
        "mma.sync.aligned.m16n8k16.row.col.f32.bf16.bf16.f32 "
        "{%0,%1,%2,%3}, {%4,%5,%6,%7}, {%8,%9}, {%0,%1,%2,%3};"
        : "+f"(c[0]), "+f"(c[1]), "+f"(c[2]), "+f"(c[3])
        : "r"(a[0]), "r"(a[1]), "r"(a[2]), "r"(a[3]), "r"(b[0]), "r"(b[1]));
}

// ======================= small math helpers ================================
__device__ __forceinline__ float gelu_tanh(float x) {
    float x3 = x * x * x;
    float t = tanhf(0.7978845608028654f * (x + 0.044715f * x3));
    return 0.5f * x * (1.0f + t);
}

__device__ __forceinline__ void store_hilo4(__nv_bfloat16* oh, __nv_bfloat16* ol,
                                            size_t idx, float4 v)
{
    __nv_bfloat16 h0 = __float2bfloat16(v.x), h1 = __float2bfloat16(v.y);
    __nv_bfloat16 h2 = __float2bfloat16(v.z), h3 = __float2bfloat16(v.w);
    float l0 = v.x - __bfloat162float(h0), l1 = v.y - __bfloat162float(h1);
    float l2 = v.z - __bfloat162float(h2), l3 = v.w - __bfloat162float(h3);
    *(__nv_bfloat162*)(oh + idx)     = __halves2bfloat162(h0, h1);
    *(__nv_bfloat162*)(oh + idx + 2) = __halves2bfloat162(h2, h3);
    *(__nv_bfloat162*)(ol + idx)     = __halves2bfloat162(__float2bfloat16(l0), __float2bfloat16(l1));
    *(__nv_bfloat162*)(ol + idx + 2) = __halves2bfloat162(__float2bfloat16(l2), __float2bfloat16(l3));
}

__device__ __forceinline__ void store_hilo2(__nv_bfloat16* oh, __nv_bfloat16* ol,
                                            size_t idx, float a, float b)
{
    __nv_bfloat16 h0 = __float2bfloat16(a), h1 = __float2bfloat16(b);
    float l0 = a - __bfloat162float(h0), l1 = b - __bfloat162float(h1);
    *(__nv_bfloat162*)(oh + idx) = __halves2bfloat162(h0, h1);
    *(__nv_bfloat162*)(ol + idx) = __halves2bfloat162(__float2bfloat16(l0), __float2bfloat16(l1));
}

// ============ weight transpose + bf16 split: Wt[n][k] = W[k][n] ============
__global__ void wsplit_t(const float* __restrict__ W, __nv_bfloat16* __restrict__ Th,
                         __nv_bfloat16* __restrict__ Tl, int K, int N)
{
    __shared__ float t[32][33];
    int bx = blockIdx.x, by = blockIdx.y;
    int x = threadIdx.x, y = threadIdx.y;
#pragma unroll
    for (int i = 0; i < 32; i += 8)
        t[y + i][x] = W[(size_t)(by * 32 + y + i) * N + bx * 32 + x];
    __syncthreads();
#pragma unroll
    for (int i = 0; i < 32; i += 8) {
        float v = t[x][y + i];
        __nv_bfloat16 h = __float2bfloat16(v);
        float lo = v - __bfloat162float(h);
        size_t o = (size_t)(bx * 32 + y + i) * K + by * 32 + x;
        Th[o] = h;
        Tl[o] = __float2bfloat16(lo);
    }
}

// ---------------- LayerNorm (+ optional pos add) -> bf16 hi/lo -------------
__global__ void ln_bf(const float* __restrict__ x,
                      const float* __restrict__ gam,
                      const float* __restrict__ bet,
                      const float* __restrict__ pos,
                      __nv_bfloat16* __restrict__ oh,
                      __nv_bfloat16* __restrict__ ol)
{
    int row = blockIdx.x;
    int tid = threadIdx.x;
    const float4* xr = (const float4*)(x + (size_t)row * DD);
    float4 v = xr[tid];
    float s  = v.x + v.y + v.z + v.w;
    float ss = v.x * v.x + v.y * v.y + v.z * v.z + v.w * v.w;
#pragma unroll
    for (int o = 16; o > 0; o >>= 1) {
        s  += __shfl_xor_sync(0xffffffffu, s,  o);
        ss += __shfl_xor_sync(0xffffffffu, ss, o);
    }
    __shared__ float sb[8], sb2[8], stats[2];
    int wid = tid >> 5, lane = tid & 31;
    if (lane == 0) { sb[wid] = s; sb2[wid] = ss; }
    __syncthreads();
    if (tid == 0) {
        float ts = 0.f, tss = 0.f;
#pragma unroll
        for (int i = 0; i < 8; i++) { ts += sb[i]; tss += sb2[i]; }
        float mu  = ts  * (1.0f / DD);
        float var = tss * (1.0f / DD) - mu * mu;
        stats[0] = mu;
        stats[1] = rsqrtf(var + 1e-5f);
    }
    __syncthreads();
    float mu = stats[0], rs = stats[1];
    int c = tid * 4;
    float4 gg = *(const float4*)(gam + c);
    float4 bb = *(const float4*)(bet + c);
    float4 o4;
    o4.x = (v.x - mu) * rs * gg.x + bb.x;
    o4.y = (v.y - mu) * rs * gg.y + bb.y;
    o4.z = (v.z - mu) * rs * gg.z + bb.z;
    o4.w = (v.w - mu) * rs * gg.w + bb.w;
    if (pos) {
        int srow = row % SS;
        float4 p = *(const float4*)(pos + (size_t)srow * DD + c);
        o4.x += p.x; o4.y += p.y; o4.z += p.z; o4.w += p.w;
    }
    store_hilo4(oh, ol, (size_t)row * DD + c, o4);
}

// =================== mma.sync bf16-split GEMM (3-stage pipeline) ===========
// C[M,N] = A[M,K] @ Wt[N,K]^T + bias (+epilogue). 128x128 CTA tile,
// 256 threads (8 warps as 4m x 2n, 32x64 warp tile).
// K-chunks of 32, three cp.async stages; loads for ch+2 cover 2 chunk-times.
// One __syncthreads per chunk (wait -> barrier -> issue -> compute).
// 3 passes (hi*hi + lo*hi + hi*lo) into fp32 accumulators.
// EPI: 0 = +bias -> fp32 ; 1 = gelu(+bias) -> bf16 hi/lo ; 2 = +bias+res -> fp32
#define OFF_AH 0
#define OFF_AL 8192
#define OFF_BH 16384
#define OFF_BL 24576
#define STAGE  32768
#define NSTAGE 3
#define TCG_SMEM (NSTAGE * STAGE)

// 64B rows: 4 x 16B chunks; conflict-free swizzle chunk ^= (row>>1)&3
__device__ __forceinline__ uint32_t swz32(int row, int chunk) {
    return (uint32_t)(row * 64 + (((chunk ^ (row >> 1)) & 3) << 4));
}

__device__ __forceinline__ void cp_stage(uint32_t sbase,
                                         const __nv_bfloat16* __restrict__ Ahi,
                                         const __nv_bfloat16* __restrict__ Alo,
                                         const __nv_bfloat16* __restrict__ Bhi,
                                         const __nv_bfloat16* __restrict__ Blo,
                                         int am0, int bn0, int k0, int ldk, int tid)
{
#pragma unroll
    for (int j = 0; j < 2; j++) {
        int v = tid + (j << 8);          // 0..511
        int r = v >> 2, c = v & 3;       // row, 16B-chunk
        uint32_t so = swz32(r, c);
        size_t goA = (size_t)(am0 + r) * ldk + k0 + c * 8;
        size_t goB = (size_t)(bn0 + r) * ldk + k0 + c * 8;
        cp_async16(sbase + OFF_AH + so, Ahi + goA);
        cp_async16(sbase + OFF_AL + so, Alo + goA);
        cp_async16(sbase + OFF_BH + so, Bhi + goB);
        cp_async16(sbase + OFF_BL + so, Blo + goB);
    }
}

template <int EPI>
__global__ __launch_bounds__(256, 2)
void tc_gemm(const __nv_bfloat16* __restrict__ Ahi, const __nv_bfloat16* __restrict__ Alo,
             const __nv_bfloat16* __restrict__ Bhi, const __nv_bfloat16* __restrict__ Blo,
             const float* __restrict__ bias, const float* __restrict__ res,
             float* __restrict__ Cf, __nv_bfloat16* __restrict__ Chi,
             __nv_bfloat16* __restrict__ Clo, int M, int N, int K)
{
    extern __shared__ __align__(128) char smc[];
    uint32_t sb = smem_u32(smc);
    int tid = threadIdx.x, wid = tid >> 5, lane = tid & 31;
    int warp_m = wid >> 1, warp_n = wid & 1;
    int bn = blockIdx.x, bm = blockIdx.y;
    int am0 = bm * 128, bn0 = bn * 128;

    float acc[2][8][4];
#pragma unroll
    for (int mi = 0; mi < 2; mi++)
#pragma unroll
        for (int ni = 0; ni < 8; ni++)
#pragma unroll
            for (int q = 0; q < 4; q++) acc[mi][ni][q] = 0.f;

    // ldmatrix per-thread bases. addr = stage + base + (kx ^ x), kx = ks*32.
    int lrA = (lane & 7) + ((lane >> 3) & 1) * 8;
    uint32_t cAoff = (uint32_t)((lane >> 4) << 4);
    uint32_t aB[2], aX[2];
#pragma unroll
    for (int mi = 0; mi < 2; mi++) {
        int row = warp_m * 32 + mi * 16 + lrA;
        aB[mi] = (uint32_t)(row * 64);
        aX[mi] = cAoff ^ (uint32_t)((((row >> 1) & 3)) << 4);
    }
    int lrB = (lane & 7) + ((lane >> 4) & 1) * 8;
    uint32_t cBoff = (uint32_t)(((lane >> 3) & 1) << 4);
    uint32_t bB[4], bX[4];
#pragma unroll
    for (int p = 0; p < 4; p++) {
        int row = warp_n * 64 + p * 16 + lrB;
        bB[p] = (uint32_t)(row * 64);
        bX[p] = cBoff ^ (uint32_t)((((row >> 1) & 3)) << 4);
    }

    int nchunk = K >> 5;
    // prologue: issue stages 0 and 1
    cp_stage(sb + 0 * STAGE, Ahi, Alo, Bhi, Blo, am0, bn0, 0, K, tid);
    cp_commit();
    cp_stage(sb + 1 * STAGE, Ahi, Alo, Bhi, Blo, am0, bn0, 32, K, tid);
    cp_commit();

    int slot = 0;
    for (int ch = 0; ch < nchunk; ch++) {
        uint32_t st = sb + (uint32_t)slot * STAGE;
        cp_wait<1>();       // chunk ch resident (ch+1 may still be in flight)
        __syncthreads();    // all warps done computing ch-1 -> fill slot is free
        // issue chunk ch+2 into the slot freed by ch-1
        int nslot = slot + 2; if (nslot >= NSTAGE) nslot -= NSTAGE;
        if (ch + 2 < nchunk)
            cp_stage(sb + (uint32_t)nslot * STAGE, Ahi, Alo, Bhi, Blo,
                     am0, bn0, (ch + 2) << 5, K, tid);
        cp_commit();        // commit every iter to keep group accounting exact

#pragma unroll
        for (int ks = 0; ks < 2; ks++) {
            uint32_t kx = (uint32_t)(ks << 5);
            uint32_t ah[2][4], bh[8][2];
#pragma unroll
            for (int mi = 0; mi < 2; mi++)
                ldsm_x4(ah[mi], st + OFF_AH + aB[mi] + (kx ^ aX[mi]));
#pragma unroll
            for (int p = 0; p < 4; p++) {
                uint32_t r4[4];
                ldsm_x4(r4, st + OFF_BH + bB[p] + (kx ^ bX[p]));
                bh[2 * p][0] = r4[0]; bh[2 * p][1] = r4[1];
                bh[2 * p + 1][0] = r4[2]; bh[2 * p + 1][1] = r4[3];
            }
            // pass 1: hi * hi
#pragma unroll
            for (int mi = 0; mi < 2; mi++)
#pragma unroll
                for (int ni = 0; ni < 8; ni++)
                    mma16816(acc[mi][ni], ah[mi], bh[ni]);
            // pass 2: lo * hi
            {
                uint32_t al[2][4];
#pragma unroll
                for (int mi = 0; mi < 2; mi++)
                    ldsm_x4(al[mi], st + OFF_AL + aB[mi] + (kx ^ aX[mi]));
#pragma unroll
                for (int mi = 0; mi < 2; mi++)
#pragma unroll
                    for (int ni = 0; ni < 8; ni++)
                        mma16816(acc[mi][ni], al[mi], bh[ni]);
            }
            // pass 3: hi * lo
            {
                uint32_t bl[8][2];
#pragma unroll
                for (int p = 0; p < 4; p++) {
                    uint32_t r4[4];
                    ldsm_x4(r4, st + OFF_BL + bB[p] + (kx ^ bX[p]));
                    bl[2 * p][0] = r4[0]; bl[2 * p][1] = r4[1];
                    bl[2 * p + 1][0] = r4[2]; bl[2 * p + 1][1] = r4[3];
                }
#pragma unroll
                for (int mi = 0; mi < 2; mi++)
#pragma unroll
                    for (int ni = 0; ni < 8; ni++)
                        mma16816(acc[mi][ni], ah[mi], bl[ni]);
            }
        }
        slot++; if (slot >= NSTAGE) slot = 0;
    }

    // epilogue
    int g = lane >> 2, tig = lane & 3;
#pragma unroll
    for (int mi = 0; mi < 2; mi++) {
#pragma unroll
        for (int half = 0; half < 2; half++) {
            int r = bm * 128 + warp_m * 32 + mi * 16 + g + half * 8;
#pragma unroll
            for (int ni = 0; ni < 8; ni++) {
                int c = bn * 128 + warp_n * 64 + ni * 8 + tig * 2;
                float v0 = acc[mi][ni][half * 2 + 0];
                float v1 = acc[mi][ni][half * 2 + 1];
                float2 bv = *(const float2*)(bias + c);
                v0 += bv.x; v1 += bv.y;
                size_t base = (size_t)r * N + c;
                if (EPI == 1) {
                    store_hilo2(Chi, Clo, base, gelu_tanh(v0), gelu_tanh(v1));
                } else {
                    if (EPI == 2) {
                        float2 rv = *(const float2*)(res + base);
                        v0 += rv.x; v1 += rv.y;
                    }
                    *(float2*)(Cf + base) = make_float2(v0, v1);
                }
            }
        }
    }
}

// ---------------- Causal attention: 64x64 tiles, register-blocked ----------
#define AT_QT(d,q) sm[(d) * 64 + (q)]
#define AT_KT(d,k) sm[4096 + (d) * 64 + (k)]
#define AT_VS(k,d) sm[8192 + (k) * 64 + (d)]
#define AT_PS(q,k) sm[12288 + (q) * 68 + (k)]
#define ATTN_SMEM ((12288 + 64 * 68) * 4)

__global__ __launch_bounds__(128)
void attn_kernel(const float* __restrict__ qkv,
                 __nv_bfloat16* __restrict__ oh, __nv_bfloat16* __restrict__ ol)
{
    extern __shared__ float sm[];
    int qt = (int)gridDim.x - 1 - (int)blockIdx.x;  // heavy blocks first
    int h = blockIdx.y, b = blockIdx.z;
    int tid = threadIdx.x;
    int tx = tid & 15, ty = tid >> 4;
    int q0 = qt * 64;

    {
        int qq = tid >> 1;
        int d0 = (tid & 1) * 32;
        const float* src = qkv + ((size_t)(b * SS + q0 + qq) * 3 + 0) * DD + h * HDIM + d0;
#pragma unroll
        for (int c = 0; c < 32; c += 4) {
            float4 v = *(const float4*)(src + c);
            AT_QT(d0 + c + 0, qq) = v.x * 0.125f;
            AT_QT(d0 + c + 1, qq) = v.y * 0.125f;
            AT_QT(d0 + c + 2, qq) = v.z * 0.125f;
            AT_QT(d0 + c + 3, qq) = v.w * 0.125f;
        }
    }

    float acc[8][4];
    float mrun[8], lrun[8];
#pragma unroll
    for (int i = 0; i < 8; i++) {
        mrun[i] = -1e30f; lrun[i] = 0.f;
#pragma unroll
        for (int d = 0; d < 4; d++) acc[i][d] = 0.f;
    }

    for (int kt = 0; kt <= qt; kt++) {
        __syncthreads();
        {
            int kk = tid >> 1;
            int d0 = (tid & 1) * 32;
            const float* ks = qkv + ((size_t)(b * SS + kt * 64 + kk) * 3 + 1) * DD + h * HDIM + d0;
            const float* vs = qkv + ((size_t)(b * SS + kt * 64 + kk) * 3 + 2) * DD + h * HDIM + d0;
#pragma unroll
            for (int c = 0; c < 32; c += 4) {
                float4 kv4 = *(const float4*)(ks + c);
                AT_KT(d0 + c + 0, kk) = kv4.x;
                AT_KT(d0 + c + 1, kk) = kv4.y;
                AT_KT(d0 + c + 2, kk) = kv4.z;
                AT_KT(d0 + c + 3, kk) = kv4.w;
                *(float4*)&AT_VS(kk, d0 + c) = *(const float4*)(vs + c);
            }
        }
        __syncthreads();

        float s[8][4];
#pragma unroll
        for (int i = 0; i < 8; i++)
#pragma unroll
            for (int j = 0; j < 4; j++) s[i][j] = 0.f;
        for (int d = 0; d < 64; d++) {
            float a[8], kb[4];
            *(float4*)&a[0] = *(const float4*)&AT_QT(d, ty * 8);
            *(float4*)&a[4] = *(const float4*)&AT_QT(d, ty * 8 + 4);
            *(float4*)&kb[0] = *(const float4*)&AT_KT(d, tx * 4);
#pragma unroll
            for (int i = 0; i < 8; i++)
#pragma unroll
                for (int j = 0; j < 4; j++) s[i][j] += a[i] * kb[j];
        }
        if (kt == qt) {
#pragma unroll
            for (int i = 0; i < 8; i++)
#pragma unroll
                for (int j = 0; j < 4; j++)
                    if (tx * 4 + j > ty * 8 + i) s[i][j] = -1e30f;
        }
#pragma unroll
        for (int i = 0; i < 8; i++) {
            float mt = fmaxf(fmaxf(s[i][0], s[i][1]), fmaxf(s[i][2], s[i][3]));
#pragma unroll
            for (int o = 1; o <= 8; o <<= 1)
                mt = fmaxf(mt, __shfl_xor_sync(0xffffffffu, mt, o));
            float nm = fmaxf(mrun[i], mt);
            float corr = __expf(mrun[i] - nm);
            float p0 = __expf(s[i][0] - nm);
            float p1 = __expf(s[i][1] - nm);
            float p2 = __expf(s[i][2] - nm);
            float p3 = __expf(s[i][3] - nm);
            *(float4*)&AT_PS(ty * 8 + i, tx * 4) = make_float4(p0, p1, p2, p3);
            float ps = p0 + p1 + p2 + p3;
#pragma unroll
            for (int o = 1; o <= 8; o <<= 1)
                ps += __shfl_xor_sync(0xffffffffu, ps, o);
            lrun[i] = lrun[i] * corr + ps;
            mrun[i] = nm;
            acc[i][0] *= corr; acc[i][1] *= corr; acc[i][2] *= corr; acc[i][3] *= corr;
        }
        __syncthreads();
        for (int k = 0; k < 64; k++) {
            float vb[4];
            *(float4*)&vb[0] = *(const float4*)&AT_VS(k, tx * 4);
#pragma unroll
            for (int i = 0; i < 8; i++) {
                float p = AT_PS(ty * 8 + i, k);
                acc[i][0] += p * vb[0];
                acc[i][1] += p * vb[1];
                acc[i][2] += p * vb[2];
                acc[i][3] += p * vb[3];
            }
        }
    }

#pragma unroll
    for (int i = 0; i < 8; i++) {
        float inv = 1.0f / lrun[i];
        int q = q0 + ty * 8 + i;
        store_hilo4(oh, ol, (size_t)(b * SS + q) * DD + h * HDIM + tx * 4,
                    make_float4(acc[i][0] * inv, acc[i][1] * inv,
                                acc[i][2] * inv, acc[i][3] * inv));
    }
}

// ---------------- launch ---------------------------------------------------
extern "C" void kernel_launch(void* const* d_in, const int* in_sizes, int n_in,
                              void* d_out, int out_size)
{
    const float* x    = (const float*)d_in[0];
    const float* pos  = (const float*)d_in[1];
    const float* ln1g = (const float*)d_in[2];
    const float* ln1b = (const float*)d_in[3];
    const float* wqkv = (const float*)d_in[4];
    const float* bqkv = (const float*)d_in[5];
    const float* wo   = (const float*)d_in[6];
    const float* bo   = (const float*)d_in[7];
    const float* ln2g = (const float*)d_in[8];
    const float* ln2b = (const float*)d_in[9];
    const float* wfc  = (const float*)d_in[10];
    const float* bfc  = (const float*)d_in[11];
    const float* wpr  = (const float*)d_in[12];
    const float* bpr  = (const float*)d_in[13];
    float* out = (float*)d_out;

    __nv_bfloat16 *p_h_hi, *p_h_lo, *p_at_hi, *p_at_lo, *p_m_hi, *p_m_lo, *p_ff_hi, *p_ff_lo;
    __nv_bfloat16 *p_wqkv_hi, *p_wqkv_lo, *p_wo_hi, *p_wo_lo, *p_wfc_hi, *p_wfc_lo, *p_wpr_hi, *p_wpr_lo;
    float *p_qkv, *p_x2;
    cudaGetSymbolAddress((void**)&p_h_hi, g_h_hi);   cudaGetSymbolAddress((void**)&p_h_lo, g_h_lo);
    cudaGetSymbolAddress((void**)&p_qkv, g_qkv);
    cudaGetSymbolAddress((void**)&p_at_hi, g_at_hi); cudaGetSymbolAddress((void**)&p_at_lo, g_at_lo);
    cudaGetSymbolAddress((void**)&p_x2, g_x2);
    cudaGetSymbolAddress((void**)&p_m_hi, g_m_hi);   cudaGetSymbolAddress((void**)&p_m_lo, g_m_lo);
    cudaGetSymbolAddress((void**)&p_ff_hi, g_ff_hi); cudaGetSymbolAddress((void**)&p_ff_lo, g_ff_lo);
    cudaGetSymbolAddress((void**)&p_wqkv_hi, g_wqkv_hi); cudaGetSymbolAddress((void**)&p_wqkv_lo, g_wqkv_lo);
    cudaGetSymbolAddress((void**)&p_wo_hi, g_wo_hi);     cudaGetSymbolAddress((void**)&p_wo_lo, g_wo_lo);
    cudaGetSymbolAddress((void**)&p_wfc_hi, g_wfc_hi);   cudaGetSymbolAddress((void**)&p_wfc_lo, g_wfc_lo);
    cudaGetSymbolAddress((void**)&p_wpr_hi, g_wpr_hi);   cudaGetSymbolAddress((void**)&p_wpr_lo, g_wpr_lo);

    cudaFuncSetAttribute(attn_kernel, cudaFuncAttributeMaxDynamicSharedMemorySize, ATTN_SMEM);
    cudaFuncSetAttribute(tc_gemm<0>, cudaFuncAttributeMaxDynamicSharedMemorySize, TCG_SMEM);
    cudaFuncSetAttribute(tc_gemm<1>, cudaFuncAttributeMaxDynamicSharedMemorySize, TCG_SMEM);
    cudaFuncSetAttribute(tc_gemm<2>, cudaFuncAttributeMaxDynamicSharedMemorySize, TCG_SMEM);

    dim3 tb(32, 8);
    // 0) weight transpose + split (deterministic, every launch)
    wsplit_t<<<dim3(3 * DD / 32, DD / 32), tb>>>(wqkv, p_wqkv_hi, p_wqkv_lo, DD, 3 * DD);
    wsplit_t<<<dim3(DD / 32, DD / 32), tb>>>(wo, p_wo_hi, p_wo_lo, DD, DD);
    wsplit_t<<<dim3(DFFN / 32, DD / 32), tb>>>(wfc, p_wfc_hi, p_wfc_lo, DD, DFFN);
    wsplit_t<<<dim3(DD / 32, DFFN / 32), tb>>>(wpr, p_wpr_hi, p_wpr_lo, DFFN, DD);

    // 1) h = LN1(x) + pos  -> bf16 hi/lo
    ln_bf<<<ROWS, 256>>>(x, ln1g, ln1b, pos, p_h_hi, p_h_lo);

    // 2) qkv = h @ w_qkv + b_qkv -> fp32 [4096 x 3072]
    tc_gemm<0><<<dim3(3 * DD / 128, ROWS / 128), 256, TCG_SMEM>>>(
        p_h_hi, p_h_lo, p_wqkv_hi, p_wqkv_lo, bqkv, nullptr,
        p_qkv, nullptr, nullptr, ROWS, 3 * DD, DD);

    // 3) causal attention -> bf16 hi/lo
    attn_kernel<<<dim3(SS / 64, HH, BB), 128, ATTN_SMEM>>>(p_qkv, p_at_hi, p_at_lo);

    // 4) x2 = x + attn @ w_o + b_o -> fp32
    tc_gemm<2><<<dim3(DD / 128, ROWS / 128), 256, TCG_SMEM>>>(
        p_at_hi, p_at_lo, p_wo_hi, p_wo_lo, bo, x,
        p_x2, nullptr, nullptr, ROWS, DD, DD);

    // 5) m = LN2(x2) -> bf16 hi/lo
    ln_bf<<<ROWS, 256>>>(p_x2, ln2g, ln2b, nullptr, p_m_hi, p_m_lo);

    // 6) ff = gelu(m @ w_fc + b_fc) -> bf16 hi/lo [4096 x 4096]
    tc_gemm<1><<<dim3(DFFN / 128, ROWS / 128), 256, TCG_SMEM>>>(
        p_m_hi, p_m_lo, p_wfc_hi, p_wfc_lo, bfc, nullptr,
        nullptr, p_ff_hi, p_ff_lo, ROWS, DFFN, DD);

    // 7) out = x2 + ff @ w_proj + b_proj -> fp32
    tc_gemm<2><<<dim3(DD / 128, ROWS / 128), 256, TCG_SMEM>>>(
        p_ff_hi, p_ff_lo, p_wpr_hi, p_wpr_lo, bpr, p_x2,
        out, nullptr, nullptr, ROWS, DD, DFFN);
}

// round 8
// speedup vs baseline: 4.2686x; 1.4283x over previous
#include <cuda_runtime.h>
#include <cuda_bf16.h>
#include <math.h>
#include <stdint.h>

// Problem constants
#define BB   2
#define SS   2048
#define DD   1024
#define HH   16
#define HDIM 64
#define DFFN 4096
#define ROWS (BB * SS)   // 4096

// -------- scratch (static device globals; no allocation) --------
__device__ __align__(16) __nv_bfloat16 g_h_hi[ROWS * DD], g_h_lo[ROWS * DD];
__device__ __align__(16) float         g_qkv[ROWS * 3 * DD];
__device__ __align__(16) __nv_bfloat16 g_at_hi[ROWS * DD], g_at_lo[ROWS * DD];
__device__ __align__(16) float         g_x2[ROWS * DD];
__device__ __align__(16) __nv_bfloat16 g_m_hi[ROWS * DD], g_m_lo[ROWS * DD];
__device__ __align__(16) __nv_bfloat16 g_ff_hi[ROWS * DFFN], g_ff_lo[ROWS * DFFN];
// transposed, split weights: Wt[n][k] = W[k][n]
__device__ __align__(16) __nv_bfloat16 g_wqkv_hi[3 * DD * DD], g_wqkv_lo[3 * DD * DD];
__device__ __align__(16) __nv_bfloat16 g_wo_hi[DD * DD],       g_wo_lo[DD * DD];
__device__ __align__(16) __nv_bfloat16 g_wfc_hi[DFFN * DD],    g_wfc_lo[DFFN * DD];
__device__ __align__(16) __nv_bfloat16 g_wpr_hi[DD * DFFN],    g_wpr_lo[DD * DFFN];

// ======================= portable PTX helpers ==============================
__device__ __forceinline__ uint32_t smem_u32(const void* p) {
    uint32_t a;
    asm("{ .reg .u64 t; cvta.to.shared.u64 t, %1; cvt.u32.u64 %0, t; }" : "=r"(a) : "l"(p));
    return a;
}

__device__ __forceinline__ void cp_async16(uint32_t saddr, const void* gaddr) {
    asm volatile("cp.async.cg.shared.global [%0], [%1], 16;" :: "r"(saddr), "l"(gaddr));
}
__device__ __forceinline__ void cp_commit() {
    asm volatile("cp.async.commit_group;" ::: "memory");
}
template <int N>
__device__ __forceinline__ void cp_wait() {
    asm volatile("cp.async.wait_group %0;" :: "n"(N) : "memory");
}

__device__ __forceinline__ void ldsm_x4(uint32_t* r, uint32_t addr) {
    asm volatile("ldmatrix.sync.aligned.m8n8.x4.shared.b16 {%0,%1,%2,%3}, [%4];"
        : "=r"(r[0]), "=r"(r[1]), "=r"(r[2]), "=r"(r[3]) : "r"(addr));
}
__device__ __forceinline__ void ldsm_x4_t(uint32_t* r, uint32_t addr) {
    asm volatile("ldmatrix.sync.aligned.m8n8.x4.trans.shared.b16 {%0,%1,%2,%3}, [%4];"
        : "=r"(r[0]), "=r"(r[1]), "=r"(r[2]), "=r"(r[3]) : "r"(addr));
}

__device__ __forceinline__ void mma16816(float* c, const uint32_t* a, const uint32_t* b) {
    asm volatile(
        "mma.sync.aligned.m16n8k16.row.col.f32.bf16.bf16.f32 "
        "{%0,%1,%2,%3}, {%4,%5,%6,%7}, {%8,%9}, {%0,%1,%2,%3};"
        : "+f"(c[0]), "+f"(c[1]), "+f"(c[2]), "+f"(c[3])
        : "r"(a[0]), "r"(a[1]), "r"(a[2]), "r"(a[3]), "r"(b[0]), "r"(b[1]));
}

// ======================= small math helpers ================================
__device__ __forceinline__ float gelu_tanh(float x) {
    float x3 = x * x * x;
    float t = tanhf(0.7978845608028654f * (x + 0.044715f * x3));
    return 0.5f * x * (1.0f + t);
}

// fast exp on the FMA pipe (no MUFU): exp(x) = 2^(x*log2e)
__device__ __forceinline__ float fexp(float x) {
    float y = fmaxf(x * 1.4426950408889634f, -126.0f);
    float z = y + 12582912.0f;                    // round-to-nearest int (magic)
    int   n = __float_as_int(z) - 0x4B400000;
    float f = y - (z - 12582912.0f);              // f in [-0.5, 0.5]
    float p = 0.0013333558146f;
    p = fmaf(p, f, 0.0096181291076f);
    p = fmaf(p, f, 0.0555041086648f);
    p = fmaf(p, f, 0.2402265069591f);
    p = fmaf(p, f, 0.6931471805599f);
    p = fmaf(p, f, 1.0f);
    return p * __int_as_float((n + 127) << 23);
}

__device__ __forceinline__ uint32_t pack_bf2(float a, float b) {
    __nv_bfloat162 t = __halves2bfloat162(__float2bfloat16(a), __float2bfloat16(b));
    return *(uint32_t*)&t;
}

__device__ __forceinline__ void store_hilo4(__nv_bfloat16* oh, __nv_bfloat16* ol,
                                            size_t idx, float4 v)
{
    __nv_bfloat16 h0 = __float2bfloat16(v.x), h1 = __float2bfloat16(v.y);
    __nv_bfloat16 h2 = __float2bfloat16(v.z), h3 = __float2bfloat16(v.w);
    float l0 = v.x - __bfloat162float(h0), l1 = v.y - __bfloat162float(h1);
    float l2 = v.z - __bfloat162float(h2), l3 = v.w - __bfloat162float(h3);
    *(__nv_bfloat162*)(oh + idx)     = __halves2bfloat162(h0, h1);
    *(__nv_bfloat162*)(oh + idx + 2) = __halves2bfloat162(h2, h3);
    *(__nv_bfloat162*)(ol + idx)     = __halves2bfloat162(__float2bfloat16(l0), __float2bfloat16(l1));
    *(__nv_bfloat162*)(ol + idx + 2) = __halves2bfloat162(__float2bfloat16(l2), __float2bfloat16(l3));
}

__device__ __forceinline__ void store_hilo2(__nv_bfloat16* oh, __nv_bfloat16* ol,
                                            size_t idx, float a, float b)
{
    __nv_bfloat16 h0 = __float2bfloat16(a), h1 = __float2bfloat16(b);
    float l0 = a - __bfloat162float(h0), l1 = b - __bfloat162float(h1);
    *(__nv_bfloat162*)(oh + idx) = __halves2bfloat162(h0, h1);
    *(__nv_bfloat162*)(ol + idx) = __halves2bfloat162(__float2bfloat16(l0), __float2bfloat16(l1));
}

// ============ weight transpose + bf16 split: Wt[n][k] = W[k][n] ============
__global__ void wsplit_t(const float* __restrict__ W, __nv_bfloat16* __restrict__ Th,
                         __nv_bfloat16* __restrict__ Tl, int K, int N)
{
    __shared__ float t[32][33];
    int bx = blockIdx.x, by = blockIdx.y;
    int x = threadIdx.x, y = threadIdx.y;
#pragma unroll
    for (int i = 0; i < 32; i += 8)
        t[y + i][x] = W[(size_t)(by * 32 + y + i) * N + bx * 32 + x];
    __syncthreads();
#pragma unroll
    for (int i = 0; i < 32; i += 8) {
        float v = t[x][y + i];
        __nv_bfloat16 h = __float2bfloat16(v);
        float lo = v - __bfloat162float(h);
        size_t o = (size_t)(bx * 32 + y + i) * K + by * 32 + x;
        Th[o] = h;
        Tl[o] = __float2bfloat16(lo);
    }
}

// ---------------- LayerNorm (+ optional pos add) -> bf16 hi/lo -------------
__global__ void ln_bf(const float* __restrict__ x,
                      const float* __restrict__ gam,
                      const float* __restrict__ bet,
                      const float* __restrict__ pos,
                      __nv_bfloat16* __restrict__ oh,
                      __nv_bfloat16* __restrict__ ol)
{
    int row = blockIdx.x;
    int tid = threadIdx.x;
    const float4* xr = (const float4*)(x + (size_t)row * DD);
    float4 v = xr[tid];
    float s  = v.x + v.y + v.z + v.w;
    float ss = v.x * v.x + v.y * v.y + v.z * v.z + v.w * v.w;
#pragma unroll
    for (int o = 16; o > 0; o >>= 1) {
        s  += __shfl_xor_sync(0xffffffffu, s,  o);
        ss += __shfl_xor_sync(0xffffffffu, ss, o);
    }
    __shared__ float sb[8], sb2[8], stats[2];
    int wid = tid >> 5, lane = tid & 31;
    if (lane == 0) { sb[wid] = s; sb2[wid] = ss; }
    __syncthreads();
    if (tid == 0) {
        float ts = 0.f, tss = 0.f;
#pragma unroll
        for (int i = 0; i < 8; i++) { ts += sb[i]; tss += sb2[i]; }
        float mu  = ts  * (1.0f / DD);
        float var = tss * (1.0f / DD) - mu * mu;
        stats[0] = mu;
        stats[1] = rsqrtf(var + 1e-5f);
    }
    __syncthreads();
    float mu = stats[0], rs = stats[1];
    int c = tid * 4;
    float4 gg = *(const float4*)(gam + c);
    float4 bb = *(const float4*)(bet + c);
    float4 o4;
    o4.x = (v.x - mu) * rs * gg.x + bb.x;
    o4.y = (v.y - mu) * rs * gg.y + bb.y;
    o4.z = (v.z - mu) * rs * gg.z + bb.z;
    o4.w = (v.w - mu) * rs * gg.w + bb.w;
    if (pos) {
        int srow = row % SS;
        float4 p = *(const float4*)(pos + (size_t)srow * DD + c);
        o4.x += p.x; o4.y += p.y; o4.z += p.z; o4.w += p.w;
    }
    store_hilo4(oh, ol, (size_t)row * DD + c, o4);
}

// =================== mma.sync bf16-split GEMM (3-stage pipeline) ===========
#define OFF_AH 0
#define OFF_AL 8192
#define OFF_BH 16384
#define OFF_BL 24576
#define STAGE  32768
#define NSTAGE 3
#define TCG_SMEM (NSTAGE * STAGE)

__device__ __forceinline__ uint32_t swz32(int row, int chunk) {
    return (uint32_t)(row * 64 + (((chunk ^ (row >> 1)) & 3) << 4));
}

__device__ __forceinline__ void cp_stage(uint32_t sbase,
                                         const __nv_bfloat16* __restrict__ Ahi,
                                         const __nv_bfloat16* __restrict__ Alo,
                                         const __nv_bfloat16* __restrict__ Bhi,
                                         const __nv_bfloat16* __restrict__ Blo,
                                         int am0, int bn0, int k0, int ldk, int tid)
{
#pragma unroll
    for (int j = 0; j < 2; j++) {
        int v = tid + (j << 8);
        int r = v >> 2, c = v & 3;
        uint32_t so = swz32(r, c);
        size_t goA = (size_t)(am0 + r) * ldk + k0 + c * 8;
        size_t goB = (size_t)(bn0 + r) * ldk + k0 + c * 8;
        cp_async16(sbase + OFF_AH + so, Ahi + goA);
        cp_async16(sbase + OFF_AL + so, Alo + goA);
        cp_async16(sbase + OFF_BH + so, Bhi + goB);
        cp_async16(sbase + OFF_BL + so, Blo + goB);
    }
}

template <int EPI>
__global__ __launch_bounds__(256, 2)
void tc_gemm(const __nv_bfloat16* __restrict__ Ahi, const __nv_bfloat16* __restrict__ Alo,
             const __nv_bfloat16* __restrict__ Bhi, const __nv_bfloat16* __restrict__ Blo,
             const float* __restrict__ bias, const float* __restrict__ res,
             float* __restrict__ Cf, __nv_bfloat16* __restrict__ Chi,
             __nv_bfloat16* __restrict__ Clo, int M, int N, int K)
{
    extern __shared__ __align__(128) char smc[];
    uint32_t sb = smem_u32(smc);
    int tid = threadIdx.x, wid = tid >> 5, lane = tid & 31;
    int warp_m = wid >> 1, warp_n = wid & 1;
    int bn = blockIdx.x, bm = blockIdx.y;
    int am0 = bm * 128, bn0 = bn * 128;

    float acc[2][8][4];
#pragma unroll
    for (int mi = 0; mi < 2; mi++)
#pragma unroll
        for (int ni = 0; ni < 8; ni++)
#pragma unroll
            for (int q = 0; q < 4; q++) acc[mi][ni][q] = 0.f;

    int lrA = (lane & 7) + ((lane >> 3) & 1) * 8;
    uint32_t cAoff = (uint32_t)((lane >> 4) << 4);
    uint32_t aB[2], aX[2];
#pragma unroll
    for (int mi = 0; mi < 2; mi++) {
        int row = warp_m * 32 + mi * 16 + lrA;
        aB[mi] = (uint32_t)(row * 64);
        aX[mi] = cAoff ^ (uint32_t)((((row >> 1) & 3)) << 4);
    }
    int lrB = (lane & 7) + ((lane >> 4) & 1) * 8;
    uint32_t cBoff = (uint32_t)(((lane >> 3) & 1) << 4);
    uint32_t bB[4], bX[4];
#pragma unroll
    for (int p = 0; p < 4; p++) {
        int row = warp_n * 64 + p * 16 + lrB;
        bB[p] = (uint32_t)(row * 64);
        bX[p] = cBoff ^ (uint32_t)((((row >> 1) & 3)) << 4);
    }

    int nchunk = K >> 5;
    cp_stage(sb + 0 * STAGE, Ahi, Alo, Bhi, Blo, am0, bn0, 0, K, tid);
    cp_commit();
    cp_stage(sb + 1 * STAGE, Ahi, Alo, Bhi, Blo, am0, bn0, 32, K, tid);
    cp_commit();

    int slot = 0;
    for (int ch = 0; ch < nchunk; ch++) {
        uint32_t st = sb + (uint32_t)slot * STAGE;
        cp_wait<1>();
        __syncthreads();
        int nslot = slot + 2; if (nslot >= NSTAGE) nslot -= NSTAGE;
        if (ch + 2 < nchunk)
            cp_stage(sb + (uint32_t)nslot * STAGE, Ahi, Alo, Bhi, Blo,
                     am0, bn0, (ch + 2) << 5, K, tid);
        cp_commit();

#pragma unroll
        for (int ks = 0; ks < 2; ks++) {
            uint32_t kx = (uint32_t)(ks << 5);
            uint32_t ah[2][4], bh[8][2];
#pragma unroll
            for (int mi = 0; mi < 2; mi++)
                ldsm_x4(ah[mi], st + OFF_AH + aB[mi] + (kx ^ aX[mi]));
#pragma unroll
            for (int p = 0; p < 4; p++) {
                uint32_t r4[4];
                ldsm_x4(r4, st + OFF_BH + bB[p] + (kx ^ bX[p]));
                bh[2 * p][0] = r4[0]; bh[2 * p][1] = r4[1];
                bh[2 * p + 1][0] = r4[2]; bh[2 * p + 1][1] = r4[3];
            }
#pragma unroll
            for (int mi = 0; mi < 2; mi++)
#pragma unroll
                for (int ni = 0; ni < 8; ni++)
                    mma16816(acc[mi][ni], ah[mi], bh[ni]);
            {
                uint32_t al[2][4];
#pragma unroll
                for (int mi = 0; mi < 2; mi++)
                    ldsm_x4(al[mi], st + OFF_AL + aB[mi] + (kx ^ aX[mi]));
#pragma unroll
                for (int mi = 0; mi < 2; mi++)
#pragma unroll
                    for (int ni = 0; ni < 8; ni++)
                        mma16816(acc[mi][ni], al[mi], bh[ni]);
            }
            {
                uint32_t bl[8][2];
#pragma unroll
                for (int p = 0; p < 4; p++) {
                    uint32_t r4[4];
                    ldsm_x4(r4, st + OFF_BL + bB[p] + (kx ^ bX[p]));
                    bl[2 * p][0] = r4[0]; bl[2 * p][1] = r4[1];
                    bl[2 * p + 1][0] = r4[2]; bl[2 * p + 1][1] = r4[3];
                }
#pragma unroll
                for (int mi = 0; mi < 2; mi++)
#pragma unroll
                    for (int ni = 0; ni < 8; ni++)
                        mma16816(acc[mi][ni], ah[mi], bl[ni]);
            }
        }
        slot++; if (slot >= NSTAGE) slot = 0;
    }

    int g = lane >> 2, tig = lane & 3;
#pragma unroll
    for (int mi = 0; mi < 2; mi++) {
#pragma unroll
        for (int half = 0; half < 2; half++) {
            int r = bm * 128 + warp_m * 32 + mi * 16 + g + half * 8;
#pragma unroll
            for (int ni = 0; ni < 8; ni++) {
                int c = bn * 128 + warp_n * 64 + ni * 8 + tig * 2;
                float v0 = acc[mi][ni][half * 2 + 0];
                float v1 = acc[mi][ni][half * 2 + 1];
                float2 bv = *(const float2*)(bias + c);
                v0 += bv.x; v1 += bv.y;
                size_t base = (size_t)r * N + c;
                if (EPI == 1) {
                    store_hilo2(Chi, Clo, base, gelu_tanh(v0), gelu_tanh(v1));
                } else {
                    if (EPI == 2) {
                        float2 rv = *(const float2*)(res + base);
                        v0 += rv.x; v1 += rv.y;
                    }
                    *(float2*)(Cf + base) = make_float2(v0, v1);
                }
            }
        }
    }
}

// ============ Tensor-core causal flash attention ===========================
// grid (S/64, H, B), 128 threads (4 warps; warp owns 16 q-rows).
// Q/K/V staged in smem as bf16 hi/lo, 128B rows, SW128-style swizzle.
// S = QK^T: 3-pass split. P·V: 3-pass (Ph*Vh + Pl*Vh + Ph*Vl), P split in regs.
#define AQH 0
#define AQL 8192
#define AKH 16384
#define AKL 24576
#define AVH 32768
#define AVL 40960

// 128B rows, 8x16B chunks, chunk ^= row&7  -> conflict-free ldmatrix
__device__ __forceinline__ void attn_load_tile(char* dstH, char* dstL,
                                               const float* __restrict__ src,
                                               int tid, float scale)
{
    int row = tid >> 1;
    int d0 = (tid & 1) * 32;
    const float* p = src + (size_t)row * (3 * DD) + d0;
#pragma unroll
    for (int c = 0; c < 4; c++) {
        float4 v0 = *(const float4*)(p + c * 8);
        float4 v1 = *(const float4*)(p + c * 8 + 4);
        float vals[8] = {v0.x, v0.y, v0.z, v0.w, v1.x, v1.y, v1.z, v1.w};
        uint32_t hi[4], lo[4];
#pragma unroll
        for (int i = 0; i < 4; i++) {
            float a = vals[2 * i] * scale, b = vals[2 * i + 1] * scale;
            __nv_bfloat16 ah = __float2bfloat16(a), bh = __float2bfloat16(b);
            float al = a - __bfloat162float(ah), bl = b - __bfloat162float(bh);
            hi[i] = pack_bf2(__bfloat162float(ah), __bfloat162float(bh));
            // pack exact hi bits (avoid double-round): rebuild from halves
            __nv_bfloat162 th = __halves2bfloat162(ah, bh);
            hi[i] = *(uint32_t*)&th;
            __nv_bfloat162 tl = __halves2bfloat162(__float2bfloat16(al), __float2bfloat16(bl));
            lo[i] = *(uint32_t*)&tl;
        }
        uint32_t cb = (uint32_t)((d0 + c * 8) * 2);
        uint32_t ad = (uint32_t)(row * 128) + (cb ^ (((uint32_t)row & 7) << 4));
        uint4 hv = make_uint4(hi[0], hi[1], hi[2], hi[3]);
        uint4 lv = make_uint4(lo[0], lo[1], lo[2], lo[3]);
        *(uint4*)(dstH + ad) = hv;
        *(uint4*)(dstL + ad) = lv;
    }
}

__global__ __launch_bounds__(128)
void attn_kernel(const float* __restrict__ qkv,
                 __nv_bfloat16* __restrict__ oh, __nv_bfloat16* __restrict__ ol)
{
    __shared__ __align__(16) char sma[49152];
    uint32_t sb = smem_u32(sma);
    int qt = (int)gridDim.x - 1 - (int)blockIdx.x;   // heavy blocks first
    int h = blockIdx.y, b = blockIdx.z;
    int tid = threadIdx.x, warp = tid >> 5, lane = tid & 31;
    int q0 = qt * 64;
    int g = lane >> 2, tig = lane & 3;

    // load Q (scaled by 1/8) once
    attn_load_tile(sma + AQH, sma + AQL,
                   qkv + ((size_t)(b * SS + q0) * 3 + 0) * DD + h * HDIM, tid, 0.125f);

    // ldmatrix address precompute (byte-chunk XOR row&7 swizzle, 128B rows)
    int lrA = (lane & 7) + ((lane >> 3) & 1) * 8;
    uint32_t cA = (uint32_t)((lane >> 4) << 4);
    int rowA = warp * 16 + lrA;
    uint32_t aBase = (uint32_t)(rowA * 128);
    uint32_t aMask = (uint32_t)((rowA & 7) << 4);

    int lrB = (lane & 7) + ((lane >> 4) & 1) * 8;
    uint32_t cB = (uint32_t)(((lane >> 3) & 1) << 4);

    // V (trans): row within 16-key group, chunk per d-pair
    int lrV = (lane & 7) + ((lane >> 3) & 1) * 8;
    uint32_t cV = (uint32_t)(((lane >> 4) & 1) << 4);

    float oacc[8][4];
    float mA = -1e30f, mB = -1e30f, lA = 0.f, lB = 0.f;
#pragma unroll
    for (int t = 0; t < 8; t++)
#pragma unroll
        for (int q = 0; q < 4; q++) oacc[t][q] = 0.f;

    for (int kt = 0; kt <= qt; kt++) {
        __syncthreads();   // prior PV ldsm done; K/V slots free (also guards Q 1st iter)
        attn_load_tile(sma + AKH, sma + AKL,
                       qkv + ((size_t)(b * SS + kt * 64) * 3 + 1) * DD + h * HDIM, tid, 1.f);
        attn_load_tile(sma + AVH, sma + AVL,
                       qkv + ((size_t)(b * SS + kt * 64) * 3 + 2) * DD + h * HDIM, tid, 1.f);
        __syncthreads();

        // ---- S = Q K^T (3-pass split), 16x64 stripe per warp ----
        float sacc[8][4];
#pragma unroll
        for (int t = 0; t < 8; t++)
#pragma unroll
            for (int q = 0; q < 4; q++) sacc[t][q] = 0.f;

#pragma unroll
        for (int ks = 0; ks < 4; ks++) {
            uint32_t kx = (uint32_t)(ks * 32);
            uint32_t qh[4], ql[4], kh[8][2];
            ldsm_x4(qh, sb + AQH + aBase + ((kx + cA) ^ aMask));
            ldsm_x4(ql, sb + AQL + aBase + ((kx + cA) ^ aMask));
#pragma unroll
            for (int p = 0; p < 4; p++) {
                int rowB = p * 16 + lrB;
                uint32_t r4[4];
                ldsm_x4(r4, sb + AKH + (uint32_t)(rowB * 128) +
                            ((kx + cB) ^ (uint32_t)((rowB & 7) << 4)));
                kh[2 * p][0] = r4[0]; kh[2 * p][1] = r4[1];
                kh[2 * p + 1][0] = r4[2]; kh[2 * p + 1][1] = r4[3];
            }
#pragma unroll
            for (int t = 0; t < 8; t++) mma16816(sacc[t], qh, kh[t]);
#pragma unroll
            for (int t = 0; t < 8; t++) mma16816(sacc[t], ql, kh[t]);
            {
                uint32_t kl[8][2];
#pragma unroll
                for (int p = 0; p < 4; p++) {
                    int rowB = p * 16 + lrB;
                    uint32_t r4[4];
                    ldsm_x4(r4, sb + AKL + (uint32_t)(rowB * 128) +
                                ((kx + cB) ^ (uint32_t)((rowB & 7) << 4)));
                    kl[2 * p][0] = r4[0]; kl[2 * p][1] = r4[1];
                    kl[2 * p + 1][0] = r4[2]; kl[2 * p + 1][1] = r4[3];
                }
#pragma unroll
                for (int t = 0; t < 8; t++) mma16816(sacc[t], qh, kl[t]);
            }
        }

        // causal mask on diagonal tile
        if (kt == qt) {
            int qlocA = warp * 16 + g, qlocB = qlocA + 8;
#pragma unroll
            for (int t = 0; t < 8; t++) {
                int k0c = t * 8 + tig * 2;
                if (k0c > qlocA)     sacc[t][0] = -1e30f;
                if (k0c + 1 > qlocA) sacc[t][1] = -1e30f;
                if (k0c > qlocB)     sacc[t][2] = -1e30f;
                if (k0c + 1 > qlocB) sacc[t][3] = -1e30f;
            }
        }

        // ---- online softmax ----
        float maA = -1e30f, maB = -1e30f;
#pragma unroll
        for (int t = 0; t < 8; t++) {
            maA = fmaxf(maA, fmaxf(sacc[t][0], sacc[t][1]));
            maB = fmaxf(maB, fmaxf(sacc[t][2], sacc[t][3]));
        }
        maA = fmaxf(maA, __shfl_xor_sync(0xffffffffu, maA, 1));
        maA = fmaxf(maA, __shfl_xor_sync(0xffffffffu, maA, 2));
        maB = fmaxf(maB, __shfl_xor_sync(0xffffffffu, maB, 1));
        maB = fmaxf(maB, __shfl_xor_sync(0xffffffffu, maB, 2));
        float nmA = fmaxf(mA, maA), nmB = fmaxf(mB, maB);
        float corrA = fexp(mA - nmA), corrB = fexp(mB - nmB);
        mA = nmA; mB = nmB;
        float sumA = 0.f, sumB = 0.f;
#pragma unroll
        for (int t = 0; t < 8; t++) {
            sacc[t][0] = fexp(sacc[t][0] - nmA);
            sacc[t][1] = fexp(sacc[t][1] - nmA);
            sacc[t][2] = fexp(sacc[t][2] - nmB);
            sacc[t][3] = fexp(sacc[t][3] - nmB);
            sumA += sacc[t][0] + sacc[t][1];
            sumB += sacc[t][2] + sacc[t][3];
        }
        sumA += __shfl_xor_sync(0xffffffffu, sumA, 1);
        sumA += __shfl_xor_sync(0xffffffffu, sumA, 2);
        sumB += __shfl_xor_sync(0xffffffffu, sumB, 1);
        sumB += __shfl_xor_sync(0xffffffffu, sumB, 2);
        lA = lA * corrA + sumA;
        lB = lB * corrB + sumB;
#pragma unroll
        for (int t = 0; t < 8; t++) {
            oacc[t][0] *= corrA; oacc[t][1] *= corrA;
            oacc[t][2] *= corrB; oacc[t][3] *= corrB;
        }

        // ---- pack P into A-fragments (hi + lo) ----
        uint32_t ph[4][4], pl[4][4];
#pragma unroll
        for (int p = 0; p < 4; p++) {
#pragma unroll
            for (int q = 0; q < 4; q++) {
                int t = 2 * p + (q >> 1);
                float a = sacc[t][(q & 1) * 2 + 0];
                float bv = sacc[t][(q & 1) * 2 + 1];
                __nv_bfloat16 ah = __float2bfloat16(a), bh2 = __float2bfloat16(bv);
                __nv_bfloat162 th = __halves2bfloat162(ah, bh2);
                ph[p][q] = *(uint32_t*)&th;
                __nv_bfloat162 tl = __halves2bfloat162(
                    __float2bfloat16(a - __bfloat162float(ah)),
                    __float2bfloat16(bv - __bfloat162float(bh2)));
                pl[p][q] = *(uint32_t*)&tl;
            }
        }
        // note: A-frag order is a0=(rows0-7,k0-7) a1=(rows8-15,k0-7) a2=(rows0-7,k8-15) a3=(rows8-15,k8-15)
        // our q index: q=0 -> tile 2p c0c1 (rows0-7 k0-7) OK; q=1 -> tile 2p c2c3 (rows8-15) OK;
        // q=2 -> tile 2p+1 c0c1 (k8-15 rows0-7) OK; q=3 -> tile 2p+1 c2c3 OK.

        // ---- O += P V (3-pass) ----
#pragma unroll
        for (int ks = 0; ks < 4; ks++) {
            int rowV = ks * 16 + lrV;
            uint32_t vMask = (uint32_t)((rowV & 7) << 4);
            uint32_t vbh[8][2], vbl[8][2];
#pragma unroll
            for (int j = 0; j < 4; j++) {
                uint32_t cb = (uint32_t)(j * 32) + cV;
                uint32_t r4[4];
                ldsm_x4_t(r4, sb + AVH + (uint32_t)(rowV * 128) + (cb ^ vMask));
                vbh[2 * j][0] = r4[0]; vbh[2 * j][1] = r4[1];
                vbh[2 * j + 1][0] = r4[2]; vbh[2 * j + 1][1] = r4[3];
            }
#pragma unroll
            for (int j = 0; j < 4; j++) {
                uint32_t cb = (uint32_t)(j * 32) + cV;
                uint32_t r4[4];
                ldsm_x4_t(r4, sb + AVL + (uint32_t)(rowV * 128) + (cb ^ vMask));
                vbl[2 * j][0] = r4[0]; vbl[2 * j][1] = r4[1];
                vbl[2 * j + 1][0] = r4[2]; vbl[2 * j + 1][1] = r4[3];
            }
#pragma unroll
            for (int t = 0; t < 8; t++) mma16816(oacc[t], ph[ks], vbh[t]);
#pragma unroll
            for (int t = 0; t < 8; t++) mma16816(oacc[t], pl[ks], vbh[t]);
#pragma unroll
            for (int t = 0; t < 8; t++) mma16816(oacc[t], ph[ks], vbl[t]);
        }
    }

    // ---- normalize + write ----
    float invA = 1.0f / lA, invB = 1.0f / lB;
    int rowAg = b * SS + q0 + warp * 16 + g;
    int rowBg = rowAg + 8;
#pragma unroll
    for (int t = 0; t < 8; t++) {
        int d0 = t * 8 + tig * 2;
        store_hilo2(oh, ol, (size_t)rowAg * DD + h * HDIM + d0,
                    oacc[t][0] * invA, oacc[t][1] * invA);
        store_hilo2(oh, ol, (size_t)rowBg * DD + h * HDIM + d0,
                    oacc[t][2] * invB, oacc[t][3] * invB);
    }
}

// ---------------- launch ---------------------------------------------------
extern "C" void kernel_launch(void* const* d_in, const int* in_sizes, int n_in,
                              void* d_out, int out_size)
{
    const float* x    = (const float*)d_in[0];
    const float* pos  = (const float*)d_in[1];
    const float* ln1g = (const float*)d_in[2];
    const float* ln1b = (const float*)d_in[3];
    const float* wqkv = (const float*)d_in[4];
    const float* bqkv = (const float*)d_in[5];
    const float* wo   = (const float*)d_in[6];
    const float* bo   = (const float*)d_in[7];
    const float* ln2g = (const float*)d_in[8];
    const float* ln2b = (const float*)d_in[9];
    const float* wfc  = (const float*)d_in[10];
    const float* bfc  = (const float*)d_in[11];
    const float* wpr  = (const float*)d_in[12];
    const float* bpr  = (const float*)d_in[13];
    float* out = (float*)d_out;

    __nv_bfloat16 *p_h_hi, *p_h_lo, *p_at_hi, *p_at_lo, *p_m_hi, *p_m_lo, *p_ff_hi, *p_ff_lo;
    __nv_bfloat16 *p_wqkv_hi, *p_wqkv_lo, *p_wo_hi, *p_wo_lo, *p_wfc_hi, *p_wfc_lo, *p_wpr_hi, *p_wpr_lo;
    float *p_qkv, *p_x2;
    cudaGetSymbolAddress((void**)&p_h_hi, g_h_hi);   cudaGetSymbolAddress((void**)&p_h_lo, g_h_lo);
    cudaGetSymbolAddress((void**)&p_qkv, g_qkv);
    cudaGetSymbolAddress((void**)&p_at_hi, g_at_hi); cudaGetSymbolAddress((void**)&p_at_lo, g_at_lo);
    cudaGetSymbolAddress((void**)&p_x2, g_x2);
    cudaGetSymbolAddress((void**)&p_m_hi, g_m_hi);   cudaGetSymbolAddress((void**)&p_m_lo, g_m_lo);
    cudaGetSymbolAddress((void**)&p_ff_hi, g_ff_hi); cudaGetSymbolAddress((void**)&p_ff_lo, g_ff_lo);
    cudaGetSymbolAddress((void**)&p_wqkv_hi, g_wqkv_hi); cudaGetSymbolAddress((void**)&p_wqkv_lo, g_wqkv_lo);
    cudaGetSymbolAddress((void**)&p_wo_hi, g_wo_hi);     cudaGetSymbolAddress((void**)&p_wo_lo, g_wo_lo);
    cudaGetSymbolAddress((void**)&p_wfc_hi, g_wfc_hi);   cudaGetSymbolAddress((void**)&p_wfc_lo, g_wfc_lo);
    cudaGetSymbolAddress((void**)&p_wpr_hi, g_wpr_hi);   cudaGetSymbolAddress((void**)&p_wpr_lo, g_wpr_lo);

    cudaFuncSetAttribute(tc_gemm<0>, cudaFuncAttributeMaxDynamicSharedMemorySize, TCG_SMEM);
    cudaFuncSetAttribute(tc_gemm<1>, cudaFuncAttributeMaxDynamicSharedMemorySize, TCG_SMEM);
    cudaFuncSetAttribute(tc_gemm<2>, cudaFuncAttributeMaxDynamicSharedMemorySize, TCG_SMEM);

    dim3 tb(32, 8);
    wsplit_t<<<dim3(3 * DD / 32, DD / 32), tb>>>(wqkv, p_wqkv_hi, p_wqkv_lo, DD, 3 * DD);
    wsplit_t<<<dim3(DD / 32, DD / 32), tb>>>(wo, p_wo_hi, p_wo_lo, DD, DD);
    wsplit_t<<<dim3(DFFN / 32, DD / 32), tb>>>(wfc, p_wfc_hi, p_wfc_lo, DD, DFFN);
    wsplit_t<<<dim3(DD / 32, DFFN / 32), tb>>>(wpr, p_wpr_hi, p_wpr_lo, DFFN, DD);

    ln_bf<<<ROWS, 256>>>(x, ln1g, ln1b, pos, p_h_hi, p_h_lo);

    tc_gemm<0><<<dim3(3 * DD / 128, ROWS / 128), 256, TCG_SMEM>>>(
        p_h_hi, p_h_lo, p_wqkv_hi, p_wqkv_lo, bqkv, nullptr,
        p_qkv, nullptr, nullptr, ROWS, 3 * DD, DD);

    attn_kernel<<<dim3(SS / 64, HH, BB), 128>>>(p_qkv, p_at_hi, p_at_lo);

    tc_gemm<2><<<dim3(DD / 128, ROWS / 128), 256, TCG_SMEM>>>(
        p_at_hi, p_at_lo, p_wo_hi, p_wo_lo, bo, x,
        p_x2, nullptr, nullptr, ROWS, DD, DD);

    ln_bf<<<ROWS, 256>>>(p_x2, ln2g, ln2b, nullptr, p_m_hi, p_m_lo);

    tc_gemm<1><<<dim3(DFFN / 128, ROWS / 128), 256, TCG_SMEM>>>(
        p_m_hi, p_m_lo, p_wfc_hi, p_wfc_lo, bfc, nullptr,
        nullptr, p_ff_hi, p_ff_lo, ROWS, DFFN, DD);

    tc_gemm<2><<<dim3(DD / 128, ROWS / 128), 256, TCG_SMEM>>>(
        p_ff_hi, p_ff_lo, p_wpr_hi, p_wpr_lo, bpr, p_x2,
        out, nullptr, nullptr, ROWS, DD, DFFN);
}

// round 9
// speedup vs baseline: 4.7490x; 1.1125x over previous
#include <cuda_runtime.h>
#include <cuda_bf16.h>
#include <math.h>
#include <stdint.h>

// Problem constants
#define BB   2
#define SS   2048
#define DD   1024
#define HH   16
#define HDIM 64
#define DFFN 4096
#define ROWS (BB * SS)   // 4096

// -------- scratch (static device globals; no allocation) --------
__device__ __align__(16) __nv_bfloat16 g_h_hi[ROWS * DD], g_h_lo[ROWS * DD];
__device__ __align__(16) __nv_bfloat16 g_qkvh[ROWS * 3 * DD], g_qkvl[ROWS * 3 * DD];
__device__ __align__(16) __nv_bfloat16 g_at_hi[ROWS * DD], g_at_lo[ROWS * DD];
__device__ __align__(16) float         g_x2[ROWS * DD];
__device__ __align__(16) __nv_bfloat16 g_m_hi[ROWS * DD], g_m_lo[ROWS * DD];
__device__ __align__(16) __nv_bfloat16 g_ff_hi[ROWS * DFFN], g_ff_lo[ROWS * DFFN];
// transposed, split weights: Wt[n][k] = W[k][n]
__device__ __align__(16) __nv_bfloat16 g_wqkv_hi[3 * DD * DD], g_wqkv_lo[3 * DD * DD];
__device__ __align__(16) __nv_bfloat16 g_wo_hi[DD * DD],       g_wo_lo[DD * DD];
__device__ __align__(16) __nv_bfloat16 g_wfc_hi[DFFN * DD],    g_wfc_lo[DFFN * DD];
__device__ __align__(16) __nv_bfloat16 g_wpr_hi[DD * DFFN],    g_wpr_lo[DD * DFFN];

// ======================= portable PTX helpers ==============================
__device__ __forceinline__ uint32_t smem_u32(const void* p) {
    uint32_t a;
    asm("{ .reg .u64 t; cvta.to.shared.u64 t, %1; cvt.u32.u64 %0, t; }" : "=r"(a) : "l"(p));
    return a;
}

__device__ __forceinline__ void cp_async16(uint32_t saddr, const void* gaddr) {
    asm volatile("cp.async.cg.shared.global [%0], [%1], 16;" :: "r"(saddr), "l"(gaddr));
}
__device__ __forceinline__ void cp_commit() {
    asm volatile("cp.async.commit_group;" ::: "memory");
}
template <int N>
__device__ __forceinline__ void cp_wait() {
    asm volatile("cp.async.wait_group %0;" :: "n"(N) : "memory");
}

__device__ __forceinline__ void ldsm_x4(uint32_t* r, uint32_t addr) {
    asm volatile("ldmatrix.sync.aligned.m8n8.x4.shared.b16 {%0,%1,%2,%3}, [%4];"
        : "=r"(r[0]), "=r"(r[1]), "=r"(r[2]), "=r"(r[3]) : "r"(addr));
}
__device__ __forceinline__ void ldsm_x4_t(uint32_t* r, uint32_t addr) {
    asm volatile("ldmatrix.sync.aligned.m8n8.x4.trans.shared.b16 {%0,%1,%2,%3}, [%4];"
        : "=r"(r[0]), "=r"(r[1]), "=r"(r[2]), "=r"(r[3]) : "r"(addr));
}

__device__ __forceinline__ void mma16816(float* c, const uint32_t* a, const uint32_t* b) {
    asm volatile(
        "mma.sync.aligned.m16n8k16.row.col.f32.bf16.bf16.f32 "
        "{%0,%1,%2,%3}, {%4,%5,%6,%7}, {%8,%9}, {%0,%1,%2,%3};"
        : "+f"(c[0]), "+f"(c[1]), "+f"(c[2]), "+f"(c[3])
        : "r"(a[0]), "r"(a[1]), "r"(a[2]), "r"(a[3]), "r"(b[0]), "r"(b[1]));
}

// ======================= small math helpers ================================
__device__ __forceinline__ float gelu_tanh(float x) {
    float x3 = x * x * x;
    float t = tanhf(0.7978845608028654f * (x + 0.044715f * x3));
    return 0.5f * x * (1.0f + t);
}

// fast exp on the FMA pipe (no MUFU): exp(x) = 2^(x*log2e)
__device__ __forceinline__ float fexp(float x) {
    float y = fmaxf(x * 1.4426950408889634f, -126.0f);
    float z = y + 12582912.0f;                    // round-to-nearest int (magic)
    int   n = __float_as_int(z) - 0x4B400000;
    float f = y - (z - 12582912.0f);              // f in [-0.5, 0.5]
    float p = 0.0013333558146f;
    p = fmaf(p, f, 0.0096181291076f);
    p = fmaf(p, f, 0.0555041086648f);
    p = fmaf(p, f, 0.2402265069591f);
    p = fmaf(p, f, 0.6931471805599f);
    p = fmaf(p, f, 1.0f);
    return p * __int_as_float((n + 127) << 23);
}

__device__ __forceinline__ void store_hilo4(__nv_bfloat16* oh, __nv_bfloat16* ol,
                                            size_t idx, float4 v)
{
    __nv_bfloat16 h0 = __float2bfloat16(v.x), h1 = __float2bfloat16(v.y);
    __nv_bfloat16 h2 = __float2bfloat16(v.z), h3 = __float2bfloat16(v.w);
    float l0 = v.x - __bfloat162float(h0), l1 = v.y - __bfloat162float(h1);
    float l2 = v.z - __bfloat162float(h2), l3 = v.w - __bfloat162float(h3);
    *(__nv_bfloat162*)(oh + idx)     = __halves2bfloat162(h0, h1);
    *(__nv_bfloat162*)(oh + idx + 2) = __halves2bfloat162(h2, h3);
    *(__nv_bfloat162*)(ol + idx)     = __halves2bfloat162(__float2bfloat16(l0), __float2bfloat16(l1));
    *(__nv_bfloat162*)(ol + idx + 2) = __halves2bfloat162(__float2bfloat16(l2), __float2bfloat16(l3));
}

__device__ __forceinline__ void store_hilo2(__nv_bfloat16* oh, __nv_bfloat16* ol,
                                            size_t idx, float a, float b)
{
    __nv_bfloat16 h0 = __float2bfloat16(a), h1 = __float2bfloat16(b);
    float l0 = a - __bfloat162float(h0), l1 = b - __bfloat162float(h1);
    *(__nv_bfloat162*)(oh + idx) = __halves2bfloat162(h0, h1);
    *(__nv_bfloat162*)(ol + idx) = __halves2bfloat162(__float2bfloat16(l0), __float2bfloat16(l1));
}

// ============ weight transpose + bf16 split: Wt[n][k] = W[k][n] ============
__global__ void wsplit_t(const float* __restrict__ W, __nv_bfloat16* __restrict__ Th,
                         __nv_bfloat16* __restrict__ Tl, int K, int N)
{
    __shared__ float t[32][33];
    int bx = blockIdx.x, by = blockIdx.y;
    int x = threadIdx.x, y = threadIdx.y;
#pragma unroll
    for (int i = 0; i < 32; i += 8)
        t[y + i][x] = W[(size_t)(by * 32 + y + i) * N + bx * 32 + x];
    __syncthreads();
#pragma unroll
    for (int i = 0; i < 32; i += 8) {
        float v = t[x][y + i];
        __nv_bfloat16 h = __float2bfloat16(v);
        float lo = v - __bfloat162float(h);
        size_t o = (size_t)(bx * 32 + y + i) * K + by * 32 + x;
        Th[o] = h;
        Tl[o] = __float2bfloat16(lo);
    }
}

// ---------------- LayerNorm (+ optional pos add) -> bf16 hi/lo -------------
__global__ void ln_bf(const float* __restrict__ x,
                      const float* __restrict__ gam,
                      const float* __restrict__ bet,
                      const float* __restrict__ pos,
                      __nv_bfloat16* __restrict__ oh,
                      __nv_bfloat16* __restrict__ ol)
{
    int row = blockIdx.x;
    int tid = threadIdx.x;
    const float4* xr = (const float4*)(x + (size_t)row * DD);
    float4 v = xr[tid];
    float s  = v.x + v.y + v.z + v.w;
    float ss = v.x * v.x + v.y * v.y + v.z * v.z + v.w * v.w;
#pragma unroll
    for (int o = 16; o > 0; o >>= 1) {
        s  += __shfl_xor_sync(0xffffffffu, s,  o);
        ss += __shfl_xor_sync(0xffffffffu, ss, o);
    }
    __shared__ float sb[8], sb2[8], stats[2];
    int wid = tid >> 5, lane = tid & 31;
    if (lane == 0) { sb[wid] = s; sb2[wid] = ss; }
    __syncthreads();
    if (tid == 0) {
        float ts = 0.f, tss = 0.f;
#pragma unroll
        for (int i = 0; i < 8; i++) { ts += sb[i]; tss += sb2[i]; }
        float mu  = ts  * (1.0f / DD);
        float var = tss * (1.0f / DD) - mu * mu;
        stats[0] = mu;
        stats[1] = rsqrtf(var + 1e-5f);
    }
    __syncthreads();
    float mu = stats[0], rs = stats[1];
    int c = tid * 4;
    float4 gg = *(const float4*)(gam + c);
    float4 bb = *(const float4*)(bet + c);
    float4 o4;
    o4.x = (v.x - mu) * rs * gg.x + bb.x;
    o4.y = (v.y - mu) * rs * gg.y + bb.y;
    o4.z = (v.z - mu) * rs * gg.z + bb.z;
    o4.w = (v.w - mu) * rs * gg.w + bb.w;
    if (pos) {
        int srow = row % SS;
        float4 p = *(const float4*)(pos + (size_t)srow * DD + c);
        o4.x += p.x; o4.y += p.y; o4.z += p.z; o4.w += p.w;
    }
    store_hilo4(oh, ol, (size_t)row * DD + c, o4);
}

// =================== mma.sync bf16-split GEMM (3-stage pipeline) ===========
// EPI: 0 = +bias -> fp32 ; 1 = gelu(+bias) -> bf16 hi/lo ;
//      2 = +bias+res -> fp32 ; 3 = +bias -> bf16 hi/lo
#define OFF_AH 0
#define OFF_AL 8192
#define OFF_BH 16384
#define OFF_BL 24576
#define STAGE  32768
#define NSTAGE 3
#define TCG_SMEM (NSTAGE * STAGE)

__device__ __forceinline__ uint32_t swz32(int row, int chunk) {
    return (uint32_t)(row * 64 + (((chunk ^ (row >> 1)) & 3) << 4));
}

__device__ __forceinline__ void cp_stage(uint32_t sbase,
                                         const __nv_bfloat16* __restrict__ Ahi,
                                         const __nv_bfloat16* __restrict__ Alo,
                                         const __nv_bfloat16* __restrict__ Bhi,
                                         const __nv_bfloat16* __restrict__ Blo,
                                         int am0, int bn0, int k0, int ldk, int tid)
{
#pragma unroll
    for (int j = 0; j < 2; j++) {
        int v = tid + (j << 8);
        int r = v >> 2, c = v & 3;
        uint32_t so = swz32(r, c);
        size_t goA = (size_t)(am0 + r) * ldk + k0 + c * 8;
        size_t goB = (size_t)(bn0 + r) * ldk + k0 + c * 8;
        cp_async16(sbase + OFF_AH + so, Ahi + goA);
        cp_async16(sbase + OFF_AL + so, Alo + goA);
        cp_async16(sbase + OFF_BH + so, Bhi + goB);
        cp_async16(sbase + OFF_BL + so, Blo + goB);
    }
}

template <int EPI>
__global__ __launch_bounds__(256, 2)
void tc_gemm(const __nv_bfloat16* __restrict__ Ahi, const __nv_bfloat16* __restrict__ Alo,
             const __nv_bfloat16* __restrict__ Bhi, const __nv_bfloat16* __restrict__ Blo,
             const float* __restrict__ bias, const float* __restrict__ res,
             float* __restrict__ Cf, __nv_bfloat16* __restrict__ Chi,
             __nv_bfloat16* __restrict__ Clo, int M, int N, int K)
{
    extern __shared__ __align__(128) char smc[];
    uint32_t sb = smem_u32(smc);
    int tid = threadIdx.x, wid = tid >> 5, lane = tid & 31;
    int warp_m = wid >> 1, warp_n = wid & 1;
    int bn = blockIdx.x, bm = blockIdx.y;
    int am0 = bm * 128, bn0 = bn * 128;

    float acc[2][8][4];
#pragma unroll
    for (int mi = 0; mi < 2; mi++)
#pragma unroll
        for (int ni = 0; ni < 8; ni++)
#pragma unroll
            for (int q = 0; q < 4; q++) acc[mi][ni][q] = 0.f;

    int lrA = (lane & 7) + ((lane >> 3) & 1) * 8;
    uint32_t cAoff = (uint32_t)((lane >> 4) << 4);
    uint32_t aB[2], aX[2];
#pragma unroll
    for (int mi = 0; mi < 2; mi++) {
        int row = warp_m * 32 + mi * 16 + lrA;
        aB[mi] = (uint32_t)(row * 64);
        aX[mi] = cAoff ^ (uint32_t)((((row >> 1) & 3)) << 4);
    }
    int lrB = (lane & 7) + ((lane >> 4) & 1) * 8;
    uint32_t cBoff = (uint32_t)(((lane >> 3) & 1) << 4);
    uint32_t bB[4], bX[4];
#pragma unroll
    for (int p = 0; p < 4; p++) {
        int row = warp_n * 64 + p * 16 + lrB;
        bB[p] = (uint32_t)(row * 64);
        bX[p] = cBoff ^ (uint32_t)((((row >> 1) & 3)) << 4);
    }

    int nchunk = K >> 5;
    cp_stage(sb + 0 * STAGE, Ahi, Alo, Bhi, Blo, am0, bn0, 0, K, tid);
    cp_commit();
    cp_stage(sb + 1 * STAGE, Ahi, Alo, Bhi, Blo, am0, bn0, 32, K, tid);
    cp_commit();

    int slot = 0;
    for (int ch = 0; ch < nchunk; ch++) {
        uint32_t st = sb + (uint32_t)slot * STAGE;
        cp_wait<1>();
        __syncthreads();
        int nslot = slot + 2; if (nslot >= NSTAGE) nslot -= NSTAGE;
        if (ch + 2 < nchunk)
            cp_stage(sb + (uint32_t)nslot * STAGE, Ahi, Alo, Bhi, Blo,
                     am0, bn0, (ch + 2) << 5, K, tid);
        cp_commit();

#pragma unroll
        for (int ks = 0; ks < 2; ks++) {
            uint32_t kx = (uint32_t)(ks << 5);
            uint32_t ah[2][4], bh[8][2];
#pragma unroll
            for (int mi = 0; mi < 2; mi++)
                ldsm_x4(ah[mi], st + OFF_AH + aB[mi] + (kx ^ aX[mi]));
#pragma unroll
            for (int p = 0; p < 4; p++) {
                uint32_t r4[4];
                ldsm_x4(r4, st + OFF_BH + bB[p] + (kx ^ bX[p]));
                bh[2 * p][0] = r4[0]; bh[2 * p][1] = r4[1];
                bh[2 * p + 1][0] = r4[2]; bh[2 * p + 1][1] = r4[3];
            }
#pragma unroll
            for (int mi = 0; mi < 2; mi++)
#pragma unroll
                for (int ni = 0; ni < 8; ni++)
                    mma16816(acc[mi][ni], ah[mi], bh[ni]);
            {
                uint32_t al[2][4];
#pragma unroll
                for (int mi = 0; mi < 2; mi++)
                    ldsm_x4(al[mi], st + OFF_AL + aB[mi] + (kx ^ aX[mi]));
#pragma unroll
                for (int mi = 0; mi < 2; mi++)
#pragma unroll
                    for (int ni = 0; ni < 8; ni++)
                        mma16816(acc[mi][ni], al[mi], bh[ni]);
            }
            {
                uint32_t bl[8][2];
#pragma unroll
                for (int p = 0; p < 4; p++) {
                    uint32_t r4[4];
                    ldsm_x4(r4, st + OFF_BL + bB[p] + (kx ^ bX[p]));
                    bl[2 * p][0] = r4[0]; bl[2 * p][1] = r4[1];
                    bl[2 * p + 1][0] = r4[2]; bl[2 * p + 1][1] = r4[3];
                }
#pragma unroll
                for (int mi = 0; mi < 2; mi++)
#pragma unroll
                    for (int ni = 0; ni < 8; ni++)
                        mma16816(acc[mi][ni], ah[mi], bl[ni]);
            }
        }
        slot++; if (slot >= NSTAGE) slot = 0;
    }

    int g = lane >> 2, tig = lane & 3;
#pragma unroll
    for (int mi = 0; mi < 2; mi++) {
#pragma unroll
        for (int half = 0; half < 2; half++) {
            int r = bm * 128 + warp_m * 32 + mi * 16 + g + half * 8;
#pragma unroll
            for (int ni = 0; ni < 8; ni++) {
                int c = bn * 128 + warp_n * 64 + ni * 8 + tig * 2;
                float v0 = acc[mi][ni][half * 2 + 0];
                float v1 = acc[mi][ni][half * 2 + 1];
                float2 bv = *(const float2*)(bias + c);
                v0 += bv.x; v1 += bv.y;
                size_t base = (size_t)r * N + c;
                if (EPI == 1) {
                    store_hilo2(Chi, Clo, base, gelu_tanh(v0), gelu_tanh(v1));
                } else if (EPI == 3) {
                    store_hilo2(Chi, Clo, base, v0, v1);
                } else {
                    if (EPI == 2) {
                        float2 rv = *(const float2*)(res + base);
                        v0 += rv.x; v1 += rv.y;
                    }
                    *(float2*)(Cf + base) = make_float2(v0, v1);
                }
            }
        }
    }
}

// ============ Tensor-core causal flash attention (cp.async pipelined) ======
// grid (S/64, H, B), 128 threads (4 warps; warp owns 16 q-rows).
// qkv already bf16 hi/lo (from qkv GEMM epilogue). Q loaded once; K/V tiles
// stream through a 3-stage cp.async pipeline. 128B rows, chunk^(row&7) swizzle.
#define AQH 0
#define AQL 8192
#define ASTG 16384
#define SKH 0
#define SKL 8192
#define SVH 16384
#define SVL 24576
#define SSTG 32768
#define ATT_SMEM (ASTG + 3 * SSTG)   // 112 KB

// copy one 64-row x 128B K tile + V tile (hi+lo) into a stage
__device__ __forceinline__ void attn_cp_kv(uint32_t stg,
                                           const __nv_bfloat16* __restrict__ qh,
                                           const __nv_bfloat16* __restrict__ ql,
                                           size_t rowbase, int hoff, int tid)
{
#pragma unroll
    for (int j = 0; j < 4; j++) {
        int idx = tid + (j << 7);
        int r = idx >> 3, c = idx & 7;
        uint32_t ad = (uint32_t)(r * 128) + (uint32_t)(((c ^ r) & 7) << 4);
        size_t gK = rowbase + (size_t)r * (3 * DD) + DD + hoff + c * 8;
        size_t gV = rowbase + (size_t)r * (3 * DD) + 2 * DD + hoff + c * 8;
        cp_async16(stg + SKH + ad, qh + gK);
        cp_async16(stg + SKL + ad, ql + gK);
        cp_async16(stg + SVH + ad, qh + gV);
        cp_async16(stg + SVL + ad, ql + gV);
    }
}

__global__ __launch_bounds__(128)
void attn_kernel(const __nv_bfloat16* __restrict__ qkvh,
                 const __nv_bfloat16* __restrict__ qkvl,
                 __nv_bfloat16* __restrict__ oh, __nv_bfloat16* __restrict__ ol)
{
    extern __shared__ __align__(128) char sma[];
    uint32_t sb = smem_u32(sma);
    int qt = (int)gridDim.x - 1 - (int)blockIdx.x;   // heavy blocks first
    int h = blockIdx.y, b = blockIdx.z;
    int tid = threadIdx.x, warp = tid >> 5, lane = tid & 31;
    int q0 = qt * 64;
    int g = lane >> 2, tig = lane & 3;
    int hoff = h * HDIM;

    // prologue: Q tile + K/V stage 0 (one group), then K/V stage 1
    {
        size_t rowQ = (size_t)(b * SS + q0) * (3 * DD);
#pragma unroll
        for (int j = 0; j < 4; j++) {
            int idx = tid + (j << 7);
            int r = idx >> 3, c = idx & 7;
            uint32_t ad = (uint32_t)(r * 128) + (uint32_t)(((c ^ r) & 7) << 4);
            size_t gQ = rowQ + (size_t)r * (3 * DD) + hoff + c * 8;
            cp_async16(sb + AQH + ad, qkvh + gQ);
            cp_async16(sb + AQL + ad, qkvl + gQ);
        }
        attn_cp_kv(sb + ASTG, qkvh, qkvl, (size_t)(b * SS) * (3 * DD), hoff, tid);
        cp_commit();
        // kt=1 prefetch always in-bounds (S >= 128)
        attn_cp_kv(sb + ASTG + SSTG, qkvh, qkvl,
                   (size_t)(b * SS + 64) * (3 * DD), hoff, tid);
        cp_commit();
    }

    // ldmatrix address precompute
    int lrA = (lane & 7) + ((lane >> 3) & 1) * 8;
    uint32_t cA = (uint32_t)((lane >> 4) << 4);
    int rowA = warp * 16 + lrA;
    uint32_t aBase = (uint32_t)(rowA * 128);
    uint32_t aMask = (uint32_t)((rowA & 7) << 4);

    int lrB = (lane & 7) + ((lane >> 4) & 1) * 8;
    uint32_t cB = (uint32_t)(((lane >> 3) & 1) << 4);

    int lrV = (lane & 7) + ((lane >> 3) & 1) * 8;
    uint32_t cV = (uint32_t)(((lane >> 4) & 1) << 4);

    float oacc[8][4];
    float mA = -1e30f, mB = -1e30f, lA = 0.f, lB = 0.f;
#pragma unroll
    for (int t = 0; t < 8; t++)
#pragma unroll
        for (int q = 0; q < 4; q++) oacc[t][q] = 0.f;

    int slot = 0;
    for (int kt = 0; kt <= qt; kt++) {
        uint32_t st = sb + ASTG + (uint32_t)slot * SSTG;
        cp_wait<1>();
        __syncthreads();
        int nslot = slot + 2; if (nslot >= 3) nslot -= 3;
        if (kt + 2 <= qt)
            attn_cp_kv(sb + ASTG + (uint32_t)nslot * SSTG, qkvh, qkvl,
                       (size_t)(b * SS + (kt + 2) * 64) * (3 * DD), hoff, tid);
        cp_commit();

        // ---- S = Q K^T (3-pass split), 16x64 stripe per warp ----
        float sacc[8][4];
#pragma unroll
        for (int t = 0; t < 8; t++)
#pragma unroll
            for (int q = 0; q < 4; q++) sacc[t][q] = 0.f;

#pragma unroll
        for (int ks = 0; ks < 4; ks++) {
            uint32_t kx = (uint32_t)(ks * 32);
            uint32_t qh4[4], ql4[4], kh[8][2];
            ldsm_x4(qh4, sb + AQH + aBase + ((kx + cA) ^ aMask));
            ldsm_x4(ql4, sb + AQL + aBase + ((kx + cA) ^ aMask));
#pragma unroll
            for (int p = 0; p < 4; p++) {
                int rowB = p * 16 + lrB;
                uint32_t r4[4];
                ldsm_x4(r4, st + SKH + (uint32_t)(rowB * 128) +
                            ((kx + cB) ^ (uint32_t)((rowB & 7) << 4)));
                kh[2 * p][0] = r4[0]; kh[2 * p][1] = r4[1];
                kh[2 * p + 1][0] = r4[2]; kh[2 * p + 1][1] = r4[3];
            }
#pragma unroll
            for (int t = 0; t < 8; t++) mma16816(sacc[t], qh4, kh[t]);
#pragma unroll
            for (int t = 0; t < 8; t++) mma16816(sacc[t], ql4, kh[t]);
            {
                uint32_t kl[8][2];
#pragma unroll
                for (int p = 0; p < 4; p++) {
                    int rowB = p * 16 + lrB;
                    uint32_t r4[4];
                    ldsm_x4(r4, st + SKL + (uint32_t)(rowB * 128) +
                                ((kx + cB) ^ (uint32_t)((rowB & 7) << 4)));
                    kl[2 * p][0] = r4[0]; kl[2 * p][1] = r4[1];
                    kl[2 * p + 1][0] = r4[2]; kl[2 * p + 1][1] = r4[3];
                }
#pragma unroll
                for (int t = 0; t < 8; t++) mma16816(sacc[t], qh4, kl[t]);
            }
        }

        // apply 1/sqrt(HDIM) scale
#pragma unroll
        for (int t = 0; t < 8; t++) {
            sacc[t][0] *= 0.125f; sacc[t][1] *= 0.125f;
            sacc[t][2] *= 0.125f; sacc[t][3] *= 0.125f;
        }

        // causal mask on diagonal tile
        if (kt == qt) {
            int qlocA = warp * 16 + g, qlocB = qlocA + 8;
#pragma unroll
            for (int t = 0; t < 8; t++) {
                int k0c = t * 8 + tig * 2;
                if (k0c > qlocA)     sacc[t][0] = -1e30f;
                if (k0c + 1 > qlocA) sacc[t][1] = -1e30f;
                if (k0c > qlocB)     sacc[t][2] = -1e30f;
                if (k0c + 1 > qlocB) sacc[t][3] = -1e30f;
            }
        }

        // ---- online softmax ----
        float maA = -1e30f, maB = -1e30f;
#pragma unroll
        for (int t = 0; t < 8; t++) {
            maA = fmaxf(maA, fmaxf(sacc[t][0], sacc[t][1]));
            maB = fmaxf(maB, fmaxf(sacc[t][2], sacc[t][3]));
        }
        maA = fmaxf(maA, __shfl_xor_sync(0xffffffffu, maA, 1));
        maA = fmaxf(maA, __shfl_xor_sync(0xffffffffu, maA, 2));
        maB = fmaxf(maB, __shfl_xor_sync(0xffffffffu, maB, 1));
        maB = fmaxf(maB, __shfl_xor_sync(0xffffffffu, maB, 2));
        float nmA = fmaxf(mA, maA), nmB = fmaxf(mB, maB);
        float corrA = fexp(mA - nmA), corrB = fexp(mB - nmB);
        mA = nmA; mB = nmB;
        float sumA = 0.f, sumB = 0.f;
#pragma unroll
        for (int t = 0; t < 8; t++) {
            sacc[t][0] = fexp(sacc[t][0] - nmA);
            sacc[t][1] = fexp(sacc[t][1] - nmA);
            sacc[t][2] = fexp(sacc[t][2] - nmB);
            sacc[t][3] = fexp(sacc[t][3] - nmB);
            sumA += sacc[t][0] + sacc[t][1];
            sumB += sacc[t][2] + sacc[t][3];
        }
        sumA += __shfl_xor_sync(0xffffffffu, sumA, 1);
        sumA += __shfl_xor_sync(0xffffffffu, sumA, 2);
        sumB += __shfl_xor_sync(0xffffffffu, sumB, 1);
        sumB += __shfl_xor_sync(0xffffffffu, sumB, 2);
        lA = lA * corrA + sumA;
        lB = lB * corrB + sumB;
#pragma unroll
        for (int t = 0; t < 8; t++) {
            oacc[t][0] *= corrA; oacc[t][1] *= corrA;
            oacc[t][2] *= corrB; oacc[t][3] *= corrB;
        }

        // ---- pack P into A-fragments (hi + lo) ----
        uint32_t ph[4][4], pl[4][4];
#pragma unroll
        for (int p = 0; p < 4; p++) {
#pragma unroll
            for (int q = 0; q < 4; q++) {
                int t = 2 * p + (q >> 1);
                float a = sacc[t][(q & 1) * 2 + 0];
                float bv = sacc[t][(q & 1) * 2 + 1];
                __nv_bfloat16 ah2 = __float2bfloat16(a), bh2 = __float2bfloat16(bv);
                __nv_bfloat162 th = __halves2bfloat162(ah2, bh2);
                ph[p][q] = *(uint32_t*)&th;
                __nv_bfloat162 tl = __halves2bfloat162(
                    __float2bfloat16(a - __bfloat162float(ah2)),
                    __float2bfloat16(bv - __bfloat162float(bh2)));
                pl[p][q] = *(uint32_t*)&tl;
            }
        }

        // ---- O += P V (3-pass) ----
#pragma unroll
        for (int ks = 0; ks < 4; ks++) {
            int rowV = ks * 16 + lrV;
            uint32_t vMask = (uint32_t)((rowV & 7) << 4);
            uint32_t vbh[8][2], vbl[8][2];
#pragma unroll
            for (int j = 0; j < 4; j++) {
                uint32_t cb = (uint32_t)(j * 32) + cV;
                uint32_t r4[4];
                ldsm_x4_t(r4, st + SVH + (uint32_t)(rowV * 128) + (cb ^ vMask));
                vbh[2 * j][0] = r4[0]; vbh[2 * j][1] = r4[1];
                vbh[2 * j + 1][0] = r4[2]; vbh[2 * j + 1][1] = r4[3];
            }
#pragma unroll
            for (int j = 0; j < 4; j++) {
                uint32_t cb = (uint32_t)(j * 32) + cV;
                uint32_t r4[4];
                ldsm_x4_t(r4, st + SVL + (uint32_t)(rowV * 128) + (cb ^ vMask));
                vbl[2 * j][0] = r4[0]; vbl[2 * j][1] = r4[1];
                vbl[2 * j + 1][0] = r4[2]; vbl[2 * j + 1][1] = r4[3];
            }
#pragma unroll
            for (int t = 0; t < 8; t++) mma16816(oacc[t], ph[ks], vbh[t]);
#pragma unroll
            for (int t = 0; t < 8; t++) mma16816(oacc[t], pl[ks], vbh[t]);
#pragma unroll
            for (int t = 0; t < 8; t++) mma16816(oacc[t], ph[ks], vbl[t]);
        }
        slot++; if (slot >= 3) slot = 0;
    }

    // ---- normalize + write ----
    float invA = 1.0f / lA, invB = 1.0f / lB;
    int rowAg = b * SS + q0 + warp * 16 + g;
    int rowBg = rowAg + 8;
#pragma unroll
    for (int t = 0; t < 8; t++) {
        int d0 = t * 8 + tig * 2;
        store_hilo2(oh, ol, (size_t)rowAg * DD + h * HDIM + d0,
                    oacc[t][0] * invA, oacc[t][1] * invA);
        store_hilo2(oh, ol, (size_t)rowBg * DD + h * HDIM + d0,
                    oacc[t][2] * invB, oacc[t][3] * invB);
    }
}

// ---------------- launch ---------------------------------------------------
extern "C" void kernel_launch(void* const* d_in, const int* in_sizes, int n_in,
                              void* d_out, int out_size)
{
    const float* x    = (const float*)d_in[0];
    const float* pos  = (const float*)d_in[1];
    const float* ln1g = (const float*)d_in[2];
    const float* ln1b = (const float*)d_in[3];
    const float* wqkv = (const float*)d_in[4];
    const float* bqkv = (const float*)d_in[5];
    const float* wo   = (const float*)d_in[6];
    const float* bo   = (const float*)d_in[7];
    const float* ln2g = (const float*)d_in[8];
    const float* ln2b = (const float*)d_in[9];
    const float* wfc  = (const float*)d_in[10];
    const float* bfc  = (const float*)d_in[11];
    const float* wpr  = (const float*)d_in[12];
    const float* bpr  = (const float*)d_in[13];
    float* out = (float*)d_out;

    __nv_bfloat16 *p_h_hi, *p_h_lo, *p_qkvh, *p_qkvl, *p_at_hi, *p_at_lo;
    __nv_bfloat16 *p_m_hi, *p_m_lo, *p_ff_hi, *p_ff_lo;
    __nv_bfloat16 *p_wqkv_hi, *p_wqkv_lo, *p_wo_hi, *p_wo_lo, *p_wfc_hi, *p_wfc_lo, *p_wpr_hi, *p_wpr_lo;
    float *p_x2;
    cudaGetSymbolAddress((void**)&p_h_hi, g_h_hi);   cudaGetSymbolAddress((void**)&p_h_lo, g_h_lo);
    cudaGetSymbolAddress((void**)&p_qkvh, g_qkvh);   cudaGetSymbolAddress((void**)&p_qkvl, g_qkvl);
    cudaGetSymbolAddress((void**)&p_at_hi, g_at_hi); cudaGetSymbolAddress((void**)&p_at_lo, g_at_lo);
    cudaGetSymbolAddress((void**)&p_x2, g_x2);
    cudaGetSymbolAddress((void**)&p_m_hi, g_m_hi);   cudaGetSymbolAddress((void**)&p_m_lo, g_m_lo);
    cudaGetSymbolAddress((void**)&p_ff_hi, g_ff_hi); cudaGetSymbolAddress((void**)&p_ff_lo, g_ff_lo);
    cudaGetSymbolAddress((void**)&p_wqkv_hi, g_wqkv_hi); cudaGetSymbolAddress((void**)&p_wqkv_lo, g_wqkv_lo);
    cudaGetSymbolAddress((void**)&p_wo_hi, g_wo_hi);     cudaGetSymbolAddress((void**)&p_wo_lo, g_wo_lo);
    cudaGetSymbolAddress((void**)&p_wfc_hi, g_wfc_hi);   cudaGetSymbolAddress((void**)&p_wfc_lo, g_wfc_lo);
    cudaGetSymbolAddress((void**)&p_wpr_hi, g_wpr_hi);   cudaGetSymbolAddress((void**)&p_wpr_lo, g_wpr_lo);

    cudaFuncSetAttribute(tc_gemm<0>, cudaFuncAttributeMaxDynamicSharedMemorySize, TCG_SMEM);
    cudaFuncSetAttribute(tc_gemm<1>, cudaFuncAttributeMaxDynamicSharedMemorySize, TCG_SMEM);
    cudaFuncSetAttribute(tc_gemm<2>, cudaFuncAttributeMaxDynamicSharedMemorySize, TCG_SMEM);
    cudaFuncSetAttribute(tc_gemm<3>, cudaFuncAttributeMaxDynamicSharedMemorySize, TCG_SMEM);
    cudaFuncSetAttribute(attn_kernel, cudaFuncAttributeMaxDynamicSharedMemorySize, ATT_SMEM);

    dim3 tb(32, 8);
    wsplit_t<<<dim3(3 * DD / 32, DD / 32), tb>>>(wqkv, p_wqkv_hi, p_wqkv_lo, DD, 3 * DD);
    wsplit_t<<<dim3(DD / 32, DD / 32), tb>>>(wo, p_wo_hi, p_wo_lo, DD, DD);
    wsplit_t<<<dim3(DFFN / 32, DD / 32), tb>>>(wfc, p_wfc_hi, p_wfc_lo, DD, DFFN);
    wsplit_t<<<dim3(DD / 32, DFFN / 32), tb>>>(wpr, p_wpr_hi, p_wpr_lo, DFFN, DD);

    ln_bf<<<ROWS, 256>>>(x, ln1g, ln1b, pos, p_h_hi, p_h_lo);

    // qkv = h @ w_qkv + b_qkv -> bf16 hi/lo
    tc_gemm<3><<<dim3(3 * DD / 128, ROWS / 128), 256, TCG_SMEM>>>(
        p_h_hi, p_h_lo, p_wqkv_hi, p_wqkv_lo, bqkv, nullptr,
        nullptr, p_qkvh, p_qkvl, ROWS, 3 * DD, DD);

    attn_kernel<<<dim3(SS / 64, HH, BB), 128, ATT_SMEM>>>(p_qkvh, p_qkvl, p_at_hi, p_at_lo);

    tc_gemm<2><<<dim3(DD / 128, ROWS / 128), 256, TCG_SMEM>>>(
        p_at_hi, p_at_lo, p_wo_hi, p_wo_lo, bo, x,
        p_x2, nullptr, nullptr, ROWS, DD, DD);

    ln_bf<<<ROWS, 256>>>(p_x2, ln2g, ln2b, nullptr, p_m_hi, p_m_lo);

    tc_gemm<1><<<dim3(DFFN / 128, ROWS / 128), 256, TCG_SMEM>>>(
        p_m_hi, p_m_lo, p_wfc_hi, p_wfc_lo, bfc, nullptr,
        nullptr, p_ff_hi, p_ff_lo, ROWS, DFFN, DD);

    tc_gemm<2><<<dim3(DD / 128, ROWS / 128), 256, TCG_SMEM>>>(
        p_ff_hi, p_ff_lo, p_wpr_hi, p_wpr_lo, bpr, p_x2,
        out, nullptr, nullptr, ROWS, DD, DFFN);
}

// round 10
// speedup vs baseline: 5.1399x; 1.0823x over previous
#include <cuda_runtime.h>
#include <cuda_bf16.h>
#include <math.h>
#include <stdint.h>

// Problem constants
#define BB   2
#define SS   2048
#define DD   1024
#define HH   16
#define HDIM 64
#define DFFN 4096
#define ROWS (BB * SS)   // 4096

// -------- scratch (static device globals; no allocation) --------
__device__ __align__(16) __nv_bfloat16 g_h_hi[ROWS * DD], g_h_lo[ROWS * DD];
__device__ __align__(16) __nv_bfloat16 g_qkvh[ROWS * 3 * DD], g_qkvl[ROWS * 3 * DD];
__device__ __align__(16) float         g_at[ROWS * DD];          // tf32-rounded
__device__ __align__(16) float         g_x2[ROWS * DD];
__device__ __align__(16) float         g_m[ROWS * DD];           // tf32-rounded
__device__ __align__(16) float         g_ff[ROWS * DFFN];        // tf32-rounded
// weights: wqkv split bf16 (transposed); others transposed fp32 tf32-rounded
__device__ __align__(16) __nv_bfloat16 g_wqkv_hi[3 * DD * DD], g_wqkv_lo[3 * DD * DD];
__device__ __align__(16) float         g_woT[DD * DD];
__device__ __align__(16) float         g_wfcT[DFFN * DD];
__device__ __align__(16) float         g_wprT[DD * DFFN];

// ======================= portable PTX helpers ==============================
__device__ __forceinline__ uint32_t smem_u32(const void* p) {
    uint32_t a;
    asm("{ .reg .u64 t; cvta.to.shared.u64 t, %1; cvt.u32.u64 %0, t; }" : "=r"(a) : "l"(p));
    return a;
}

__device__ __forceinline__ void cp_async16(uint32_t saddr, const void* gaddr) {
    asm volatile("cp.async.cg.shared.global [%0], [%1], 16;" :: "r"(saddr), "l"(gaddr));
}
__device__ __forceinline__ void cp_commit() {
    asm volatile("cp.async.commit_group;" ::: "memory");
}
template <int N>
__device__ __forceinline__ void cp_wait() {
    asm volatile("cp.async.wait_group %0;" :: "n"(N) : "memory");
}

__device__ __forceinline__ void ldsm_x4(uint32_t* r, uint32_t addr) {
    asm volatile("ldmatrix.sync.aligned.m8n8.x4.shared.b16 {%0,%1,%2,%3}, [%4];"
        : "=r"(r[0]), "=r"(r[1]), "=r"(r[2]), "=r"(r[3]) : "r"(addr));
}
__device__ __forceinline__ void ldsm_x4_t(uint32_t* r, uint32_t addr) {
    asm volatile("ldmatrix.sync.aligned.m8n8.x4.trans.shared.b16 {%0,%1,%2,%3}, [%4];"
        : "=r"(r[0]), "=r"(r[1]), "=r"(r[2]), "=r"(r[3]) : "r"(addr));
}

__device__ __forceinline__ void mma16816(float* c, const uint32_t* a, const uint32_t* b) {
    asm volatile(
        "mma.sync.aligned.m16n8k16.row.col.f32.bf16.bf16.f32 "
        "{%0,%1,%2,%3}, {%4,%5,%6,%7}, {%8,%9}, {%0,%1,%2,%3};"
        : "+f"(c[0]), "+f"(c[1]), "+f"(c[2]), "+f"(c[3])
        : "r"(a[0]), "r"(a[1]), "r"(a[2]), "r"(a[3]), "r"(b[0]), "r"(b[1]));
}

__device__ __forceinline__ void mma_tf32(float* c, const uint32_t* a, const uint32_t* b) {
    asm volatile(
        "mma.sync.aligned.m16n8k8.row.col.f32.tf32.tf32.f32 "
        "{%0,%1,%2,%3}, {%4,%5,%6,%7}, {%8,%9}, {%0,%1,%2,%3};"
        : "+f"(c[0]), "+f"(c[1]), "+f"(c[2]), "+f"(c[3])
        : "r"(a[0]), "r"(a[1]), "r"(a[2]), "r"(a[3]), "r"(b[0]), "r"(b[1]));
}

__device__ __forceinline__ float to_tf32(float x) {
    uint32_t o;
    asm("cvt.rna.tf32.f32 %0, %1;" : "=r"(o) : "f"(x));
    return __uint_as_float(o);
}

// ======================= small math helpers ================================
__device__ __forceinline__ float gelu_tanh(float x) {
    float x3 = x * x * x;
    float t = tanhf(0.7978845608028654f * (x + 0.044715f * x3));
    return 0.5f * x * (1.0f + t);
}

// fast exp on the FMA pipe (no MUFU)
__device__ __forceinline__ float fexp(float x) {
    float y = fmaxf(x * 1.4426950408889634f, -126.0f);
    float z = y + 12582912.0f;
    int   n = __float_as_int(z) - 0x4B400000;
    float f = y - (z - 12582912.0f);
    float p = 0.0013333558146f;
    p = fmaf(p, f, 0.0096181291076f);
    p = fmaf(p, f, 0.0555041086648f);
    p = fmaf(p, f, 0.2402265069591f);
    p = fmaf(p, f, 0.6931471805599f);
    p = fmaf(p, f, 1.0f);
    return p * __int_as_float((n + 127) << 23);
}

__device__ __forceinline__ void store_hilo4(__nv_bfloat16* oh, __nv_bfloat16* ol,
                                            size_t idx, float4 v)
{
    __nv_bfloat16 h0 = __float2bfloat16(v.x), h1 = __float2bfloat16(v.y);
    __nv_bfloat16 h2 = __float2bfloat16(v.z), h3 = __float2bfloat16(v.w);
    float l0 = v.x - __bfloat162float(h0), l1 = v.y - __bfloat162float(h1);
    float l2 = v.z - __bfloat162float(h2), l3 = v.w - __bfloat162float(h3);
    *(__nv_bfloat162*)(oh + idx)     = __halves2bfloat162(h0, h1);
    *(__nv_bfloat162*)(oh + idx + 2) = __halves2bfloat162(h2, h3);
    *(__nv_bfloat162*)(ol + idx)     = __halves2bfloat162(__float2bfloat16(l0), __float2bfloat16(l1));
    *(__nv_bfloat162*)(ol + idx + 2) = __halves2bfloat162(__float2bfloat16(l2), __float2bfloat16(l3));
}

__device__ __forceinline__ void store_hilo2(__nv_bfloat16* oh, __nv_bfloat16* ol,
                                            size_t idx, float a, float b)
{
    __nv_bfloat16 h0 = __float2bfloat16(a), h1 = __float2bfloat16(b);
    float l0 = a - __bfloat162float(h0), l1 = b - __bfloat162float(h1);
    *(__nv_bfloat162*)(oh + idx) = __halves2bfloat162(h0, h1);
    *(__nv_bfloat162*)(ol + idx) = __halves2bfloat162(__float2bfloat16(l0), __float2bfloat16(l1));
}

// ============ weight transpose + bf16 split (qkv only) =====================
__global__ void wsplit_t(const float* __restrict__ W, __nv_bfloat16* __restrict__ Th,
                         __nv_bfloat16* __restrict__ Tl, int K, int N)
{
    __shared__ float t[32][33];
    int bx = blockIdx.x, by = blockIdx.y;
    int x = threadIdx.x, y = threadIdx.y;
#pragma unroll
    for (int i = 0; i < 32; i += 8)
        t[y + i][x] = W[(size_t)(by * 32 + y + i) * N + bx * 32 + x];
    __syncthreads();
#pragma unroll
    for (int i = 0; i < 32; i += 8) {
        float v = t[x][y + i];
        __nv_bfloat16 h = __float2bfloat16(v);
        float lo = v - __bfloat162float(h);
        size_t o = (size_t)(bx * 32 + y + i) * K + by * 32 + x;
        Th[o] = h;
        Tl[o] = __float2bfloat16(lo);
    }
}

// ============ weight transpose + tf32 round (others) =======================
__global__ void wtrans(const float* __restrict__ W, float* __restrict__ T, int K, int N)
{
    __shared__ float t[32][33];
    int bx = blockIdx.x, by = blockIdx.y;
    int x = threadIdx.x, y = threadIdx.y;
#pragma unroll
    for (int i = 0; i < 32; i += 8)
        t[y + i][x] = W[(size_t)(by * 32 + y + i) * N + bx * 32 + x];
    __syncthreads();
#pragma unroll
    for (int i = 0; i < 32; i += 8)
        T[(size_t)(bx * 32 + y + i) * K + by * 32 + x] = to_tf32(t[x][y + i]);
}

// ---------------- LayerNorm -> bf16 hi/lo (feeds bf16 GEMM) ----------------
__global__ void ln_bf(const float* __restrict__ x,
                      const float* __restrict__ gam,
                      const float* __restrict__ bet,
                      const float* __restrict__ pos,
                      __nv_bfloat16* __restrict__ oh,
                      __nv_bfloat16* __restrict__ ol)
{
    int row = blockIdx.x;
    int tid = threadIdx.x;
    const float4* xr = (const float4*)(x + (size_t)row * DD);
    float4 v = xr[tid];
    float s  = v.x + v.y + v.z + v.w;
    float ss = v.x * v.x + v.y * v.y + v.z * v.z + v.w * v.w;
#pragma unroll
    for (int o = 16; o > 0; o >>= 1) {
        s  += __shfl_xor_sync(0xffffffffu, s,  o);
        ss += __shfl_xor_sync(0xffffffffu, ss, o);
    }
    __shared__ float sb[8], sb2[8], stats[2];
    int wid = tid >> 5, lane = tid & 31;
    if (lane == 0) { sb[wid] = s; sb2[wid] = ss; }
    __syncthreads();
    if (tid == 0) {
        float ts = 0.f, tss = 0.f;
#pragma unroll
        for (int i = 0; i < 8; i++) { ts += sb[i]; tss += sb2[i]; }
        float mu  = ts  * (1.0f / DD);
        float var = tss * (1.0f / DD) - mu * mu;
        stats[0] = mu;
        stats[1] = rsqrtf(var + 1e-5f);
    }
    __syncthreads();
    float mu = stats[0], rs = stats[1];
    int c = tid * 4;
    float4 gg = *(const float4*)(gam + c);
    float4 bb = *(const float4*)(bet + c);
    float4 o4;
    o4.x = (v.x - mu) * rs * gg.x + bb.x;
    o4.y = (v.y - mu) * rs * gg.y + bb.y;
    o4.z = (v.z - mu) * rs * gg.z + bb.z;
    o4.w = (v.w - mu) * rs * gg.w + bb.w;
    if (pos) {
        int srow = row % SS;
        float4 p = *(const float4*)(pos + (size_t)srow * DD + c);
        o4.x += p.x; o4.y += p.y; o4.z += p.z; o4.w += p.w;
    }
    store_hilo4(oh, ol, (size_t)row * DD + c, o4);
}

// ---------------- LayerNorm -> tf32-rounded fp32 (feeds tf32 GEMM) ---------
__global__ void ln_tf(const float* __restrict__ x,
                      const float* __restrict__ gam,
                      const float* __restrict__ bet,
                      float* __restrict__ out)
{
    int row = blockIdx.x;
    int tid = threadIdx.x;
    const float4* xr = (const float4*)(x + (size_t)row * DD);
    float4 v = xr[tid];
    float s  = v.x + v.y + v.z + v.w;
    float ss = v.x * v.x + v.y * v.y + v.z * v.z + v.w * v.w;
#pragma unroll
    for (int o = 16; o > 0; o >>= 1) {
        s  += __shfl_xor_sync(0xffffffffu, s,  o);
        ss += __shfl_xor_sync(0xffffffffu, ss, o);
    }
    __shared__ float sb[8], sb2[8], stats[2];
    int wid = tid >> 5, lane = tid & 31;
    if (lane == 0) { sb[wid] = s; sb2[wid] = ss; }
    __syncthreads();
    if (tid == 0) {
        float ts = 0.f, tss = 0.f;
#pragma unroll
        for (int i = 0; i < 8; i++) { ts += sb[i]; tss += sb2[i]; }
        float mu  = ts  * (1.0f / DD);
        float var = tss * (1.0f / DD) - mu * mu;
        stats[0] = mu;
        stats[1] = rsqrtf(var + 1e-5f);
    }
    __syncthreads();
    float mu = stats[0], rs = stats[1];
    int c = tid * 4;
    float4 gg = *(const float4*)(gam + c);
    float4 bb = *(const float4*)(bet + c);
    float4 o4;
    o4.x = to_tf32((v.x - mu) * rs * gg.x + bb.x);
    o4.y = to_tf32((v.y - mu) * rs * gg.y + bb.y);
    o4.z = to_tf32((v.z - mu) * rs * gg.z + bb.z);
    o4.w = to_tf32((v.w - mu) * rs * gg.w + bb.w);
    *(float4*)(out + (size_t)row * DD + c) = o4;
}

// =================== bf16 3-pass GEMM (qkv only; 3-stage pipeline) =========
#define OFF_AH 0
#define OFF_AL 8192
#define OFF_BH 16384
#define OFF_BL 24576
#define STAGE  32768
#define NSTAGE 3
#define TCG_SMEM (NSTAGE * STAGE)

__device__ __forceinline__ uint32_t swz32(int row, int chunk) {
    return (uint32_t)(row * 64 + (((chunk ^ (row >> 1)) & 3) << 4));
}

__device__ __forceinline__ void cp_stage(uint32_t sbase,
                                         const __nv_bfloat16* __restrict__ Ahi,
                                         const __nv_bfloat16* __restrict__ Alo,
                                         const __nv_bfloat16* __restrict__ Bhi,
                                         const __nv_bfloat16* __restrict__ Blo,
                                         int am0, int bn0, int k0, int ldk, int tid)
{
#pragma unroll
    for (int j = 0; j < 2; j++) {
        int v = tid + (j << 8);
        int r = v >> 2, c = v & 3;
        uint32_t so = swz32(r, c);
        size_t goA = (size_t)(am0 + r) * ldk + k0 + c * 8;
        size_t goB = (size_t)(bn0 + r) * ldk + k0 + c * 8;
        cp_async16(sbase + OFF_AH + so, Ahi + goA);
        cp_async16(sbase + OFF_AL + so, Alo + goA);
        cp_async16(sbase + OFF_BH + so, Bhi + goB);
        cp_async16(sbase + OFF_BL + so, Blo + goB);
    }
}

__global__ __launch_bounds__(256, 2)
void tc_gemm_bf(const __nv_bfloat16* __restrict__ Ahi, const __nv_bfloat16* __restrict__ Alo,
                const __nv_bfloat16* __restrict__ Bhi, const __nv_bfloat16* __restrict__ Blo,
                const float* __restrict__ bias,
                __nv_bfloat16* __restrict__ Chi, __nv_bfloat16* __restrict__ Clo,
                int M, int N, int K)
{
    extern __shared__ __align__(128) char smc[];
    uint32_t sb = smem_u32(smc);
    int tid = threadIdx.x, wid = tid >> 5, lane = tid & 31;
    int warp_m = wid >> 1, warp_n = wid & 1;
    int bn = blockIdx.x, bm = blockIdx.y;
    int am0 = bm * 128, bn0 = bn * 128;

    float acc[2][8][4];
#pragma unroll
    for (int mi = 0; mi < 2; mi++)
#pragma unroll
        for (int ni = 0; ni < 8; ni++)
#pragma unroll
            for (int q = 0; q < 4; q++) acc[mi][ni][q] = 0.f;

    int lrA = (lane & 7) + ((lane >> 3) & 1) * 8;
    uint32_t cAoff = (uint32_t)((lane >> 4) << 4);
    uint32_t aB[2], aX[2];
#pragma unroll
    for (int mi = 0; mi < 2; mi++) {
        int row = warp_m * 32 + mi * 16 + lrA;
        aB[mi] = (uint32_t)(row * 64);
        aX[mi] = cAoff ^ (uint32_t)((((row >> 1) & 3)) << 4);
    }
    int lrB = (lane & 7) + ((lane >> 4) & 1) * 8;
    uint32_t cBoff = (uint32_t)(((lane >> 3) & 1) << 4);
    uint32_t bB[4], bX[4];
#pragma unroll
    for (int p = 0; p < 4; p++) {
        int row = warp_n * 64 + p * 16 + lrB;
        bB[p] = (uint32_t)(row * 64);
        bX[p] = cBoff ^ (uint32_t)((((row >> 1) & 3)) << 4);
    }

    int nchunk = K >> 5;
    cp_stage(sb + 0 * STAGE, Ahi, Alo, Bhi, Blo, am0, bn0, 0, K, tid);
    cp_commit();
    cp_stage(sb + 1 * STAGE, Ahi, Alo, Bhi, Blo, am0, bn0, 32, K, tid);
    cp_commit();

    int slot = 0;
    for (int ch = 0; ch < nchunk; ch++) {
        uint32_t st = sb + (uint32_t)slot * STAGE;
        cp_wait<1>();
        __syncthreads();
        int nslot = slot + 2; if (nslot >= NSTAGE) nslot -= NSTAGE;
        if (ch + 2 < nchunk)
            cp_stage(sb + (uint32_t)nslot * STAGE, Ahi, Alo, Bhi, Blo,
                     am0, bn0, (ch + 2) << 5, K, tid);
        cp_commit();

#pragma unroll
        for (int ks = 0; ks < 2; ks++) {
            uint32_t kx = (uint32_t)(ks << 5);
            uint32_t ah[2][4], bh[8][2];
#pragma unroll
            for (int mi = 0; mi < 2; mi++)
                ldsm_x4(ah[mi], st + OFF_AH + aB[mi] + (kx ^ aX[mi]));
#pragma unroll
            for (int p = 0; p < 4; p++) {
                uint32_t r4[4];
                ldsm_x4(r4, st + OFF_BH + bB[p] + (kx ^ bX[p]));
                bh[2 * p][0] = r4[0]; bh[2 * p][1] = r4[1];
                bh[2 * p + 1][0] = r4[2]; bh[2 * p + 1][1] = r4[3];
            }
#pragma unroll
            for (int mi = 0; mi < 2; mi++)
#pragma unroll
                for (int ni = 0; ni < 8; ni++)
                    mma16816(acc[mi][ni], ah[mi], bh[ni]);
            {
                uint32_t al[2][4];
#pragma unroll
                for (int mi = 0; mi < 2; mi++)
                    ldsm_x4(al[mi], st + OFF_AL + aB[mi] + (kx ^ aX[mi]));
#pragma unroll
                for (int mi = 0; mi < 2; mi++)
#pragma unroll
                    for (int ni = 0; ni < 8; ni++)
                        mma16816(acc[mi][ni], al[mi], bh[ni]);
            }
            {
                uint32_t bl[8][2];
#pragma unroll
                for (int p = 0; p < 4; p++) {
                    uint32_t r4[4];
                    ldsm_x4(r4, st + OFF_BL + bB[p] + (kx ^ bX[p]));
                    bl[2 * p][0] = r4[0]; bl[2 * p][1] = r4[1];
                    bl[2 * p + 1][0] = r4[2]; bl[2 * p + 1][1] = r4[3];
                }
#pragma unroll
                for (int mi = 0; mi < 2; mi++)
#pragma unroll
                    for (int ni = 0; ni < 8; ni++)
                        mma16816(acc[mi][ni], ah[mi], bl[ni]);
            }
        }
        slot++; if (slot >= NSTAGE) slot = 0;
    }

    int g = lane >> 2, tig = lane & 3;
#pragma unroll
    for (int mi = 0; mi < 2; mi++) {
#pragma unroll
        for (int half = 0; half < 2; half++) {
            int r = bm * 128 + warp_m * 32 + mi * 16 + g + half * 8;
#pragma unroll
            for (int ni = 0; ni < 8; ni++) {
                int c = bn * 128 + warp_n * 64 + ni * 8 + tig * 2;
                float v0 = acc[mi][ni][half * 2 + 0];
                float v1 = acc[mi][ni][half * 2 + 1];
                float2 bv = *(const float2*)(bias + c);
                v0 += bv.x; v1 += bv.y;
                store_hilo2(Chi, Clo, (size_t)r * N + c, v0, v1);
            }
        }
    }
}

// =================== tf32 single-pass GEMM (3-stage pipeline) ==============
// C = A[M,K] @ Wt[N,K]^T + bias (+epilogue). Inputs pre-rounded to tf32.
// 128x128 CTA tile, 256 thr (8 warps 4m x 2n, 32x64 warp tile), K-chunks 32.
// smem: padded rows of 36 floats (bank = 4g+tig, conflict-free).
// EPI: 1 = gelu(+bias) -> tf32-rounded fp32 ; 2 = +bias+res -> fp32
#define TROW 36
#define TTILE (128 * TROW)          // floats per tile (4608)
#define TSTAGEF (2 * TTILE)         // floats per stage (9216)
#define TSTAGEB (TSTAGEF * 4)       // bytes per stage (36864)
#define TF_SMEM (3 * TSTAGEB)       // 110592 bytes

__device__ __forceinline__ void cp_stage_tf(uint32_t sbase,
                                            const float* __restrict__ A,
                                            const float* __restrict__ Bt,
                                            int am0, int bn0, int k0, int ldk, int tid)
{
#pragma unroll
    for (int j = 0; j < 8; j++) {
        int idx = tid + (j << 8);        // 0..2047
        int tile = idx >> 10;
        int w = idx & 1023;
        int r = w >> 3, c = w & 7;       // row, 16B chunk (4 floats)
        uint32_t dst = sbase + (uint32_t)tile * (TTILE * 4) + (uint32_t)(r * TROW * 4 + c * 16);
        const float* src = (tile ? Bt + (size_t)(bn0 + r) * ldk : A + (size_t)(am0 + r) * ldk)
                           + k0 + c * 4;
        cp_async16(dst, src);
    }
}

template <int EPI>
__global__ __launch_bounds__(256, 2)
void tf_gemm(const float* __restrict__ A, const float* __restrict__ Bt,
             const float* __restrict__ bias, const float* __restrict__ res,
             float* __restrict__ Cf, int M, int N, int K)
{
    extern __shared__ __align__(128) float smf[];
    uint32_t sb = smem_u32(smf);
    int tid = threadIdx.x, wid = tid >> 5, lane = tid & 31;
    int warp_m = wid >> 1, warp_n = wid & 1;
    int g = lane >> 2, tig = lane & 3;
    int bn = blockIdx.x, bm = blockIdx.y;
    int am0 = bm * 128, bn0 = bn * 128;

    float acc[2][8][4];
#pragma unroll
    for (int mi = 0; mi < 2; mi++)
#pragma unroll
        for (int ni = 0; ni < 8; ni++)
#pragma unroll
            for (int q = 0; q < 4; q++) acc[mi][ni][q] = 0.f;

    int nchunk = K >> 5;
    cp_stage_tf(sb + 0 * TSTAGEB, A, Bt, am0, bn0, 0, K, tid);
    cp_commit();
    cp_stage_tf(sb + 1 * TSTAGEB, A, Bt, am0, bn0, 32, K, tid);
    cp_commit();

    int slot = 0;
    for (int ch = 0; ch < nchunk; ch++) {
        cp_wait<1>();
        __syncthreads();
        int nslot = slot + 2; if (nslot >= 3) nslot -= 3;
        if (ch + 2 < nchunk)
            cp_stage_tf(sb + (uint32_t)nslot * TSTAGEB, A, Bt, am0, bn0,
                        (ch + 2) << 5, K, tid);
        cp_commit();

        const float* As = smf + slot * TSTAGEF;
        const float* Bs = As + TTILE;

#pragma unroll
        for (int ks = 0; ks < 4; ks++) {
            int kb = ks * 8;
            uint32_t a[2][4];
#pragma unroll
            for (int mi = 0; mi < 2; mi++) {
                int rb = warp_m * 32 + mi * 16;
                a[mi][0] = __float_as_uint(As[(rb + g) * TROW + kb + tig]);
                a[mi][1] = __float_as_uint(As[(rb + 8 + g) * TROW + kb + tig]);
                a[mi][2] = __float_as_uint(As[(rb + g) * TROW + kb + tig + 4]);
                a[mi][3] = __float_as_uint(As[(rb + 8 + g) * TROW + kb + tig + 4]);
            }
            uint32_t b[8][2];
#pragma unroll
            for (int ni = 0; ni < 8; ni++) {
                int rn = warp_n * 64 + ni * 8 + g;
                b[ni][0] = __float_as_uint(Bs[rn * TROW + kb + tig]);
                b[ni][1] = __float_as_uint(Bs[rn * TROW + kb + tig + 4]);
            }
#pragma unroll
            for (int mi = 0; mi < 2; mi++)
#pragma unroll
                for (int ni = 0; ni < 8; ni++)
                    mma_tf32(acc[mi][ni], a[mi], b[ni]);
        }
        slot++; if (slot >= 3) slot = 0;
    }

#pragma unroll
    for (int mi = 0; mi < 2; mi++) {
#pragma unroll
        for (int half = 0; half < 2; half++) {
            int r = bm * 128 + warp_m * 32 + mi * 16 + g + half * 8;
#pragma unroll
            for (int ni = 0; ni < 8; ni++) {
                int c = bn * 128 + warp_n * 64 + ni * 8 + tig * 2;
                float v0 = acc[mi][ni][half * 2 + 0];
                float v1 = acc[mi][ni][half * 2 + 1];
                float2 bv = *(const float2*)(bias + c);
                v0 += bv.x; v1 += bv.y;
                size_t base = (size_t)r * N + c;
                if (EPI == 1) {
                    v0 = to_tf32(gelu_tanh(v0));
                    v1 = to_tf32(gelu_tanh(v1));
                } else {
                    float2 rv = *(const float2*)(res + base);
                    v0 += rv.x; v1 += rv.y;
                }
                *(float2*)(Cf + base) = make_float2(v0, v1);
            }
        }
    }
}

// ============ Tensor-core causal flash attention (cp.async pipelined) ======
#define AQH 0
#define AQL 8192
#define ASTG 16384
#define SKH 0
#define SKL 8192
#define SVH 16384
#define SVL 24576
#define SSTG 32768
#define ATT_SMEM (ASTG + 3 * SSTG)   // 112 KB

__device__ __forceinline__ void attn_cp_kv(uint32_t stg,
                                           const __nv_bfloat16* __restrict__ qh,
                                           const __nv_bfloat16* __restrict__ ql,
                                           size_t rowbase, int hoff, int tid)
{
#pragma unroll
    for (int j = 0; j < 4; j++) {
        int idx = tid + (j << 7);
        int r = idx >> 3, c = idx & 7;
        uint32_t ad = (uint32_t)(r * 128) + (uint32_t)(((c ^ r) & 7) << 4);
        size_t gK = rowbase + (size_t)r * (3 * DD) + DD + hoff + c * 8;
        size_t gV = rowbase + (size_t)r * (3 * DD) + 2 * DD + hoff + c * 8;
        cp_async16(stg + SKH + ad, qh + gK);
        cp_async16(stg + SKL + ad, ql + gK);
        cp_async16(stg + SVH + ad, qh + gV);
        cp_async16(stg + SVL + ad, ql + gV);
    }
}

__global__ __launch_bounds__(128)
void attn_kernel(const __nv_bfloat16* __restrict__ qkvh,
                 const __nv_bfloat16* __restrict__ qkvl,
                 float* __restrict__ oat)
{
    extern __shared__ __align__(128) char sma[];
    uint32_t sb = smem_u32(sma);
    int qt = (int)gridDim.x - 1 - (int)blockIdx.x;
    int h = blockIdx.y, b = blockIdx.z;
    int tid = threadIdx.x, warp = tid >> 5, lane = tid & 31;
    int q0 = qt * 64;
    int g = lane >> 2, tig = lane & 3;
    int hoff = h * HDIM;

    {
        size_t rowQ = (size_t)(b * SS + q0) * (3 * DD);
#pragma unroll
        for (int j = 0; j < 4; j++) {
            int idx = tid + (j << 7);
            int r = idx >> 3, c = idx & 7;
            uint32_t ad = (uint32_t)(r * 128) + (uint32_t)(((c ^ r) & 7) << 4);
            size_t gQ = rowQ + (size_t)r * (3 * DD) + hoff + c * 8;
            cp_async16(sb + AQH + ad, qkvh + gQ);
            cp_async16(sb + AQL + ad, qkvl + gQ);
        }
        attn_cp_kv(sb + ASTG, qkvh, qkvl, (size_t)(b * SS) * (3 * DD), hoff, tid);
        cp_commit();
        attn_cp_kv(sb + ASTG + SSTG, qkvh, qkvl,
                   (size_t)(b * SS + 64) * (3 * DD), hoff, tid);
        cp_commit();
    }

    int lrA = (lane & 7) + ((lane >> 3) & 1) * 8;
    uint32_t cA = (uint32_t)((lane >> 4) << 4);
    int rowA = warp * 16 + lrA;
    uint32_t aBase = (uint32_t)(rowA * 128);
    uint32_t aMask = (uint32_t)((rowA & 7) << 4);

    int lrB = (lane & 7) + ((lane >> 4) & 1) * 8;
    uint32_t cB = (uint32_t)(((lane >> 3) & 1) << 4);

    int lrV = (lane & 7) + ((lane >> 3) & 1) * 8;
    uint32_t cV = (uint32_t)(((lane >> 4) & 1) << 4);

    float oacc[8][4];
    float mA = -1e30f, mB = -1e30f, lA = 0.f, lB = 0.f;
#pragma unroll
    for (int t = 0; t < 8; t++)
#pragma unroll
        for (int q = 0; q < 4; q++) oacc[t][q] = 0.f;

    int slot = 0;
    for (int kt = 0; kt <= qt; kt++) {
        uint32_t st = sb + ASTG + (uint32_t)slot * SSTG;
        cp_wait<1>();
        __syncthreads();
        int nslot = slot + 2; if (nslot >= 3) nslot -= 3;
        if (kt + 2 <= qt)
            attn_cp_kv(sb + ASTG + (uint32_t)nslot * SSTG, qkvh, qkvl,
                       (size_t)(b * SS + (kt + 2) * 64) * (3 * DD), hoff, tid);
        cp_commit();

        float sacc[8][4];
#pragma unroll
        for (int t = 0; t < 8; t++)
#pragma unroll
            for (int q = 0; q < 4; q++) sacc[t][q] = 0.f;

#pragma unroll
        for (int ks = 0; ks < 4; ks++) {
            uint32_t kx = (uint32_t)(ks * 32);
            uint32_t qh4[4], ql4[4], kh[8][2];
            ldsm_x4(qh4, sb + AQH + aBase + ((kx + cA) ^ aMask));
            ldsm_x4(ql4, sb + AQL + aBase + ((kx + cA) ^ aMask));
#pragma unroll
            for (int p = 0; p < 4; p++) {
                int rowB = p * 16 + lrB;
                uint32_t r4[4];
                ldsm_x4(r4, st + SKH + (uint32_t)(rowB * 128) +
                            ((kx + cB) ^ (uint32_t)((rowB & 7) << 4)));
                kh[2 * p][0] = r4[0]; kh[2 * p][1] = r4[1];
                kh[2 * p + 1][0] = r4[2]; kh[2 * p + 1][1] = r4[3];
            }
#pragma unroll
            for (int t = 0; t < 8; t++) mma16816(sacc[t], qh4, kh[t]);
#pragma unroll
            for (int t = 0; t < 8; t++) mma16816(sacc[t], ql4, kh[t]);
            {
                uint32_t kl[8][2];
#pragma unroll
                for (int p = 0; p < 4; p++) {
                    int rowB = p * 16 + lrB;
                    uint32_t r4[4];
                    ldsm_x4(r4, st + SKL + (uint32_t)(rowB * 128) +
                                ((kx + cB) ^ (uint32_t)((rowB & 7) << 4)));
                    kl[2 * p][0] = r4[0]; kl[2 * p][1] = r4[1];
                    kl[2 * p + 1][0] = r4[2]; kl[2 * p + 1][1] = r4[3];
                }
#pragma unroll
                for (int t = 0; t < 8; t++) mma16816(sacc[t], qh4, kl[t]);
            }
        }

#pragma unroll
        for (int t = 0; t < 8; t++) {
            sacc[t][0] *= 0.125f; sacc[t][1] *= 0.125f;
            sacc[t][2] *= 0.125f; sacc[t][3] *= 0.125f;
        }

        if (kt == qt) {
            int qlocA = warp * 16 + g, qlocB = qlocA + 8;
#pragma unroll
            for (int t = 0; t < 8; t++) {
                int k0c = t * 8 + tig * 2;
                if (k0c > qlocA)     sacc[t][0] = -1e30f;
                if (k0c + 1 > qlocA) sacc[t][1] = -1e30f;
                if (k0c > qlocB)     sacc[t][2] = -1e30f;
                if (k0c + 1 > qlocB) sacc[t][3] = -1e30f;
            }
        }

        float maA = -1e30f, maB = -1e30f;
#pragma unroll
        for (int t = 0; t < 8; t++) {
            maA = fmaxf(maA, fmaxf(sacc[t][0], sacc[t][1]));
            maB = fmaxf(maB, fmaxf(sacc[t][2], sacc[t][3]));
        }
        maA = fmaxf(maA, __shfl_xor_sync(0xffffffffu, maA, 1));
        maA = fmaxf(maA, __shfl_xor_sync(0xffffffffu, maA, 2));
        maB = fmaxf(maB, __shfl_xor_sync(0xffffffffu, maB, 1));
        maB = fmaxf(maB, __shfl_xor_sync(0xffffffffu, maB, 2));
        float nmA = fmaxf(mA, maA), nmB = fmaxf(mB, maB);
        float corrA = fexp(mA - nmA), corrB = fexp(mB - nmB);
        mA = nmA; mB = nmB;
        float sumA = 0.f, sumB = 0.f;
#pragma unroll
        for (int t = 0; t < 8; t++) {
            sacc[t][0] = fexp(sacc[t][0] - nmA);
            sacc[t][1] = fexp(sacc[t][1] - nmA);
            sacc[t][2] = fexp(sacc[t][2] - nmB);
            sacc[t][3] = fexp(sacc[t][3] - nmB);
            sumA += sacc[t][0] + sacc[t][1];
            sumB += sacc[t][2] + sacc[t][3];
        }
        sumA += __shfl_xor_sync(0xffffffffu, sumA, 1);
        sumA += __shfl_xor_sync(0xffffffffu, sumA, 2);
        sumB += __shfl_xor_sync(0xffffffffu, sumB, 1);
        sumB += __shfl_xor_sync(0xffffffffu, sumB, 2);
        lA = lA * corrA + sumA;
        lB = lB * corrB + sumB;
#pragma unroll
        for (int t = 0; t < 8; t++) {
            oacc[t][0] *= corrA; oacc[t][1] *= corrA;
            oacc[t][2] *= corrB; oacc[t][3] *= corrB;
        }

        uint32_t ph[4][4], pl[4][4];
#pragma unroll
        for (int p = 0; p < 4; p++) {
#pragma unroll
            for (int q = 0; q < 4; q++) {
                int t = 2 * p + (q >> 1);
                float a = sacc[t][(q & 1) * 2 + 0];
                float bv = sacc[t][(q & 1) * 2 + 1];
                __nv_bfloat16 ah2 = __float2bfloat16(a), bh2 = __float2bfloat16(bv);
                __nv_bfloat162 th = __halves2bfloat162(ah2, bh2);
                ph[p][q] = *(uint32_t*)&th;
                __nv_bfloat162 tl = __halves2bfloat162(
                    __float2bfloat16(a - __bfloat162float(ah2)),
                    __float2bfloat16(bv - __bfloat162float(bh2)));
                pl[p][q] = *(uint32_t*)&tl;
            }
        }

#pragma unroll
        for (int ks = 0; ks < 4; ks++) {
            int rowV = ks * 16 + lrV;
            uint32_t vMask = (uint32_t)((rowV & 7) << 4);
            uint32_t vbh[8][2], vbl[8][2];
#pragma unroll
            for (int j = 0; j < 4; j++) {
                uint32_t cb = (uint32_t)(j * 32) + cV;
                uint32_t r4[4];
                ldsm_x4_t(r4, st + SVH + (uint32_t)(rowV * 128) + (cb ^ vMask));
                vbh[2 * j][0] = r4[0]; vbh[2 * j][1] = r4[1];
                vbh[2 * j + 1][0] = r4[2]; vbh[2 * j + 1][1] = r4[3];
            }
#pragma unroll
            for (int j = 0; j < 4; j++) {
                uint32_t cb = (uint32_t)(j * 32) + cV;
                uint32_t r4[4];
                ldsm_x4_t(r4, st + SVL + (uint32_t)(rowV * 128) + (cb ^ vMask));
                vbl[2 * j][0] = r4[0]; vbl[2 * j][1] = r4[1];
                vbl[2 * j + 1][0] = r4[2]; vbl[2 * j + 1][1] = r4[3];
            }
#pragma unroll
            for (int t = 0; t < 8; t++) mma16816(oacc[t], ph[ks], vbh[t]);
#pragma unroll
            for (int t = 0; t < 8; t++) mma16816(oacc[t], pl[ks], vbh[t]);
#pragma unroll
            for (int t = 0; t < 8; t++) mma16816(oacc[t], ph[ks], vbl[t]);
        }
        slot++; if (slot >= 3) slot = 0;
    }

    float invA = 1.0f / lA, invB = 1.0f / lB;
    int rowAg = b * SS + q0 + warp * 16 + g;
    int rowBg = rowAg + 8;
#pragma unroll
    for (int t = 0; t < 8; t++) {
        int d0 = t * 8 + tig * 2;
        *(float2*)(oat + (size_t)rowAg * DD + h * HDIM + d0) =
            make_float2(to_tf32(oacc[t][0] * invA), to_tf32(oacc[t][1] * invA));
        *(float2*)(oat + (size_t)rowBg * DD + h * HDIM + d0) =
            make_float2(to_tf32(oacc[t][2] * invB), to_tf32(oacc[t][3] * invB));
    }
}

// ---------------- launch ---------------------------------------------------
extern "C" void kernel_launch(void* const* d_in, const int* in_sizes, int n_in,
                              void* d_out, int out_size)
{
    const float* x    = (const float*)d_in[0];
    const float* pos  = (const float*)d_in[1];
    const float* ln1g = (const float*)d_in[2];
    const float* ln1b = (const float*)d_in[3];
    const float* wqkv = (const float*)d_in[4];
    const float* bqkv = (const float*)d_in[5];
    const float* wo   = (const float*)d_in[6];
    const float* bo   = (const float*)d_in[7];
    const float* ln2g = (const float*)d_in[8];
    const float* ln2b = (const float*)d_in[9];
    const float* wfc  = (const float*)d_in[10];
    const float* bfc  = (const float*)d_in[11];
    const float* wpr  = (const float*)d_in[12];
    const float* bpr  = (const float*)d_in[13];
    float* out = (float*)d_out;

    __nv_bfloat16 *p_h_hi, *p_h_lo, *p_qkvh, *p_qkvl, *p_wqkv_hi, *p_wqkv_lo;
    float *p_at, *p_x2, *p_m, *p_ff, *p_woT, *p_wfcT, *p_wprT;
    cudaGetSymbolAddress((void**)&p_h_hi, g_h_hi);   cudaGetSymbolAddress((void**)&p_h_lo, g_h_lo);
    cudaGetSymbolAddress((void**)&p_qkvh, g_qkvh);   cudaGetSymbolAddress((void**)&p_qkvl, g_qkvl);
    cudaGetSymbolAddress((void**)&p_at, g_at);
    cudaGetSymbolAddress((void**)&p_x2, g_x2);
    cudaGetSymbolAddress((void**)&p_m, g_m);
    cudaGetSymbolAddress((void**)&p_ff, g_ff);
    cudaGetSymbolAddress((void**)&p_wqkv_hi, g_wqkv_hi); cudaGetSymbolAddress((void**)&p_wqkv_lo, g_wqkv_lo);
    cudaGetSymbolAddress((void**)&p_woT, g_woT);
    cudaGetSymbolAddress((void**)&p_wfcT, g_wfcT);
    cudaGetSymbolAddress((void**)&p_wprT, g_wprT);

    cudaFuncSetAttribute(tc_gemm_bf, cudaFuncAttributeMaxDynamicSharedMemorySize, TCG_SMEM);
    cudaFuncSetAttribute(tf_gemm<1>, cudaFuncAttributeMaxDynamicSharedMemorySize, TF_SMEM);
    cudaFuncSetAttribute(tf_gemm<2>, cudaFuncAttributeMaxDynamicSharedMemorySize, TF_SMEM);
    cudaFuncSetAttribute(attn_kernel, cudaFuncAttributeMaxDynamicSharedMemorySize, ATT_SMEM);

    dim3 tb(32, 8);
    wsplit_t<<<dim3(3 * DD / 32, DD / 32), tb>>>(wqkv, p_wqkv_hi, p_wqkv_lo, DD, 3 * DD);
    wtrans<<<dim3(DD / 32, DD / 32), tb>>>(wo, p_woT, DD, DD);
    wtrans<<<dim3(DFFN / 32, DD / 32), tb>>>(wfc, p_wfcT, DD, DFFN);
    wtrans<<<dim3(DD / 32, DFFN / 32), tb>>>(wpr, p_wprT, DFFN, DD);

    // 1) h = LN1(x) + pos -> bf16 hi/lo
    ln_bf<<<ROWS, 256>>>(x, ln1g, ln1b, pos, p_h_hi, p_h_lo);

    // 2) qkv = h @ w_qkv + b_qkv -> bf16 hi/lo (bf16 3-pass for accuracy)
    tc_gemm_bf<<<dim3(3 * DD / 128, ROWS / 128), 256, TCG_SMEM>>>(
        p_h_hi, p_h_lo, p_wqkv_hi, p_wqkv_lo, bqkv,
        p_qkvh, p_qkvl, ROWS, 3 * DD, DD);

    // 3) causal attention -> tf32-rounded fp32
    attn_kernel<<<dim3(SS / 64, HH, BB), 128, ATT_SMEM>>>(p_qkvh, p_qkvl, p_at);

    // 4) x2 = x + attn @ w_o + b_o (tf32)
    tf_gemm<2><<<dim3(DD / 128, ROWS / 128), 256, TF_SMEM>>>(
        p_at, p_woT, bo, x, p_x2, ROWS, DD, DD);

    // 5) m = LN2(x2) -> tf32-rounded fp32
    ln_tf<<<ROWS, 256>>>(p_x2, ln2g, ln2b, p_m);

    // 6) ff = gelu(m @ w_fc + b_fc) (tf32) -> tf32-rounded fp32
    tf_gemm<1><<<dim3(DFFN / 128, ROWS / 128), 256, TF_SMEM>>>(
        p_m, p_wfcT, bfc, nullptr, p_ff, ROWS, DFFN, DD);

    // 7) out = x2 + ff @ w_proj + b_proj (tf32)
    tf_gemm<2><<<dim3(DD / 128, ROWS / 128), 256, TF_SMEM>>>(
        p_ff, p_wprT, bpr, p_x2, out, ROWS, DD, DFFN);
}